// round 8
// baseline (speedup 1.0000x reference)
#include <cuda_runtime.h>
#include <math.h>
#include <stdint.h>

// ---------------------------------------------------------------------------
// SLAMv2: 14-layer MoE-attention transformer, segmented schedule.
// Round 8: all GEMM B-operands repacked to [N][K]-major (one-time tiled
// transpose) -> single-LDS.64 fragments everywhere; bigger warp tiles
// (64x32 / 64x16); V written transposed by qkv epilogue; routing grid x2.
// Numerics (rounding sites, accumulation order) identical to R7.
// ---------------------------------------------------------------------------

namespace {
constexpr int B = 2, S = 1024, D = 1000, E = 20, HD = 50, TH = 3 * HD;
constexpr int HD_P = 52;  // padded head dim (rows 208B, 16B-aligned)
constexpr int F = 2048, CYCLES = 3, L = 14;

constexpr long long NX = (long long)B * S * D;  // 2,048,000
constexpr long long OFF_X    = 0;
constexpr long long OFF_XNEW = OFF_X + NX;
constexpr long long OFF_T    = OFF_XNEW + NX;
constexpr long long OFF_X1   = OFF_T + NX;
constexpr long long OFF_Y    = OFF_X1 + NX;
constexpr long long OFF_A    = OFF_Y + NX;
constexpr long long OFF_ROUT = OFF_A + NX;                        // B*S*E
constexpr long long OFF_H    = OFF_ROUT + (long long)B * S * E;   // B*S*F
constexpr long long OFF_QK   = OFF_H + (long long)B * S * F;      // B*E*2*S*HD_P
constexpr long long OFF_VT   = OFF_QK + (long long)B * E * 2 * S * HD_P;
constexpr long long OFF_SC   = OFF_VT + (long long)B * E * HD * S;
constexpr long long OFF_EWT  = OFF_SC + (long long)B * E * S * S; // [L,E,TH,D]
constexpr long long OFF_OWT  = OFF_EWT + (long long)L * E * TH * D;
constexpr long long OFF_W1T  = OFF_OWT + (long long)L * D * D;    // [L,F,D]
constexpr long long OFF_W2T  = OFF_W1T + (long long)L * D * F;    // [L,D,F]
constexpr long long TOTAL    = OFF_W2T + (long long)L * F * D;

// Segment schedule for S=1024: (0,460) (256,665) (460,870) (665,1024)+wrap 51
constexpr int SEG_ST[4] = {0, 256, 460, 665};
constexpr int SEG_N[4]  = {460, 409, 410, 410};
constexpr int SEG_P1[4] = {460, 409, 410, 359};
}  // namespace

__device__ float g_scratch[TOTAL];

struct GemmP {
  const float* A; const float* Bm; const float* bias; float* C;
  int M, N, K, lda, ldb, ldc;
  int aDiv; long long as1, as2;
  int bDiv; long long bs1, bs2;
  int cDiv; long long cs1, cs2;
  int biasDiv; long long biasS;
  long long splitStride;
  float scale;
  const float* rout; int routN;
  float* C2; long long vs1; int ldc2;  // V-transposed output (EPI=5)
};

__device__ __forceinline__ float to_tf32(float x) {
  asm("cvt.rna.tf32.f32 %0, %0;" : "+f"(x));
  return x;
}

__device__ __forceinline__ void cp16(uint32_t dst, const float* src, int bytes) {
  asm volatile("cp.async.cg.shared.global [%0], [%1], 16, %2;\n"
               :: "r"(dst), "l"(src), "r"(bytes));
}
__device__ __forceinline__ void cp_commit() {
  asm volatile("cp.async.commit_group;\n");
}
template <int N>
__device__ __forceinline__ void cp_wait() {
  asm volatile("cp.async.wait_group %0;\n" :: "n"(N));
}

// ---------------------------------------------------------------------------
// TF32 tensor-core GEMM; cp.async 4-stage ring; B always [N][K]-major.
// Both A and B fragments: one LDS.64 each (k-slot remap: slot t <- k=2t,
// slot t+4 <- k=2t+1, consistently on A and B -> bit-identical result).
// EPI: 0 +bias; 1 +bias,GELU(round); 2 *scale; 3 *routing(round);
//      5 +bias, split Q/K rows + V transposed (round).
// ---------------------------------------------------------------------------
template <int BM, int BN, int WM, int WN, int EPI>
__global__ __launch_bounds__(256, 2) void tmma_k(GemmP p) {
  constexpr int BK = 16, ST = 4;
  constexpr int SKA = BK + 4;  // 20 floats = 80B rows (16B-aligned)
  constexpr int ASZ = BM * SKA;
  constexpr int BSZ = BN * SKA;
  constexpr int NWN = BN / WN;
  constexpr int MT = WM / 16, NT = WN / 8;
  constexpr int AV_ = BM / 64;
  constexpr int BV_ = BN / 64;
  static_assert((BM / WM) * (BN / WN) == 8, "need 8 warps");

  extern __shared__ float sm[];
  float* As = sm;             // [ST][BM][SKA]
  float* Bs = sm + ST * ASZ;  // [ST][BN][SKA]
  const uint32_t a_u32 = (uint32_t)__cvta_generic_to_shared(As);
  const uint32_t b_u32 = (uint32_t)__cvta_generic_to_shared(Bs);

  const int z = blockIdx.z;
  const float* Ab =
      p.A + (long long)(z / p.aDiv) * p.as1 + (long long)(z % p.aDiv) * p.as2;
  const float* Bb =
      p.Bm + (long long)(z / p.bDiv) * p.bs1 + (long long)(z % p.bDiv) * p.bs2;
  float* Cb =
      p.C + (long long)(z / p.cDiv) * p.cs1 + (long long)(z % p.cDiv) * p.cs2;

  const int m0 = blockIdx.y * BM, n0 = blockIdx.x * BN;
  const int tid = threadIdx.x;
  const int warp = tid >> 5, lane = tid & 31;
  const int g = lane >> 2, t = lane & 3;
  const int wm = (warp / NWN) * WM, wn = (warp % NWN) * WN;

  auto issue = [&](int it) {
    const int s = it % ST;
    const int kb = it * BK;
#pragma unroll
    for (int v = 0; v < AV_; v++) {
      int idx = tid + v * 256;
      int m = idx >> 2, c4 = (idx & 3) * 4;
      int gm = m0 + m, gk = kb + c4;
      int by = 0;
      if (gm < p.M) {
        int rem = (p.K - gk) * 4;
        by = rem > 16 ? 16 : (rem > 0 ? rem : 0);
      }
      const float* src = Ab + (long long)(by ? gm : 0) * p.lda + (by ? gk : 0);
      cp16(a_u32 + (uint32_t)(s * ASZ + m * SKA + c4) * 4u, src, by);
    }
#pragma unroll
    for (int v = 0; v < BV_; v++) {
      int idx = tid + v * 256;
      int n = idx >> 2, c4 = (idx & 3) * 4;
      int gn = n0 + n, gk = kb + c4;
      int by = 0;
      if (gn < p.N) {
        int rem = (p.K - gk) * 4;
        by = rem > 16 ? 16 : (rem > 0 ? rem : 0);
      }
      const float* src = Bb + (long long)(by ? gn : 0) * p.ldb + (by ? gk : 0);
      cp16(b_u32 + (uint32_t)(s * BSZ + n * SKA + c4) * 4u, src, by);
    }
  };

  float c[MT][NT][4];
#pragma unroll
  for (int i = 0; i < MT; i++)
#pragma unroll
    for (int j = 0; j < NT; j++)
#pragma unroll
      for (int r = 0; r < 4; r++) c[i][j][r] = 0.f;

  auto comp = [&](int s) {
    const float* Asb = As + s * ASZ;
    const float* Bsb = Bs + s * BSZ;
#pragma unroll
    for (int kq = 0; kq < 2; kq++) {
      const int ko = kq * 8 + 2 * t;
      float2 af[MT][2];
#pragma unroll
      for (int mt = 0; mt < MT; mt++) {
        int r0 = wm + mt * 16 + g;
        af[mt][0] = *reinterpret_cast<const float2*>(&Asb[r0 * SKA + ko]);
        af[mt][1] = *reinterpret_cast<const float2*>(&Asb[(r0 + 8) * SKA + ko]);
      }
      float2 bf[NT];
#pragma unroll
      for (int nt = 0; nt < NT; nt++)
        bf[nt] = *reinterpret_cast<const float2*>(
            &Bsb[(wn + nt * 8 + g) * SKA + ko]);
#pragma unroll
      for (int mt = 0; mt < MT; mt++)
#pragma unroll
        for (int nt = 0; nt < NT; nt++) {
          asm volatile(
              "mma.sync.aligned.m16n8k8.row.col.f32.tf32.tf32.f32 "
              "{%0,%1,%2,%3}, {%4,%5,%6,%7}, {%8,%9}, {%0,%1,%2,%3};"
              : "+f"(c[mt][nt][0]), "+f"(c[mt][nt][1]), "+f"(c[mt][nt][2]),
                "+f"(c[mt][nt][3])
              : "r"(__float_as_uint(af[mt][0].x)),
                "r"(__float_as_uint(af[mt][1].x)),
                "r"(__float_as_uint(af[mt][0].y)),
                "r"(__float_as_uint(af[mt][1].y)),
                "r"(__float_as_uint(bf[nt].x)),
                "r"(__float_as_uint(bf[nt].y)));
        }
    }
  };

  const int iters = (p.K + BK - 1) / BK;
#pragma unroll
  for (int s = 0; s < ST - 1; s++) {
    if (s < iters) issue(s);
    cp_commit();
  }
  for (int it = 0; it < iters; it++) {
    cp_wait<ST - 2>();
    __syncthreads();
    if (it + ST - 1 < iters) issue(it + ST - 1);
    cp_commit();
    comp(it % ST);
  }

  const float* biasb = nullptr;
  if ((EPI == 0 || EPI == 1 || EPI == 5) && p.bias)
    biasb = p.bias + (long long)(z % p.biasDiv) * p.biasS;
  float* C2b = (EPI == 5) ? p.C2 + (long long)z * p.vs1 : nullptr;

#pragma unroll
  for (int mt = 0; mt < MT; mt++)
#pragma unroll
    for (int nt = 0; nt < NT; nt++)
#pragma unroll
      for (int r = 0; r < 4; r++) {
        int row = m0 + wm + mt * 16 + g + ((r >> 1) ? 8 : 0);
        int col = n0 + wn + nt * 8 + 2 * t + (r & 1);
        if (row >= p.M || col >= p.N) continue;
        float v = c[mt][nt][r];
        if (biasb) v += biasb[col];
        if (EPI == 1) {
          v = 0.5f * v * (1.f + erff(v * 0.70710678118654752f));
          v = to_tf32(v);
        }
        if (EPI == 2) v *= p.scale;
        if (EPI == 3) {
          v *= p.rout[((long long)(z / p.cDiv) * p.routN + row) * E +
                      (z % p.cDiv)];
          v = to_tf32(v);
        }
        if (EPI == 5) {
          v = to_tf32(v);
          if (col < 2 * HD) {
            int h = col / HD, s2 = col - h * HD;
            Cb[(long long)h * p.splitStride + (long long)row * p.ldc + s2] = v;
          } else {
            C2b[(long long)(col - 2 * HD) * p.ldc2 + row] = v;
          }
        } else {
          Cb[(long long)row * p.ldc + col] = v;
        }
      }
}

// ---------------------------------------------------------------------------
// SIMT SGEMM (routing GEMM, N=20, kept fp32 for numeric stability)
// ---------------------------------------------------------------------------
template <int BM, int BN, int BK, int TM, int TN>
__global__ __launch_bounds__((BM / TM) * (BN / TN)) void sgemm2_k(GemmP p) {
  constexpr int NTHR = (BM / TM) * (BN / TN);
  constexpr int TX = BN / TN;
  __shared__ float As[BK][BM + 4];
  __shared__ float Bs[BK][BN + 4];

  const float* Ab = p.A;
  const float* Bb = p.Bm;
  float* Cb = p.C;

  const int m0 = blockIdx.y * BM, n0 = blockIdx.x * BN;
  const int tid = threadIdx.x;
  const int tx = tid % TX, ty = tid / TX;

  float acc[TM][TN];
#pragma unroll
  for (int i = 0; i < TM; i++)
#pragma unroll
    for (int j = 0; j < TN; j++) acc[i][j] = 0.f;

  for (int k0 = 0; k0 < p.K; k0 += BK) {
    for (int idx = tid; idx < BM * BK; idx += NTHR) {
      int m = idx / BK, kk = idx % BK;
      int gm = m0 + m, gk = k0 + kk;
      As[kk][m] = (gm < p.M && gk < p.K) ? Ab[(long long)gm * p.lda + gk] : 0.f;
    }
    for (int idx = tid; idx < BK * BN; idx += NTHR) {
      int kk = idx / BN, nn = idx % BN;
      int gk = k0 + kk, gn = n0 + nn;
      Bs[kk][nn] = (gk < p.K && gn < p.N) ? Bb[(long long)gk * p.ldb + gn] : 0.f;
    }
    __syncthreads();
#pragma unroll
    for (int kk = 0; kk < BK; kk++) {
      float a[TM], b[TN];
#pragma unroll
      for (int i = 0; i < TM; i++) a[i] = As[kk][ty * TM + i];
#pragma unroll
      for (int j = 0; j < TN; j++) b[j] = Bs[kk][tx * TN + j];
#pragma unroll
      for (int i = 0; i < TM; i++)
#pragma unroll
        for (int j = 0; j < TN; j++) acc[i][j] += a[i] * b[j];
    }
    __syncthreads();
  }

#pragma unroll
  for (int i = 0; i < TM; i++) {
    int row = m0 + ty * TM + i;
    if (row >= p.M) continue;
#pragma unroll
    for (int j = 0; j < TN; j++) {
      int col = n0 + tx * TN + j;
      if (col >= p.N) continue;
      float v = acc[i][j] + (p.bias ? p.bias[col] : 0.f);
      Cb[(long long)row * p.ldc + col] = v;
    }
  }
}

// ---------------------------------------------------------------------------
// Tiled batched transpose with tf32 rounding: src [z][K][N] -> dst [z][N][K]
// ---------------------------------------------------------------------------
__global__ void transpose_k(float* dst, const float* src, int K, int N) {
  __shared__ float tile[32][33];
  const long long zo = (long long)blockIdx.z * K * N;
  src += zo;
  dst += zo;
  int n0 = blockIdx.x * 32, k0 = blockIdx.y * 32;
  int tx = threadIdx.x, ty = threadIdx.y;  // 32 x 8
  for (int i = ty; i < 32; i += 8) {
    int k = k0 + i, n = n0 + tx;
    tile[i][tx] = (k < K && n < N) ? src[(long long)k * N + n] : 0.f;
  }
  __syncthreads();
  for (int i = ty; i < 32; i += 8) {
    int n = n0 + i, k = k0 + tx;
    if (n < N && k < K) dst[(long long)n * K + k] = to_tf32(tile[tx][i]);
  }
}

// ---------------------------------------------------------------------------
// Small kernels
// ---------------------------------------------------------------------------
__global__ void copy_round_k(float* dst, const float* src, long long n) {
  long long i = (long long)blockIdx.x * blockDim.x + threadIdx.x;
  if (i < n) dst[i] = to_tf32(src[i]);
}

__global__ void zero_k(float* dst, long long n) {
  long long i = (long long)blockIdx.x * blockDim.x + threadIdx.x;
  if (i < n) dst[i] = 0.f;
}

__global__ void gather_k(float* dst, const float* src, int nseg, int st, int p1) {
  long long i = (long long)blockIdx.x * blockDim.x + threadIdx.x;
  long long tot = (long long)B * nseg * D;
  if (i >= tot) return;
  int d = (int)(i % D);
  long long r = i / D;
  int ii = (int)(r % nseg);
  int b_ = (int)(r / nseg);
  int si = (ii < p1) ? (st + ii) : (ii - p1);
  dst[i] = src[((long long)b_ * S + si) * D + d];
}

__global__ void scatter_add_k(float* dst, const float* src, int nseg, int st,
                              int p1) {
  long long i = (long long)blockIdx.x * blockDim.x + threadIdx.x;
  long long tot = (long long)B * nseg * D;
  if (i >= tot) return;
  int d = (int)(i % D);
  long long r = i / D;
  int ii = (int)(r % nseg);
  int b_ = (int)(r / nseg);
  int si = (ii < p1) ? (st + ii) : (ii - p1);
  dst[((long long)b_ * S + si) * D + d] += src[i];
}

__device__ __forceinline__ float seg_cnt(int i) {
  float c = 0.f;
  c += (i < 460);
  c += (i >= 256 && i < 665);
  c += (i >= 460 && i < 870);
  c += (i >= 665);
  c += (i < 51);
  return c;
}

__global__ void div_counts_k(float* x, const float* xn) {
  long long i = (long long)blockIdx.x * blockDim.x + threadIdx.x;
  if (i >= NX) return;
  int ii = (int)((i / D) % S);
  x[i] = to_tf32(xn[i] / seg_cnt(ii));
}

__global__ void softmaxE_k(float* r, int rows) {
  int i = blockIdx.x * blockDim.x + threadIdx.x;
  if (i >= rows) return;
  float* p = r + (long long)i * E;
  float m = -1e30f;
  for (int e = 0; e < E; e++) m = fmaxf(m, p[e]);
  float s = 0.f;
  for (int e = 0; e < E; e++) {
    float v = __expf(p[e] - m);
    p[e] = v;
    s += v;
  }
  float inv = 1.f / s;
  for (int e = 0; e < E; e++) p[e] *= inv;
}

// In-place row softmax (output rounded to tf32 — feeds AV GEMM).
__global__ void softmax_rows_k(float* s, int n, int ld) {
  float* row = s + (long long)blockIdx.y * n * ld + (long long)blockIdx.x * ld;
  __shared__ float red[32];
  __shared__ float bcast;
  int tid = threadIdx.x;
  int nw = blockDim.x >> 5;

  float m = -1e30f;
  for (int j = tid; j < n; j += blockDim.x) m = fmaxf(m, row[j]);
  for (int o = 16; o; o >>= 1) m = fmaxf(m, __shfl_xor_sync(0xffffffffu, m, o));
  if ((tid & 31) == 0) red[tid >> 5] = m;
  __syncthreads();
  if (tid < 32) {
    float v = (tid < nw) ? red[tid] : -1e30f;
    for (int o = 16; o; o >>= 1) v = fmaxf(v, __shfl_xor_sync(0xffffffffu, v, o));
    if (tid == 0) bcast = v;
  }
  __syncthreads();
  m = bcast;

  float sum = 0.f;
  for (int j = tid; j < n; j += blockDim.x) {
    float e = __expf(row[j] - m);
    row[j] = e;
    sum += e;
  }
  for (int o = 16; o; o >>= 1) sum += __shfl_xor_sync(0xffffffffu, sum, o);
  if ((tid & 31) == 0) red[tid >> 5] = sum;
  __syncthreads();
  if (tid < 32) {
    float v = (tid < nw) ? red[tid] : 0.f;
    for (int o = 16; o; o >>= 1) v += __shfl_xor_sync(0xffffffffu, v, o);
    if (tid == 0) bcast = v;
  }
  __syncthreads();
  float inv = 1.f / bcast;
  for (int j = tid; j < n; j += blockDim.x) row[j] = to_tf32(row[j] * inv);
}

// out = layernorm(x + r) * g + b; CVT rounds output to tf32 (GEMM input).
template <bool CVT>
__global__ void add_ln_k(const float* x, const float* r, const float* g,
                         const float* b, float* out) {
  long long base = (long long)blockIdx.x * D;
  __shared__ float buf[D];
  __shared__ float redA[32], redB[32];
  __shared__ float sh_m, sh_inv;
  int tid = threadIdx.x;
  int nw = blockDim.x >> 5;

  float s = 0.f, s2 = 0.f;
  for (int d = tid; d < D; d += blockDim.x) {
    float v = x[base + d] + r[base + d];
    buf[d] = v;
    s += v;
    s2 += v * v;
  }
  for (int o = 16; o; o >>= 1) {
    s += __shfl_xor_sync(0xffffffffu, s, o);
    s2 += __shfl_xor_sync(0xffffffffu, s2, o);
  }
  if ((tid & 31) == 0) { redA[tid >> 5] = s; redB[tid >> 5] = s2; }
  __syncthreads();
  if (tid < 32) {
    float a2 = (tid < nw) ? redA[tid] : 0.f;
    float b2 = (tid < nw) ? redB[tid] : 0.f;
    for (int o = 16; o; o >>= 1) {
      a2 += __shfl_xor_sync(0xffffffffu, a2, o);
      b2 += __shfl_xor_sync(0xffffffffu, b2, o);
    }
    if (tid == 0) {
      float mean = a2 / D;
      float var = b2 / D - mean * mean;
      sh_m = mean;
      sh_inv = rsqrtf(var + 1e-5f);
    }
  }
  __syncthreads();
  float mean = sh_m, inv = sh_inv;
  for (int d = tid; d < D; d += blockDim.x) {
    float v = (buf[d] - mean) * inv * g[d] + b[d];
    out[base + d] = CVT ? to_tf32(v) : v;
  }
}

// ---------------------------------------------------------------------------
// Host-side driver
// ---------------------------------------------------------------------------
static inline int cdiv(int a, int b) { return (a + b - 1) / b; }

struct Wts {
  const float *ew, *eb, *rw, *rb, *ow, *ob, *l1g, *l1b, *w1, *b1, *w2, *b2,
      *l2g, *l2b;
};

// dynamic smem: ST=4, SKA=20
constexpr int SM_128x64 = 4 * (128 + 64) * 20 * 4;    // 61440
constexpr int SM_128x128 = 4 * (128 + 128) * 20 * 4;  // 81920

static void run_block(float* sc, const float* t, float* out, int layer, int n,
                      const Wts& w) {
  const int M = B * n;
  const int n4 = (n + 3) & ~3;
  float* rout = sc + OFF_ROUT;
  float* qk = sc + OFF_QK;
  float* vt = sc + OFF_VT;
  float* sco = sc + OFF_SC;
  float* y = sc + OFF_Y;
  float* a = sc + OFF_A;
  float* x1 = sc + OFF_X1;
  float* h = sc + OFF_H;
  const float* ewt = sc + OFF_EWT + (long long)layer * E * TH * D;
  const float* owt = sc + OFF_OWT + (long long)layer * D * D;
  const float* w1t = sc + OFF_W1T + (long long)layer * D * F;
  const float* w2t = sc + OFF_W2T + (long long)layer * F * D;

  GemmP p;
  auto reset = [&]() {
    p = GemmP{};
    p.aDiv = p.bDiv = p.cDiv = p.biasDiv = 1;
    p.scale = 1.f;
  };

  // 1. routing logits + softmax over experts (fp32 SIMT, N=20)
  reset();
  p.A = t; p.Bm = w.rw + (long long)layer * D * E;
  p.bias = w.rb + (long long)layer * E; p.C = rout;
  p.M = M; p.N = E; p.K = D; p.lda = D; p.ldb = E; p.ldc = E;
  sgemm2_k<32, 64, 16, 2, 4><<<dim3(1, cdiv(M, 32), 1), 256>>>(p);
  softmaxE_k<<<cdiv(M, 256), 256>>>(rout, M);

  // 2. qkv: Q,K -> [z][2][n][HD_P]; V -> transposed [z][HD][n4]
  reset();
  p.A = t; p.lda = D; p.aDiv = E; p.as1 = (long long)n * D;
  p.Bm = ewt; p.ldb = D; p.bDiv = E; p.bs2 = (long long)TH * D;
  p.bias = w.eb + (long long)layer * E * TH; p.biasDiv = E; p.biasS = TH;
  p.C = qk; p.ldc = HD_P; p.cs1 = 2LL * n * HD_P;
  p.splitStride = (long long)n * HD_P;
  p.C2 = vt; p.vs1 = (long long)HD * n4; p.ldc2 = n4;
  p.M = n; p.N = TH; p.K = D;
  tmma_k<128, 64, 64, 16, 5>
      <<<dim3(3, cdiv(n, 128), B * E), 256, SM_128x64>>>(p);

  // 3. scores = Q @ K^T * HD^-0.5, batched over (b,e)
  reset();
  p.A = qk; p.lda = HD_P; p.as1 = 2LL * n * HD_P;
  p.Bm = qk + (long long)n * HD_P; p.ldb = HD_P; p.bs1 = 2LL * n * HD_P;
  p.C = sco; p.ldc = n4; p.cs1 = (long long)n * n4;
  p.M = n; p.N = n; p.K = HD;
  p.scale = 0.14142135623730950488f;  // 1/sqrt(50)
  tmma_k<128, 128, 64, 32, 2>
      <<<dim3(cdiv(n, 128), cdiv(n, 128), B * E), 256, SM_128x128>>>(p);

  softmax_rows_k<<<dim3(n, B * E), 256>>>(sco, n, n4);

  // 4. y[:, e*HD:(e+1)*HD] = (P @ V) * routing;  V is [HD][n4] per z
  reset();
  p.A = sco; p.lda = n4; p.as1 = (long long)n * n4;
  p.Bm = vt; p.ldb = n4; p.bs1 = (long long)HD * n4;
  p.C = y; p.ldc = D; p.cDiv = E; p.cs1 = (long long)n * D; p.cs2 = HD;
  p.M = n; p.N = HD; p.K = n;
  p.rout = rout; p.routN = n;
  tmma_k<128, 64, 64, 16, 3>
      <<<dim3(1, cdiv(n, 128), B * E), 256, SM_128x64>>>(p);

  // 5. a = y @ out_w + out_b   (owt is [D_n][D_k])
  reset();
  p.A = y; p.lda = D;
  p.Bm = owt; p.ldb = D;
  p.bias = w.ob + (long long)layer * D;
  p.C = a; p.ldc = D;
  p.M = M; p.N = D; p.K = D;
  tmma_k<128, 128, 64, 32, 0>
      <<<dim3(cdiv(D, 128), cdiv(M, 128), 1), 256, SM_128x128>>>(p);

  // 6. x1 = LN1(t + a)
  add_ln_k<true><<<M, 256>>>(t, a, w.l1g + (long long)layer * D,
                             w.l1b + (long long)layer * D, x1);

  // 7. h = gelu(x1 @ ff_w1 + ff_b1)   (w1t is [F][D])
  reset();
  p.A = x1; p.lda = D;
  p.Bm = w1t; p.ldb = D;
  p.bias = w.b1 + (long long)layer * F;
  p.C = h; p.ldc = F;
  p.M = M; p.N = F; p.K = D;
  tmma_k<128, 128, 64, 32, 1>
      <<<dim3(cdiv(F, 128), cdiv(M, 128), 1), 256, SM_128x128>>>(p);

  // 8. f = h @ ff_w2 + ff_b2 (into y)   (w2t is [D][F])
  reset();
  p.A = h; p.lda = F;
  p.Bm = w2t; p.ldb = F;
  p.bias = w.b2 + (long long)layer * D;
  p.C = y; p.ldc = D;
  p.M = M; p.N = D; p.K = F;
  tmma_k<128, 128, 64, 32, 0>
      <<<dim3(cdiv(D, 128), cdiv(M, 128), 1), 256, SM_128x128>>>(p);

  // 9. out = LN2(x1 + f); final layer output stays unrounded
  if (layer == L - 1)
    add_ln_k<false><<<M, 256>>>(x1, y, w.l2g + (long long)layer * D,
                                w.l2b + (long long)layer * D, out);
  else
    add_ln_k<true><<<M, 256>>>(x1, y, w.l2g + (long long)layer * D,
                               w.l2b + (long long)layer * D, out);
}

extern "C" void kernel_launch(void* const* d_in, const int* in_sizes, int n_in,
                              void* d_out, int out_size) {
  (void)in_sizes; (void)n_in; (void)out_size;
  float* sc = nullptr;
  cudaGetSymbolAddress((void**)&sc, g_scratch);

  cudaFuncSetAttribute((const void*)tmma_k<128, 64, 64, 16, 5>,
                       cudaFuncAttributeMaxDynamicSharedMemorySize, SM_128x64);
  cudaFuncSetAttribute((const void*)tmma_k<128, 64, 64, 16, 3>,
                       cudaFuncAttributeMaxDynamicSharedMemorySize, SM_128x64);
  cudaFuncSetAttribute((const void*)tmma_k<128, 128, 64, 32, 2>,
                       cudaFuncAttributeMaxDynamicSharedMemorySize, SM_128x128);
  cudaFuncSetAttribute((const void*)tmma_k<128, 128, 64, 32, 0>,
                       cudaFuncAttributeMaxDynamicSharedMemorySize, SM_128x128);
  cudaFuncSetAttribute((const void*)tmma_k<128, 128, 64, 32, 1>,
                       cudaFuncAttributeMaxDynamicSharedMemorySize, SM_128x128);

  const float* x_in = (const float*)d_in[0];
  Wts w;
  w.ew = (const float*)d_in[1];  w.eb = (const float*)d_in[2];
  w.rw = (const float*)d_in[3];  w.rb = (const float*)d_in[4];
  w.ow = (const float*)d_in[5];  w.ob = (const float*)d_in[6];
  w.l1g = (const float*)d_in[7]; w.l1b = (const float*)d_in[8];
  w.w1 = (const float*)d_in[9];  w.b1 = (const float*)d_in[10];
  w.w2 = (const float*)d_in[11]; w.b2 = (const float*)d_in[12];
  w.l2g = (const float*)d_in[13]; w.l2b = (const float*)d_in[14];

  // One-time weight transposes ([K][N] -> [N][K]) with tf32 rounding
  {
    dim3 thr(32, 8);
    transpose_k<<<dim3(cdiv(TH, 32), cdiv(D, 32), L * E), thr>>>(
        sc + OFF_EWT, w.ew, D, TH);
    transpose_k<<<dim3(cdiv(D, 32), cdiv(D, 32), L), thr>>>(
        sc + OFF_OWT, w.ow, D, D);
    transpose_k<<<dim3(cdiv(F, 32), cdiv(D, 32), L), thr>>>(
        sc + OFF_W1T, w.w1, D, F);
    transpose_k<<<dim3(cdiv(D, 32), cdiv(F, 32), L), thr>>>(
        sc + OFF_W2T, w.w2, F, D);
  }

  // x = round(input)
  copy_round_k<<<cdiv((int)NX, 256), 256>>>(sc + OFF_X, x_in, NX);

  run_block(sc, sc + OFF_X, sc + OFF_X, 0, S, w);

  for (int c = 0; c < CYCLES; c++) {
    zero_k<<<cdiv((int)NX, 256), 256>>>(sc + OFF_XNEW, NX);
    for (int j = 0; j < 4; j++) {
      int nseg = SEG_N[j];
      int tot = B * nseg * D;
      gather_k<<<cdiv(tot, 256), 256>>>(sc + OFF_T, sc + OFF_X, nseg, SEG_ST[j],
                                        SEG_P1[j]);
      run_block(sc, sc + OFF_T, sc + OFF_A, 1 + 4 * c + j, nseg, w);
      scatter_add_k<<<cdiv(tot, 256), 256>>>(sc + OFF_XNEW, sc + OFF_A, nseg,
                                             SEG_ST[j], SEG_P1[j]);
    }
    div_counts_k<<<cdiv((int)NX, 256), 256>>>(sc + OFF_X, sc + OFF_XNEW);
  }

  run_block(sc, sc + OFF_X, (float*)d_out, 13, S, w);
}

// round 9
// speedup vs baseline: 1.0659x; 1.0659x over previous
#include <cuda_runtime.h>
#include <math.h>
#include <stdint.h>

// ---------------------------------------------------------------------------
// SLAMv2: 14-layer MoE-attention transformer, segmented schedule.
// Round 9: R7 base (cp.async 4-stage, k-slot remap) + ONE change: weight
// operands transposed once to [N][K] so qkv/out/FF GEMMs take the BTRANS=1
// path (single LDS.64 B-fragments). Tiles/grids/epilogues/rounding = R7.
// ---------------------------------------------------------------------------

namespace {
constexpr int B = 2, S = 1024, D = 1000, E = 20, HD = 50, TH = 3 * HD;
constexpr int HD_P = 52;  // padded head dim
constexpr int F = 2048, CYCLES = 3, L = 14;

constexpr long long NX = (long long)B * S * D;  // 2,048,000
constexpr long long OFF_X    = 0;
constexpr long long OFF_XNEW = OFF_X + NX;
constexpr long long OFF_T    = OFF_XNEW + NX;
constexpr long long OFF_X1   = OFF_T + NX;
constexpr long long OFF_Y    = OFF_X1 + NX;
constexpr long long OFF_A    = OFF_Y + NX;
constexpr long long OFF_ROUT = OFF_A + NX;                       // B*S*E
constexpr long long OFF_H    = OFF_ROUT + (long long)B * S * E;  // B*S*F
constexpr long long OFF_QKV  = OFF_H + (long long)B * S * F;     // B*E*3*S*HD_P
constexpr long long OFF_SC   = OFF_QKV + (long long)B * E * 3 * S * HD_P;
constexpr long long OFF_EWT  = OFF_SC + (long long)B * E * S * S;  // [L,E,TH,D]
constexpr long long OFF_OWT  = OFF_EWT + (long long)L * E * TH * D;
constexpr long long OFF_W1T  = OFF_OWT + (long long)L * D * D;   // [L,F,D]
constexpr long long OFF_W2T  = OFF_W1T + (long long)L * D * F;   // [L,D,F]
constexpr long long TOTAL    = OFF_W2T + (long long)L * F * D;

// Segment schedule for S=1024: (0,460) (256,665) (460,870) (665,1024)+wrap 51
constexpr int SEG_ST[4] = {0, 256, 460, 665};
constexpr int SEG_N[4]  = {460, 409, 410, 410};
constexpr int SEG_P1[4] = {460, 409, 410, 359};
}  // namespace

__device__ float g_scratch[TOTAL];

struct GemmP {
  const float* A; const float* Bm; const float* bias; float* C;
  int M, N, K, lda, ldb, ldc;
  int aDiv; long long as1, as2;
  int bDiv; long long bs1, bs2;
  int cDiv; long long cs1, cs2;
  int biasDiv; long long biasS;
  long long splitStride;
  float scale;
  const float* rout; int routN;
};

__device__ __forceinline__ float to_tf32(float x) {
  asm("cvt.rna.tf32.f32 %0, %0;" : "+f"(x));
  return x;
}

__device__ __forceinline__ void cp16(uint32_t dst, const float* src, int bytes) {
  asm volatile("cp.async.cg.shared.global [%0], [%1], 16, %2;\n"
               :: "r"(dst), "l"(src), "r"(bytes));
}
__device__ __forceinline__ void cp_commit() {
  asm volatile("cp.async.commit_group;\n");
}
template <int N>
__device__ __forceinline__ void cp_wait() {
  asm volatile("cp.async.wait_group %0;\n" :: "n"(N));
}

// ---------------------------------------------------------------------------
// TF32 tensor-core GEMM; cp.async 4-stage ring; k-slot remap fragments.
// BTRANS: 0 -> B is [K,N] (smem Bs[k][n]); 1 -> B is [N,K] (smem Bs[n][k]).
// EPI: 0 +bias; 1 +bias,GELU(round); 2 *scale; 3 *routing(round);
//      4 +bias,split-QKV(round).
// ---------------------------------------------------------------------------
template <int BM, int BN, int WM, int WN, int BTRANS, int EPI>
__global__ __launch_bounds__(256) void tmma_k(GemmP p) {
  constexpr int BK = 16, ST = 4;
  constexpr int SKA = BK + 4;   // 20 floats, 80B rows (16B-aligned)
  constexpr int LDB0 = BN + 4;  // for BTRANS=0 layout
  constexpr int ASZ = BM * SKA;
  constexpr int BSZ = BTRANS ? BN * SKA : BK * LDB0;
  constexpr int NWN = BN / WN;
  constexpr int MT = WM / 16, NT = WN / 8;
  constexpr int AV_ = BM / 64;
  constexpr int BV_ = BN / 64;
  static_assert((BM / WM) * (BN / WN) == 8, "need 8 warps");

  extern __shared__ float sm[];
  float* As = sm;              // [ST][BM][SKA]
  float* Bs = sm + ST * ASZ;   // [ST][BSZ]
  const uint32_t a_u32 = (uint32_t)__cvta_generic_to_shared(As);
  const uint32_t b_u32 = (uint32_t)__cvta_generic_to_shared(Bs);

  const int z = blockIdx.z;
  const float* Ab =
      p.A + (long long)(z / p.aDiv) * p.as1 + (long long)(z % p.aDiv) * p.as2;
  const float* Bb =
      p.Bm + (long long)(z / p.bDiv) * p.bs1 + (long long)(z % p.bDiv) * p.bs2;
  float* Cb =
      p.C + (long long)(z / p.cDiv) * p.cs1 + (long long)(z % p.cDiv) * p.cs2;

  const int m0 = blockIdx.y * BM, n0 = blockIdx.x * BN;
  const int tid = threadIdx.x;
  const int warp = tid >> 5, lane = tid & 31;
  const int g = lane >> 2, t = lane & 3;
  const int wm = (warp / NWN) * WM, wn = (warp % NWN) * WN;

  auto issue = [&](int it) {
    const int s = it % ST;
    const int kb = it * BK;
#pragma unroll
    for (int v = 0; v < AV_; v++) {
      int idx = tid + v * 256;
      int m = idx >> 2, c4 = (idx & 3) * 4;
      int gm = m0 + m, gk = kb + c4;
      int by = 0;
      if (gm < p.M) {
        int rem = (p.K - gk) * 4;
        by = rem > 16 ? 16 : (rem > 0 ? rem : 0);
      }
      const float* src = Ab + (long long)(by ? gm : 0) * p.lda + (by ? gk : 0);
      cp16(a_u32 + (uint32_t)(s * ASZ + m * SKA + c4) * 4u, src, by);
    }
    if (BTRANS == 0) {
#pragma unroll
      for (int v = 0; v < BV_; v++) {
        int idx = tid + v * 256;
        int kk = idx / (BN / 4), n4 = (idx % (BN / 4)) * 4;
        int gk = kb + kk, gn = n0 + n4;
        int by = 0;
        if (gk < p.K) {
          int rem = (p.N - gn) * 4;
          by = rem > 16 ? 16 : (rem > 0 ? rem : 0);
        }
        const float* src = Bb + (long long)(by ? gk : 0) * p.ldb + (by ? gn : 0);
        cp16(b_u32 + (uint32_t)(s * BSZ + kk * LDB0 + n4) * 4u, src, by);
      }
    } else {
#pragma unroll
      for (int v = 0; v < BV_; v++) {
        int idx = tid + v * 256;
        int n = idx >> 2, c4 = (idx & 3) * 4;
        int gn = n0 + n, gk = kb + c4;
        int by = 0;
        if (gn < p.N) {
          int rem = (p.K - gk) * 4;
          by = rem > 16 ? 16 : (rem > 0 ? rem : 0);
        }
        const float* src = Bb + (long long)(by ? gn : 0) * p.ldb + (by ? gk : 0);
        cp16(b_u32 + (uint32_t)(s * BSZ + n * SKA + c4) * 4u, src, by);
      }
    }
  };

  float c[MT][NT][4];
#pragma unroll
  for (int i = 0; i < MT; i++)
#pragma unroll
    for (int j = 0; j < NT; j++)
#pragma unroll
      for (int r = 0; r < 4; r++) c[i][j][r] = 0.f;

  auto comp = [&](int s) {
    const float* Asb = As + s * ASZ;
    const float* Bsb = Bs + s * BSZ;
#pragma unroll
    for (int kq = 0; kq < 2; kq++) {
      const int ko = kq * 8 + 2 * t;
      float2 af[MT][2];
#pragma unroll
      for (int mt = 0; mt < MT; mt++) {
        int r0 = wm + mt * 16 + g;
        af[mt][0] = *reinterpret_cast<const float2*>(&Asb[r0 * SKA + ko]);
        af[mt][1] = *reinterpret_cast<const float2*>(&Asb[(r0 + 8) * SKA + ko]);
      }
      float bx[NT], by_[NT];
#pragma unroll
      for (int nt = 0; nt < NT; nt++) {
        int col = wn + nt * 8 + g;
        if (BTRANS == 1) {
          float2 bb = *reinterpret_cast<const float2*>(&Bsb[col * SKA + ko]);
          bx[nt] = bb.x;
          by_[nt] = bb.y;
        } else {
          bx[nt] = Bsb[ko * LDB0 + col];
          by_[nt] = Bsb[(ko + 1) * LDB0 + col];
        }
      }
#pragma unroll
      for (int mt = 0; mt < MT; mt++)
#pragma unroll
        for (int nt = 0; nt < NT; nt++) {
          asm volatile(
              "mma.sync.aligned.m16n8k8.row.col.f32.tf32.tf32.f32 "
              "{%0,%1,%2,%3}, {%4,%5,%6,%7}, {%8,%9}, {%0,%1,%2,%3};"
              : "+f"(c[mt][nt][0]), "+f"(c[mt][nt][1]), "+f"(c[mt][nt][2]),
                "+f"(c[mt][nt][3])
              : "r"(__float_as_uint(af[mt][0].x)),
                "r"(__float_as_uint(af[mt][1].x)),
                "r"(__float_as_uint(af[mt][0].y)),
                "r"(__float_as_uint(af[mt][1].y)),
                "r"(__float_as_uint(bx[nt])), "r"(__float_as_uint(by_[nt])));
        }
    }
  };

  const int iters = (p.K + BK - 1) / BK;
#pragma unroll
  for (int s = 0; s < ST - 1; s++) {
    if (s < iters) issue(s);
    cp_commit();
  }
  for (int it = 0; it < iters; it++) {
    cp_wait<ST - 2>();
    __syncthreads();
    if (it + ST - 1 < iters) issue(it + ST - 1);
    cp_commit();
    comp(it % ST);
  }

  const float* biasb = nullptr;
  if ((EPI == 0 || EPI == 1 || EPI == 4) && p.bias)
    biasb = p.bias + (long long)(z % p.biasDiv) * p.biasS;

#pragma unroll
  for (int mt = 0; mt < MT; mt++)
#pragma unroll
    for (int nt = 0; nt < NT; nt++)
#pragma unroll
      for (int r = 0; r < 4; r++) {
        int row = m0 + wm + mt * 16 + g + ((r >> 1) ? 8 : 0);
        int col = n0 + wn + nt * 8 + 2 * t + (r & 1);
        if (row >= p.M || col >= p.N) continue;
        float v = c[mt][nt][r];
        if (biasb) v += biasb[col];
        if (EPI == 1) {
          v = 0.5f * v * (1.f + erff(v * 0.70710678118654752f));
          v = to_tf32(v);
        }
        if (EPI == 2) v *= p.scale;
        if (EPI == 3) {
          v *= p.rout[((long long)(z / p.cDiv) * p.routN + row) * E +
                      (z % p.cDiv)];
          v = to_tf32(v);
        }
        if (EPI == 4) {
          v = to_tf32(v);
          int h = col / HD, s2 = col - h * HD;
          Cb[(long long)h * p.splitStride + (long long)row * p.ldc + s2] = v;
        } else {
          Cb[(long long)row * p.ldc + col] = v;
        }
      }
}

// ---------------------------------------------------------------------------
// SIMT SGEMM (tiny routing GEMM, N=20; fp32 for numeric stability)
// ---------------------------------------------------------------------------
template <int BM, int BN, int BK, int TM, int TN>
__global__ __launch_bounds__((BM / TM) * (BN / TN)) void sgemm2_k(GemmP p) {
  constexpr int NTHR = (BM / TM) * (BN / TN);
  constexpr int TX = BN / TN;
  __shared__ float As[BK][BM + 4];
  __shared__ float Bs[BK][BN + 4];

  const float* Ab = p.A;
  const float* Bb = p.Bm;
  float* Cb = p.C;

  const int m0 = blockIdx.y * BM, n0 = blockIdx.x * BN;
  const int tid = threadIdx.x;
  const int tx = tid % TX, ty = tid / TX;

  float acc[TM][TN];
#pragma unroll
  for (int i = 0; i < TM; i++)
#pragma unroll
    for (int j = 0; j < TN; j++) acc[i][j] = 0.f;

  for (int k0 = 0; k0 < p.K; k0 += BK) {
    for (int idx = tid; idx < BM * BK; idx += NTHR) {
      int m = idx / BK, kk = idx % BK;
      int gm = m0 + m, gk = k0 + kk;
      As[kk][m] = (gm < p.M && gk < p.K) ? Ab[(long long)gm * p.lda + gk] : 0.f;
    }
    for (int idx = tid; idx < BK * BN; idx += NTHR) {
      int kk = idx / BN, nn = idx % BN;
      int gk = k0 + kk, gn = n0 + nn;
      Bs[kk][nn] = (gk < p.K && gn < p.N) ? Bb[(long long)gk * p.ldb + gn] : 0.f;
    }
    __syncthreads();
#pragma unroll
    for (int kk = 0; kk < BK; kk++) {
      float a[TM], b[TN];
#pragma unroll
      for (int i = 0; i < TM; i++) a[i] = As[kk][ty * TM + i];
#pragma unroll
      for (int j = 0; j < TN; j++) b[j] = Bs[kk][tx * TN + j];
#pragma unroll
      for (int i = 0; i < TM; i++)
#pragma unroll
        for (int j = 0; j < TN; j++) acc[i][j] += a[i] * b[j];
    }
    __syncthreads();
  }

#pragma unroll
  for (int i = 0; i < TM; i++) {
    int row = m0 + ty * TM + i;
    if (row >= p.M) continue;
#pragma unroll
    for (int j = 0; j < TN; j++) {
      int col = n0 + tx * TN + j;
      if (col >= p.N) continue;
      float v = acc[i][j] + (p.bias ? p.bias[col] : 0.f);
      Cb[(long long)row * p.ldc + col] = v;
    }
  }
}

// ---------------------------------------------------------------------------
// Tiled batched transpose with tf32 rounding: src [z][K][N] -> dst [z][N][K]
// ---------------------------------------------------------------------------
__global__ void transpose_k(float* dst, const float* src, int K, int N) {
  __shared__ float tile[32][33];
  const long long zo = (long long)blockIdx.z * K * N;
  src += zo;
  dst += zo;
  int n0 = blockIdx.x * 32, k0 = blockIdx.y * 32;
  int tx = threadIdx.x, ty = threadIdx.y;  // 32 x 8
  for (int i = ty; i < 32; i += 8) {
    int k = k0 + i, n = n0 + tx;
    tile[i][tx] = (k < K && n < N) ? src[(long long)k * N + n] : 0.f;
  }
  __syncthreads();
  for (int i = ty; i < 32; i += 8) {
    int n = n0 + i, k = k0 + tx;
    if (n < N && k < K) dst[(long long)n * K + k] = to_tf32(tile[tx][i]);
  }
}

// ---------------------------------------------------------------------------
// Small kernels
// ---------------------------------------------------------------------------
__global__ void copy_round_k(float* dst, const float* src, long long n) {
  long long i = (long long)blockIdx.x * blockDim.x + threadIdx.x;
  if (i < n) dst[i] = to_tf32(src[i]);
}

__global__ void zero_k(float* dst, long long n) {
  long long i = (long long)blockIdx.x * blockDim.x + threadIdx.x;
  if (i < n) dst[i] = 0.f;
}

__global__ void gather_k(float* dst, const float* src, int nseg, int st, int p1) {
  long long i = (long long)blockIdx.x * blockDim.x + threadIdx.x;
  long long tot = (long long)B * nseg * D;
  if (i >= tot) return;
  int d = (int)(i % D);
  long long r = i / D;
  int ii = (int)(r % nseg);
  int b_ = (int)(r / nseg);
  int si = (ii < p1) ? (st + ii) : (ii - p1);
  dst[i] = src[((long long)b_ * S + si) * D + d];
}

__global__ void scatter_add_k(float* dst, const float* src, int nseg, int st,
                              int p1) {
  long long i = (long long)blockIdx.x * blockDim.x + threadIdx.x;
  long long tot = (long long)B * nseg * D;
  if (i >= tot) return;
  int d = (int)(i % D);
  long long r = i / D;
  int ii = (int)(r % nseg);
  int b_ = (int)(r / nseg);
  int si = (ii < p1) ? (st + ii) : (ii - p1);
  dst[((long long)b_ * S + si) * D + d] += src[i];
}

__device__ __forceinline__ float seg_cnt(int i) {
  float c = 0.f;
  c += (i < 460);
  c += (i >= 256 && i < 665);
  c += (i >= 460 && i < 870);
  c += (i >= 665);
  c += (i < 51);
  return c;
}

__global__ void div_counts_k(float* x, const float* xn) {
  long long i = (long long)blockIdx.x * blockDim.x + threadIdx.x;
  if (i >= NX) return;
  int ii = (int)((i / D) % S);
  x[i] = to_tf32(xn[i] / seg_cnt(ii));
}

__global__ void softmaxE_k(float* r, int rows) {
  int i = blockIdx.x * blockDim.x + threadIdx.x;
  if (i >= rows) return;
  float* p = r + (long long)i * E;
  float m = -1e30f;
  for (int e = 0; e < E; e++) m = fmaxf(m, p[e]);
  float s = 0.f;
  for (int e = 0; e < E; e++) {
    float v = __expf(p[e] - m);
    p[e] = v;
    s += v;
  }
  float inv = 1.f / s;
  for (int e = 0; e < E; e++) p[e] *= inv;
}

// In-place row softmax (output rounded to tf32 — feeds AV GEMM).
__global__ void softmax_rows_k(float* s, int n, int ld) {
  float* row = s + (long long)blockIdx.y * n * ld + (long long)blockIdx.x * ld;
  __shared__ float red[32];
  __shared__ float bcast;
  int tid = threadIdx.x;
  int nw = blockDim.x >> 5;

  float m = -1e30f;
  for (int j = tid; j < n; j += blockDim.x) m = fmaxf(m, row[j]);
  for (int o = 16; o; o >>= 1) m = fmaxf(m, __shfl_xor_sync(0xffffffffu, m, o));
  if ((tid & 31) == 0) red[tid >> 5] = m;
  __syncthreads();
  if (tid < 32) {
    float v = (tid < nw) ? red[tid] : -1e30f;
    for (int o = 16; o; o >>= 1) v = fmaxf(v, __shfl_xor_sync(0xffffffffu, v, o));
    if (tid == 0) bcast = v;
  }
  __syncthreads();
  m = bcast;

  float sum = 0.f;
  for (int j = tid; j < n; j += blockDim.x) {
    float e = __expf(row[j] - m);
    row[j] = e;
    sum += e;
  }
  for (int o = 16; o; o >>= 1) sum += __shfl_xor_sync(0xffffffffu, sum, o);
  if ((tid & 31) == 0) red[tid >> 5] = sum;
  __syncthreads();
  if (tid < 32) {
    float v = (tid < nw) ? red[tid] : 0.f;
    for (int o = 16; o; o >>= 1) v += __shfl_xor_sync(0xffffffffu, v, o);
    if (tid == 0) bcast = v;
  }
  __syncthreads();
  float inv = 1.f / bcast;
  for (int j = tid; j < n; j += blockDim.x) row[j] = to_tf32(row[j] * inv);
}

// out = layernorm(x + r) * g + b; CVT rounds output to tf32 (GEMM input).
template <bool CVT>
__global__ void add_ln_k(const float* x, const float* r, const float* g,
                         const float* b, float* out) {
  long long base = (long long)blockIdx.x * D;
  __shared__ float buf[D];
  __shared__ float redA[32], redB[32];
  __shared__ float sh_m, sh_inv;
  int tid = threadIdx.x;
  int nw = blockDim.x >> 5;

  float s = 0.f, s2 = 0.f;
  for (int d = tid; d < D; d += blockDim.x) {
    float v = x[base + d] + r[base + d];
    buf[d] = v;
    s += v;
    s2 += v * v;
  }
  for (int o = 16; o; o >>= 1) {
    s += __shfl_xor_sync(0xffffffffu, s, o);
    s2 += __shfl_xor_sync(0xffffffffu, s2, o);
  }
  if ((tid & 31) == 0) { redA[tid >> 5] = s; redB[tid >> 5] = s2; }
  __syncthreads();
  if (tid < 32) {
    float a2 = (tid < nw) ? redA[tid] : 0.f;
    float b2 = (tid < nw) ? redB[tid] : 0.f;
    for (int o = 16; o; o >>= 1) {
      a2 += __shfl_xor_sync(0xffffffffu, a2, o);
      b2 += __shfl_xor_sync(0xffffffffu, b2, o);
    }
    if (tid == 0) {
      float mean = a2 / D;
      float var = b2 / D - mean * mean;
      sh_m = mean;
      sh_inv = rsqrtf(var + 1e-5f);
    }
  }
  __syncthreads();
  float mean = sh_m, inv = sh_inv;
  for (int d = tid; d < D; d += blockDim.x) {
    float v = (buf[d] - mean) * inv * g[d] + b[d];
    out[base + d] = CVT ? to_tf32(v) : v;
  }
}

// ---------------------------------------------------------------------------
// Host-side driver
// ---------------------------------------------------------------------------
static inline int cdiv(int a, int b) { return (a + b - 1) / b; }

struct Wts {
  const float *ew, *eb, *rw, *rb, *ow, *ob, *l1g, *l1b, *w1, *b1, *w2, *b2,
      *l2g, *l2b;
};

// dynamic smem (ST=4, SKA=20)
constexpr int SM_128x64_T1 = 4 * (128 + 64) * 20 * 4;          // 61440
constexpr int SM_128x64_T0 = 4 * (128 * 20 + 16 * 68) * 4;     // 58368
constexpr int SM_128x128_T1 = 4 * (128 + 128) * 20 * 4;        // 81920
constexpr int SM_64x128_T1 = 4 * (64 + 128) * 20 * 4;          // 61440

static void run_block(float* sc, const float* t, float* out, int layer, int n,
                      const Wts& w) {
  const int M = B * n;
  const int n4 = (n + 3) & ~3;
  float* rout = sc + OFF_ROUT;
  float* qkv = sc + OFF_QKV;
  float* sco = sc + OFF_SC;
  float* y = sc + OFF_Y;
  float* a = sc + OFF_A;
  float* x1 = sc + OFF_X1;
  float* h = sc + OFF_H;
  const float* ewt = sc + OFF_EWT + (long long)layer * E * TH * D;
  const float* owt = sc + OFF_OWT + (long long)layer * D * D;
  const float* w1t = sc + OFF_W1T + (long long)layer * D * F;
  const float* w2t = sc + OFF_W2T + (long long)layer * F * D;

  GemmP p;
  auto reset = [&]() {
    p = GemmP{};
    p.aDiv = p.bDiv = p.cDiv = p.biasDiv = 1;
    p.scale = 1.f;
  };

  // 1. routing logits + softmax over experts (fp32 SIMT, N=20)
  reset();
  p.A = t; p.Bm = w.rw + (long long)layer * D * E;
  p.bias = w.rb + (long long)layer * E; p.C = rout;
  p.M = M; p.N = E; p.K = D; p.lda = D; p.ldb = E; p.ldc = E;
  sgemm2_k<64, 64, 16, 4, 4><<<dim3(1, cdiv(M, 64), 1), 256>>>(p);
  softmaxE_k<<<cdiv(M, 256), 256>>>(rout, M);

  // 2. qkv = t @ ewt[e]^T + eb[e], split-stored as Q/K/V [z][3][n][52]
  reset();
  p.A = t; p.lda = D; p.aDiv = E; p.as1 = (long long)n * D;
  p.Bm = ewt; p.ldb = D;  // [TH][D] per expert
  p.bDiv = E; p.bs2 = (long long)TH * D;
  p.bias = w.eb + (long long)layer * E * TH; p.biasDiv = E; p.biasS = TH;
  p.C = qkv; p.ldc = HD_P; p.cs1 = 3LL * n * HD_P;
  p.splitStride = (long long)n * HD_P;
  p.M = n; p.N = TH; p.K = D;
  tmma_k<128, 64, 32, 32, 1, 4>
      <<<dim3(3, cdiv(n, 128), B * E), 256, SM_128x64_T1>>>(p);

  // 3. scores = Q @ K^T * HD^-0.5 (NT), batched over (b,e)
  reset();
  p.A = qkv; p.lda = HD_P; p.as1 = 3LL * n * HD_P;
  p.Bm = qkv + (long long)n * HD_P; p.ldb = HD_P; p.bs1 = 3LL * n * HD_P;
  p.C = sco; p.ldc = n4; p.cs1 = (long long)n * n4;
  p.M = n; p.N = n; p.K = HD;
  p.scale = 0.14142135623730950488f;  // 1/sqrt(50)
  tmma_k<128, 128, 64, 32, 1, 2>
      <<<dim3(cdiv(n, 128), cdiv(n, 128), B * E), 256, SM_128x128_T1>>>(p);

  softmax_rows_k<<<dim3(n, B * E), 256>>>(sco, n, n4);

  // 4. y[:, e*HD:(e+1)*HD] = (P @ V) * routing[b, s, e]
  reset();
  p.A = sco; p.lda = n4; p.as1 = (long long)n * n4;
  p.Bm = qkv + 2LL * n * HD_P; p.ldb = HD_P; p.bs1 = 3LL * n * HD_P;
  p.C = y; p.ldc = D; p.cDiv = E; p.cs1 = (long long)n * D; p.cs2 = HD;
  p.M = n; p.N = HD; p.K = n;
  p.rout = rout; p.routN = n;
  tmma_k<128, 64, 32, 32, 0, 3>
      <<<dim3(1, cdiv(n, 128), B * E), 256, SM_128x64_T0>>>(p);

  // 5. a = y @ out_w + out_b  (owt [D_n][D_k])
  reset();
  p.A = y; p.lda = D;
  p.Bm = owt; p.ldb = D;
  p.bias = w.ob + (long long)layer * D;
  p.C = a; p.ldc = D;
  p.M = M; p.N = D; p.K = D;
  tmma_k<64, 128, 32, 32, 1, 0>
      <<<dim3(cdiv(D, 128), cdiv(M, 64), 1), 256, SM_64x128_T1>>>(p);

  // 6. x1 = LN1(t + a)
  add_ln_k<true><<<M, 256>>>(t, a, w.l1g + (long long)layer * D,
                             w.l1b + (long long)layer * D, x1);

  // 7. h = gelu(x1 @ ff_w1 + ff_b1)  (w1t [F][D])
  reset();
  p.A = x1; p.lda = D;
  p.Bm = w1t; p.ldb = D;
  p.bias = w.b1 + (long long)layer * F;
  p.C = h; p.ldc = F;
  p.M = M; p.N = F; p.K = D;
  tmma_k<64, 128, 32, 32, 1, 1>
      <<<dim3(cdiv(F, 128), cdiv(M, 64), 1), 256, SM_64x128_T1>>>(p);

  // 8. f = h @ ff_w2 + ff_b2 (into y)  (w2t [D][F])
  reset();
  p.A = h; p.lda = F;
  p.Bm = w2t; p.ldb = F;
  p.bias = w.b2 + (long long)layer * D;
  p.C = y; p.ldc = D;
  p.M = M; p.N = D; p.K = F;
  tmma_k<64, 128, 32, 32, 1, 0>
      <<<dim3(cdiv(D, 128), cdiv(M, 64), 1), 256, SM_64x128_T1>>>(p);

  // 9. out = LN2(x1 + f); final layer output stays unrounded
  if (layer == L - 1)
    add_ln_k<false><<<M, 256>>>(x1, y, w.l2g + (long long)layer * D,
                                w.l2b + (long long)layer * D, out);
  else
    add_ln_k<true><<<M, 256>>>(x1, y, w.l2g + (long long)layer * D,
                               w.l2b + (long long)layer * D, out);
}

extern "C" void kernel_launch(void* const* d_in, const int* in_sizes, int n_in,
                              void* d_out, int out_size) {
  (void)in_sizes; (void)n_in; (void)out_size;
  float* sc = nullptr;
  cudaGetSymbolAddress((void**)&sc, g_scratch);

  cudaFuncSetAttribute((const void*)tmma_k<128, 64, 32, 32, 1, 4>,
                       cudaFuncAttributeMaxDynamicSharedMemorySize,
                       SM_128x64_T1);
  cudaFuncSetAttribute((const void*)tmma_k<128, 64, 32, 32, 0, 3>,
                       cudaFuncAttributeMaxDynamicSharedMemorySize,
                       SM_128x64_T0);
  cudaFuncSetAttribute((const void*)tmma_k<128, 128, 64, 32, 1, 2>,
                       cudaFuncAttributeMaxDynamicSharedMemorySize,
                       SM_128x128_T1);
  cudaFuncSetAttribute((const void*)tmma_k<64, 128, 32, 32, 1, 0>,
                       cudaFuncAttributeMaxDynamicSharedMemorySize,
                       SM_64x128_T1);
  cudaFuncSetAttribute((const void*)tmma_k<64, 128, 32, 32, 1, 1>,
                       cudaFuncAttributeMaxDynamicSharedMemorySize,
                       SM_64x128_T1);

  const float* x_in = (const float*)d_in[0];
  Wts w;
  w.ew = (const float*)d_in[1];  w.eb = (const float*)d_in[2];
  w.rw = (const float*)d_in[3];  w.rb = (const float*)d_in[4];
  w.ow = (const float*)d_in[5];  w.ob = (const float*)d_in[6];
  w.l1g = (const float*)d_in[7]; w.l1b = (const float*)d_in[8];
  w.w1 = (const float*)d_in[9];  w.b1 = (const float*)d_in[10];
  w.w2 = (const float*)d_in[11]; w.b2 = (const float*)d_in[12];
  w.l2g = (const float*)d_in[13]; w.l2b = (const float*)d_in[14];

  // One-time weight transposes ([K][N] -> [N][K]) with tf32 rounding
  {
    dim3 thr(32, 8);
    transpose_k<<<dim3(cdiv(TH, 32), cdiv(D, 32), L * E), thr>>>(
        sc + OFF_EWT, w.ew, D, TH);
    transpose_k<<<dim3(cdiv(D, 32), cdiv(D, 32), L), thr>>>(
        sc + OFF_OWT, w.ow, D, D);
    transpose_k<<<dim3(cdiv(F, 32), cdiv(D, 32), L), thr>>>(
        sc + OFF_W1T, w.w1, D, F);
    transpose_k<<<dim3(cdiv(D, 32), cdiv(F, 32), L), thr>>>(
        sc + OFF_W2T, w.w2, F, D);
  }

  // x = round(input)
  copy_round_k<<<cdiv((int)NX, 256), 256>>>(sc + OFF_X, x_in, NX);

  run_block(sc, sc + OFF_X, sc + OFF_X, 0, S, w);

  for (int c = 0; c < CYCLES; c++) {
    zero_k<<<cdiv((int)NX, 256), 256>>>(sc + OFF_XNEW, NX);
    for (int j = 0; j < 4; j++) {
      int nseg = SEG_N[j];
      int tot = B * nseg * D;
      gather_k<<<cdiv(tot, 256), 256>>>(sc + OFF_T, sc + OFF_X, nseg, SEG_ST[j],
                                        SEG_P1[j]);
      run_block(sc, sc + OFF_T, sc + OFF_A, 1 + 4 * c + j, nseg, w);
      scatter_add_k<<<cdiv(tot, 256), 256>>>(sc + OFF_XNEW, sc + OFF_A, nseg,
                                             SEG_ST[j], SEG_P1[j]);
    }
    div_counts_k<<<cdiv((int)NX, 256), 256>>>(sc + OFF_X, sc + OFF_XNEW);
  }

  run_block(sc, sc + OFF_X, (float*)d_out, 13, S, w);
}

// round 10
// speedup vs baseline: 1.1410x; 1.0705x over previous
#include <cuda_runtime.h>
#include <math.h>
#include <stdint.h>

// ---------------------------------------------------------------------------
// SLAMv2: 14-layer MoE-attention transformer, segmented schedule.
// Round 10: R7 base (best, 8.48ms) + merged one-launch weight prep (same
// numerics, frees ncu window) + 32x128 tile for segment-sized out/FF2 GEMMs
// (104 -> 208+ blocks, full SM coverage). Everything else identical to R7.
// ---------------------------------------------------------------------------

namespace {
constexpr int B = 2, S = 1024, D = 1000, E = 20, HD = 50, TH = 3 * HD;
constexpr int HD_P = 52;    // padded head dim
constexpr int TH_P = 160;   // padded qkv width (16B-aligned rows for cp.async)
constexpr int F = 2048, CYCLES = 3, L = 14;

constexpr long long NX = (long long)B * S * D;  // 2,048,000
constexpr long long OFF_X    = 0;
constexpr long long OFF_XNEW = OFF_X + NX;
constexpr long long OFF_T    = OFF_XNEW + NX;
constexpr long long OFF_X1   = OFF_T + NX;
constexpr long long OFF_Y    = OFF_X1 + NX;
constexpr long long OFF_A    = OFF_Y + NX;
constexpr long long OFF_ROUT = OFF_A + NX;                       // B*S*E
constexpr long long OFF_H    = OFF_ROUT + (long long)B * S * E;  // B*S*F
constexpr long long OFF_QKV  = OFF_H + (long long)B * S * F;     // B*E*3*S*HD_P
constexpr long long OFF_SC   = OFF_QKV + (long long)B * E * 3 * S * HD_P;
constexpr long long OFF_EWP  = OFF_SC + (long long)B * E * S * S;
constexpr long long OFF_OWR  = OFF_EWP + (long long)L * E * D * TH_P;
constexpr long long OFF_W1R  = OFF_OWR + (long long)L * D * D;
constexpr long long OFF_W2R  = OFF_W1R + (long long)L * D * F;
constexpr long long TOTAL    = OFF_W2R + (long long)L * F * D;

// Segment schedule for S=1024: (0,460) (256,665) (460,870) (665,1024)+wrap 51
constexpr int SEG_ST[4] = {0, 256, 460, 665};
constexpr int SEG_N[4]  = {460, 409, 410, 410};
constexpr int SEG_P1[4] = {460, 409, 410, 359};
}  // namespace

__device__ float g_scratch[TOTAL];

struct GemmP {
  const float* A; const float* Bm; const float* bias; float* C;
  int M, N, K, lda, ldb, ldc;
  int aDiv; long long as1, as2;
  int bDiv; long long bs1, bs2;
  int cDiv; long long cs1, cs2;
  int biasDiv; long long biasS;
  long long splitStride;
  float scale;
  const float* rout; int routN;
};

__device__ __forceinline__ float to_tf32(float x) {
  asm("cvt.rna.tf32.f32 %0, %0;" : "+f"(x));
  return x;
}

__device__ __forceinline__ void cp16(uint32_t dst, const float* src, int bytes) {
  asm volatile("cp.async.cg.shared.global [%0], [%1], 16, %2;\n"
               :: "r"(dst), "l"(src), "r"(bytes));
}
__device__ __forceinline__ void cp_commit() {
  asm volatile("cp.async.commit_group;\n");
}
template <int N>
__device__ __forceinline__ void cp_wait() {
  asm volatile("cp.async.wait_group %0;\n" :: "n"(N));
}

// ---------------------------------------------------------------------------
// TF32 tensor-core GEMM; cp.async 4-stage ring; k-slot remap fragments.
// BTRANS: 0 -> B is [K,N] (smem Bs[k][n]); 1 -> B is [N,K] (smem Bs[n][k]).
// EPI: 0 +bias; 1 +bias,GELU(round); 2 *scale; 3 *routing(round);
//      4 +bias,split-QKV(round).
// Inputs assumed pre-rounded to tf32 by producers.
// ---------------------------------------------------------------------------
template <int BM, int BN, int WM, int WN, int BTRANS, int EPI>
__global__ __launch_bounds__(256) void tmma_k(GemmP p) {
  constexpr int BK = 16, ST = 4;
  constexpr int SKA = BK + 4;   // 20 floats, 80B rows (16B-aligned)
  constexpr int LDB0 = BN + 4;  // for BTRANS=0 layout
  constexpr int ASZ = BM * SKA;
  constexpr int BSZ = BTRANS ? BN * SKA : BK * LDB0;
  constexpr int NWN = BN / WN;
  constexpr int MT = WM / 16, NT = WN / 8;
  constexpr int ACH = BM * 4;                   // 16B A-chunks per stage
  constexpr int AV_ = (ACH + 255) / 256;
  constexpr int BV_ = BN / 64;
  static_assert((BM / WM) * (BN / WN) == 8, "need 8 warps");

  extern __shared__ float sm[];
  float* As = sm;              // [ST][BM][SKA]
  float* Bs = sm + ST * ASZ;   // [ST][BSZ]
  const uint32_t a_u32 = (uint32_t)__cvta_generic_to_shared(As);
  const uint32_t b_u32 = (uint32_t)__cvta_generic_to_shared(Bs);

  const int z = blockIdx.z;
  const float* Ab =
      p.A + (long long)(z / p.aDiv) * p.as1 + (long long)(z % p.aDiv) * p.as2;
  const float* Bb =
      p.Bm + (long long)(z / p.bDiv) * p.bs1 + (long long)(z % p.bDiv) * p.bs2;
  float* Cb =
      p.C + (long long)(z / p.cDiv) * p.cs1 + (long long)(z % p.cDiv) * p.cs2;

  const int m0 = blockIdx.y * BM, n0 = blockIdx.x * BN;
  const int tid = threadIdx.x;
  const int warp = tid >> 5, lane = tid & 31;
  const int g = lane >> 2, t = lane & 3;
  const int wm = (warp / NWN) * WM, wn = (warp % NWN) * WN;

  auto issue = [&](int it) {
    const int s = it % ST;
    const int kb = it * BK;
#pragma unroll
    for (int v = 0; v < AV_; v++) {
      int idx = tid + v * 256;
      if ((ACH % 256) != 0 && idx >= ACH) break;
      int m = idx >> 2, c4 = (idx & 3) * 4;
      int gm = m0 + m, gk = kb + c4;
      int by = 0;
      if (gm < p.M) {
        int rem = (p.K - gk) * 4;
        by = rem > 16 ? 16 : (rem > 0 ? rem : 0);
      }
      const float* src = Ab + (long long)(by ? gm : 0) * p.lda + (by ? gk : 0);
      cp16(a_u32 + (uint32_t)(s * ASZ + m * SKA + c4) * 4u, src, by);
    }
    if (BTRANS == 0) {
#pragma unroll
      for (int v = 0; v < BV_; v++) {
        int idx = tid + v * 256;
        int kk = idx / (BN / 4), n4 = (idx % (BN / 4)) * 4;
        int gk = kb + kk, gn = n0 + n4;
        int by = 0;
        if (gk < p.K) {
          int rem = (p.N - gn) * 4;
          by = rem > 16 ? 16 : (rem > 0 ? rem : 0);
        }
        const float* src = Bb + (long long)(by ? gk : 0) * p.ldb + (by ? gn : 0);
        cp16(b_u32 + (uint32_t)(s * BSZ + kk * LDB0 + n4) * 4u, src, by);
      }
    } else {
#pragma unroll
      for (int v = 0; v < BV_; v++) {
        int idx = tid + v * 256;
        int n = idx >> 2, c4 = (idx & 3) * 4;
        int gn = n0 + n, gk = kb + c4;
        int by = 0;
        if (gn < p.N) {
          int rem = (p.K - gk) * 4;
          by = rem > 16 ? 16 : (rem > 0 ? rem : 0);
        }
        const float* src = Bb + (long long)(by ? gn : 0) * p.ldb + (by ? gk : 0);
        cp16(b_u32 + (uint32_t)(s * BSZ + n * SKA + c4) * 4u, src, by);
      }
    }
  };

  float c[MT][NT][4];
#pragma unroll
  for (int i = 0; i < MT; i++)
#pragma unroll
    for (int j = 0; j < NT; j++)
#pragma unroll
      for (int r = 0; r < 4; r++) c[i][j][r] = 0.f;

  auto comp = [&](int s) {
    const float* Asb = As + s * ASZ;
    const float* Bsb = Bs + s * BSZ;
#pragma unroll
    for (int kq = 0; kq < 2; kq++) {
      const int ko = kq * 8 + 2 * t;
      float2 af[MT][2];
#pragma unroll
      for (int mt = 0; mt < MT; mt++) {
        int r0 = wm + mt * 16 + g;
        af[mt][0] = *reinterpret_cast<const float2*>(&Asb[r0 * SKA + ko]);
        af[mt][1] = *reinterpret_cast<const float2*>(&Asb[(r0 + 8) * SKA + ko]);
      }
      float bx[NT], by_[NT];
#pragma unroll
      for (int nt = 0; nt < NT; nt++) {
        int col = wn + nt * 8 + g;
        if (BTRANS == 1) {
          float2 bb = *reinterpret_cast<const float2*>(&Bsb[col * SKA + ko]);
          bx[nt] = bb.x;
          by_[nt] = bb.y;
        } else {
          bx[nt] = Bsb[ko * LDB0 + col];
          by_[nt] = Bsb[(ko + 1) * LDB0 + col];
        }
      }
#pragma unroll
      for (int mt = 0; mt < MT; mt++)
#pragma unroll
        for (int nt = 0; nt < NT; nt++) {
          asm volatile(
              "mma.sync.aligned.m16n8k8.row.col.f32.tf32.tf32.f32 "
              "{%0,%1,%2,%3}, {%4,%5,%6,%7}, {%8,%9}, {%0,%1,%2,%3};"
              : "+f"(c[mt][nt][0]), "+f"(c[mt][nt][1]), "+f"(c[mt][nt][2]),
                "+f"(c[mt][nt][3])
              : "r"(__float_as_uint(af[mt][0].x)),
                "r"(__float_as_uint(af[mt][1].x)),
                "r"(__float_as_uint(af[mt][0].y)),
                "r"(__float_as_uint(af[mt][1].y)),
                "r"(__float_as_uint(bx[nt])), "r"(__float_as_uint(by_[nt])));
        }
    }
  };

  const int iters = (p.K + BK - 1) / BK;
#pragma unroll
  for (int s = 0; s < ST - 1; s++) {
    if (s < iters) issue(s);
    cp_commit();
  }
  for (int it = 0; it < iters; it++) {
    cp_wait<ST - 2>();
    __syncthreads();
    if (it + ST - 1 < iters) issue(it + ST - 1);
    cp_commit();
    comp(it % ST);
  }

  const float* biasb = nullptr;
  if ((EPI == 0 || EPI == 1 || EPI == 4) && p.bias)
    biasb = p.bias + (long long)(z % p.biasDiv) * p.biasS;

#pragma unroll
  for (int mt = 0; mt < MT; mt++)
#pragma unroll
    for (int nt = 0; nt < NT; nt++)
#pragma unroll
      for (int r = 0; r < 4; r++) {
        int row = m0 + wm + mt * 16 + g + ((r >> 1) ? 8 : 0);
        int col = n0 + wn + nt * 8 + 2 * t + (r & 1);
        if (row >= p.M || col >= p.N) continue;
        float v = c[mt][nt][r];
        if (biasb) v += biasb[col];
        if (EPI == 1) {
          v = 0.5f * v * (1.f + erff(v * 0.70710678118654752f));
          v = to_tf32(v);
        }
        if (EPI == 2) v *= p.scale;
        if (EPI == 3) {
          v *= p.rout[((long long)(z / p.cDiv) * p.routN + row) * E +
                      (z % p.cDiv)];
          v = to_tf32(v);
        }
        if (EPI == 4) {
          v = to_tf32(v);
          int h = col / HD, s2 = col - h * HD;
          Cb[(long long)h * p.splitStride + (long long)row * p.ldc + s2] = v;
        } else {
          Cb[(long long)row * p.ldc + col] = v;
        }
      }
}

// ---------------------------------------------------------------------------
// SIMT SGEMM (tiny routing GEMM, N=20; fp32 for numeric stability)
// ---------------------------------------------------------------------------
template <int BM, int BN, int BK, int TM, int TN>
__global__ __launch_bounds__((BM / TM) * (BN / TN)) void sgemm2_k(GemmP p) {
  constexpr int NTHR = (BM / TM) * (BN / TN);
  constexpr int TX = BN / TN;
  __shared__ float As[BK][BM + 4];
  __shared__ float Bs[BK][BN + 4];

  const float* Ab = p.A;
  const float* Bb = p.Bm;
  float* Cb = p.C;

  const int m0 = blockIdx.y * BM, n0 = blockIdx.x * BN;
  const int tid = threadIdx.x;
  const int tx = tid % TX, ty = tid / TX;

  float acc[TM][TN];
#pragma unroll
  for (int i = 0; i < TM; i++)
#pragma unroll
    for (int j = 0; j < TN; j++) acc[i][j] = 0.f;

  for (int k0 = 0; k0 < p.K; k0 += BK) {
    for (int idx = tid; idx < BM * BK; idx += NTHR) {
      int m = idx / BK, kk = idx % BK;
      int gm = m0 + m, gk = k0 + kk;
      As[kk][m] = (gm < p.M && gk < p.K) ? Ab[(long long)gm * p.lda + gk] : 0.f;
    }
    for (int idx = tid; idx < BK * BN; idx += NTHR) {
      int kk = idx / BN, nn = idx % BN;
      int gk = k0 + kk, gn = n0 + nn;
      Bs[kk][nn] = (gk < p.K && gn < p.N) ? Bb[(long long)gk * p.ldb + gn] : 0.f;
    }
    __syncthreads();
#pragma unroll
    for (int kk = 0; kk < BK; kk++) {
      float a[TM], b[TN];
#pragma unroll
      for (int i = 0; i < TM; i++) a[i] = As[kk][ty * TM + i];
#pragma unroll
      for (int j = 0; j < TN; j++) b[j] = Bs[kk][tx * TN + j];
#pragma unroll
      for (int i = 0; i < TM; i++)
#pragma unroll
        for (int j = 0; j < TN; j++) acc[i][j] += a[i] * b[j];
    }
    __syncthreads();
  }

#pragma unroll
  for (int i = 0; i < TM; i++) {
    int row = m0 + ty * TM + i;
    if (row >= p.M) continue;
#pragma unroll
    for (int j = 0; j < TN; j++) {
      int col = n0 + tx * TN + j;
      if (col >= p.N) continue;
      float v = acc[i][j] + (p.bias ? p.bias[col] : 0.f);
      Cb[(long long)row * p.ldc + col] = v;
    }
  }
}

// ---------------------------------------------------------------------------
// One-launch weight prep: ew -> padded+rounded [L,E,D,160]; ow/w1/w2 rounded.
// Same per-element math as R7's four kernels (identical numerics).
// ---------------------------------------------------------------------------
__global__ void prep_k(float* sc, const float* ew, const float* ow,
                       const float* w1, const float* w2) {
  const long long n_ewp = (long long)L * E * D * TH_P;
  const long long n_ow = (long long)L * D * D;
  const long long n_w1 = (long long)L * D * F;
  const long long n_w2 = (long long)L * F * D;
  long long i = (long long)blockIdx.x * blockDim.x + threadIdx.x;
  if (i < n_ewp) {
    int col = (int)(i % TH_P);
    long long base = i / TH_P;
    sc[OFF_EWP + i] = (col < TH) ? to_tf32(ew[base * TH + col]) : 0.f;
    return;
  }
  i -= n_ewp;
  if (i < n_ow) { sc[OFF_OWR + i] = to_tf32(ow[i]); return; }
  i -= n_ow;
  if (i < n_w1) { sc[OFF_W1R + i] = to_tf32(w1[i]); return; }
  i -= n_w1;
  if (i < n_w2) { sc[OFF_W2R + i] = to_tf32(w2[i]); }
}

// ---------------------------------------------------------------------------
// Small kernels
// ---------------------------------------------------------------------------
__global__ void copy_round_k(float* dst, const float* src, long long n) {
  long long i = (long long)blockIdx.x * blockDim.x + threadIdx.x;
  if (i < n) dst[i] = to_tf32(src[i]);
}

__global__ void zero_k(float* dst, long long n) {
  long long i = (long long)blockIdx.x * blockDim.x + threadIdx.x;
  if (i < n) dst[i] = 0.f;
}

__global__ void gather_k(float* dst, const float* src, int nseg, int st, int p1) {
  long long i = (long long)blockIdx.x * blockDim.x + threadIdx.x;
  long long tot = (long long)B * nseg * D;
  if (i >= tot) return;
  int d = (int)(i % D);
  long long r = i / D;
  int ii = (int)(r % nseg);
  int b_ = (int)(r / nseg);
  int si = (ii < p1) ? (st + ii) : (ii - p1);
  dst[i] = src[((long long)b_ * S + si) * D + d];
}

__global__ void scatter_add_k(float* dst, const float* src, int nseg, int st,
                              int p1) {
  long long i = (long long)blockIdx.x * blockDim.x + threadIdx.x;
  long long tot = (long long)B * nseg * D;
  if (i >= tot) return;
  int d = (int)(i % D);
  long long r = i / D;
  int ii = (int)(r % nseg);
  int b_ = (int)(r / nseg);
  int si = (ii < p1) ? (st + ii) : (ii - p1);
  dst[((long long)b_ * S + si) * D + d] += src[i];
}

__device__ __forceinline__ float seg_cnt(int i) {
  float c = 0.f;
  c += (i < 460);
  c += (i >= 256 && i < 665);
  c += (i >= 460 && i < 870);
  c += (i >= 665);
  c += (i < 51);
  return c;
}

__global__ void div_counts_k(float* x, const float* xn) {
  long long i = (long long)blockIdx.x * blockDim.x + threadIdx.x;
  if (i >= NX) return;
  int ii = (int)((i / D) % S);
  x[i] = to_tf32(xn[i] / seg_cnt(ii));
}

__global__ void softmaxE_k(float* r, int rows) {
  int i = blockIdx.x * blockDim.x + threadIdx.x;
  if (i >= rows) return;
  float* p = r + (long long)i * E;
  float m = -1e30f;
  for (int e = 0; e < E; e++) m = fmaxf(m, p[e]);
  float s = 0.f;
  for (int e = 0; e < E; e++) {
    float v = __expf(p[e] - m);
    p[e] = v;
    s += v;
  }
  float inv = 1.f / s;
  for (int e = 0; e < E; e++) p[e] *= inv;
}

// In-place row softmax (output rounded to tf32 — feeds AV GEMM).
__global__ void softmax_rows_k(float* s, int n, int ld) {
  float* row = s + (long long)blockIdx.y * n * ld + (long long)blockIdx.x * ld;
  __shared__ float red[32];
  __shared__ float bcast;
  int tid = threadIdx.x;
  int nw = blockDim.x >> 5;

  float m = -1e30f;
  for (int j = tid; j < n; j += blockDim.x) m = fmaxf(m, row[j]);
  for (int o = 16; o; o >>= 1) m = fmaxf(m, __shfl_xor_sync(0xffffffffu, m, o));
  if ((tid & 31) == 0) red[tid >> 5] = m;
  __syncthreads();
  if (tid < 32) {
    float v = (tid < nw) ? red[tid] : -1e30f;
    for (int o = 16; o; o >>= 1) v = fmaxf(v, __shfl_xor_sync(0xffffffffu, v, o));
    if (tid == 0) bcast = v;
  }
  __syncthreads();
  m = bcast;

  float sum = 0.f;
  for (int j = tid; j < n; j += blockDim.x) {
    float e = __expf(row[j] - m);
    row[j] = e;
    sum += e;
  }
  for (int o = 16; o; o >>= 1) sum += __shfl_xor_sync(0xffffffffu, sum, o);
  if ((tid & 31) == 0) red[tid >> 5] = sum;
  __syncthreads();
  if (tid < 32) {
    float v = (tid < nw) ? red[tid] : 0.f;
    for (int o = 16; o; o >>= 1) v += __shfl_xor_sync(0xffffffffu, v, o);
    if (tid == 0) bcast = v;
  }
  __syncthreads();
  float inv = 1.f / bcast;
  for (int j = tid; j < n; j += blockDim.x) row[j] = to_tf32(row[j] * inv);
}

// out = layernorm(x + r) * g + b; CVT rounds output to tf32 (GEMM input).
template <bool CVT>
__global__ void add_ln_k(const float* x, const float* r, const float* g,
                         const float* b, float* out) {
  long long base = (long long)blockIdx.x * D;
  __shared__ float buf[D];
  __shared__ float redA[32], redB[32];
  __shared__ float sh_m, sh_inv;
  int tid = threadIdx.x;
  int nw = blockDim.x >> 5;

  float s = 0.f, s2 = 0.f;
  for (int d = tid; d < D; d += blockDim.x) {
    float v = x[base + d] + r[base + d];
    buf[d] = v;
    s += v;
    s2 += v * v;
  }
  for (int o = 16; o; o >>= 1) {
    s += __shfl_xor_sync(0xffffffffu, s, o);
    s2 += __shfl_xor_sync(0xffffffffu, s2, o);
  }
  if ((tid & 31) == 0) { redA[tid >> 5] = s; redB[tid >> 5] = s2; }
  __syncthreads();
  if (tid < 32) {
    float a2 = (tid < nw) ? redA[tid] : 0.f;
    float b2 = (tid < nw) ? redB[tid] : 0.f;
    for (int o = 16; o; o >>= 1) {
      a2 += __shfl_xor_sync(0xffffffffu, a2, o);
      b2 += __shfl_xor_sync(0xffffffffu, b2, o);
    }
    if (tid == 0) {
      float mean = a2 / D;
      float var = b2 / D - mean * mean;
      sh_m = mean;
      sh_inv = rsqrtf(var + 1e-5f);
    }
  }
  __syncthreads();
  float mean = sh_m, inv = sh_inv;
  for (int d = tid; d < D; d += blockDim.x) {
    float v = (buf[d] - mean) * inv * g[d] + b[d];
    out[base + d] = CVT ? to_tf32(v) : v;
  }
}

// ---------------------------------------------------------------------------
// Host-side driver
// ---------------------------------------------------------------------------
static inline int cdiv(int a, int b) { return (a + b - 1) / b; }

struct Wts {
  const float *ew, *eb, *rw, *rb, *ow, *ob, *l1g, *l1b, *w1, *b1, *w2, *b2,
      *l2g, *l2b;
};

// dynamic smem sizes per instantiation (ST=4, SKA=20)
constexpr int SMEM_128x64_T0 = 4 * (128 * 20 + 16 * 68) * 4;    // 58368
constexpr int SMEM_128x128_T1 = 4 * (128 * 20 + 128 * 20) * 4;  // 81920
constexpr int SMEM_64x128_T0 = 4 * (64 * 20 + 16 * 132) * 4;    // 54272
constexpr int SMEM_32x128_T0 = 4 * (32 * 20 + 16 * 132) * 4;    // 44032

static void run_block(float* sc, const float* t, float* out, int layer, int n,
                      const Wts& w) {
  const int M = B * n;
  const int n4 = (n + 3) & ~3;
  float* rout = sc + OFF_ROUT;
  float* qkv = sc + OFF_QKV;
  float* sco = sc + OFF_SC;
  float* y = sc + OFF_Y;
  float* a = sc + OFF_A;
  float* x1 = sc + OFF_X1;
  float* h = sc + OFF_H;
  const float* ewp = sc + OFF_EWP + (long long)layer * E * D * TH_P;
  const float* owr = sc + OFF_OWR + (long long)layer * D * D;
  const float* w1r = sc + OFF_W1R + (long long)layer * D * F;
  const float* w2r = sc + OFF_W2R + (long long)layer * F * D;

  GemmP p;
  auto reset = [&]() {
    p = GemmP{};
    p.aDiv = p.bDiv = p.cDiv = p.biasDiv = 1;
    p.scale = 1.f;
  };

  // 1. routing logits + softmax over experts (fp32 SIMT, N=20)
  reset();
  p.A = t; p.Bm = w.rw + (long long)layer * D * E;
  p.bias = w.rb + (long long)layer * E; p.C = rout;
  p.M = M; p.N = E; p.K = D; p.lda = D; p.ldb = E; p.ldc = E;
  sgemm2_k<64, 64, 16, 4, 4><<<dim3(1, cdiv(M, 64), 1), 256>>>(p);
  softmaxE_k<<<cdiv(M, 256), 256>>>(rout, M);

  // 2. qkv = t @ ewp[e] + eb[e], split-stored as Q/K/V [z][3][n][52]
  reset();
  p.A = t; p.lda = D; p.aDiv = E; p.as1 = (long long)n * D;
  p.Bm = ewp; p.ldb = TH_P;
  p.bDiv = E; p.bs2 = (long long)D * TH_P;
  p.bias = w.eb + (long long)layer * E * TH; p.biasDiv = E; p.biasS = TH;
  p.C = qkv; p.ldc = HD_P; p.cs1 = 3LL * n * HD_P;
  p.splitStride = (long long)n * HD_P;
  p.M = n; p.N = TH; p.K = D;
  tmma_k<128, 64, 32, 32, 0, 4>
      <<<dim3(3, cdiv(n, 128), B * E), 256, SMEM_128x64_T0>>>(p);

  // 3. scores = Q @ K^T * HD^-0.5 (NT), batched over (b,e)
  reset();
  p.A = qkv; p.lda = HD_P; p.as1 = 3LL * n * HD_P;
  p.Bm = qkv + (long long)n * HD_P; p.ldb = HD_P; p.bs1 = 3LL * n * HD_P;
  p.C = sco; p.ldc = n4; p.cs1 = (long long)n * n4;
  p.M = n; p.N = n; p.K = HD;
  p.scale = 0.14142135623730950488f;  // 1/sqrt(50)
  tmma_k<128, 128, 64, 32, 1, 2>
      <<<dim3(cdiv(n, 128), cdiv(n, 128), B * E), 256, SMEM_128x128_T1>>>(p);

  softmax_rows_k<<<dim3(n, B * E), 256>>>(sco, n, n4);

  // 4. y[:, e*HD:(e+1)*HD] = (P @ V) * routing[b, s, e]
  reset();
  p.A = sco; p.lda = n4; p.as1 = (long long)n * n4;
  p.Bm = qkv + 2LL * n * HD_P; p.ldb = HD_P; p.bs1 = 3LL * n * HD_P;
  p.C = y; p.ldc = D; p.cDiv = E; p.cs1 = (long long)n * D; p.cs2 = HD;
  p.M = n; p.N = HD; p.K = n;
  p.rout = rout; p.routN = n;
  tmma_k<128, 64, 32, 32, 0, 3>
      <<<dim3(1, cdiv(n, 128), B * E), 256, SMEM_128x64_T0>>>(p);

  // 5. a = y @ out_w + out_b  (32-wide M tile for segment sizes -> >=148 blks)
  reset();
  p.A = y; p.lda = D;
  p.Bm = owr; p.ldb = D;
  p.bias = w.ob + (long long)layer * D;
  p.C = a; p.ldc = D;
  p.M = M; p.N = D; p.K = D;
  if (M <= 1024)
    tmma_k<32, 128, 16, 32, 0, 0>
        <<<dim3(cdiv(D, 128), cdiv(M, 32), 1), 256, SMEM_32x128_T0>>>(p);
  else
    tmma_k<64, 128, 32, 32, 0, 0>
        <<<dim3(cdiv(D, 128), cdiv(M, 64), 1), 256, SMEM_64x128_T0>>>(p);

  // 6. x1 = LN1(t + a)
  add_ln_k<true><<<M, 256>>>(t, a, w.l1g + (long long)layer * D,
                             w.l1b + (long long)layer * D, x1);

  // 7. h = gelu(x1 @ ff_w1 + ff_b1)
  reset();
  p.A = x1; p.lda = D;
  p.Bm = w1r; p.ldb = F;
  p.bias = w.b1 + (long long)layer * F;
  p.C = h; p.ldc = F;
  p.M = M; p.N = F; p.K = D;
  tmma_k<64, 128, 32, 32, 0, 1>
      <<<dim3(cdiv(F, 128), cdiv(M, 64), 1), 256, SMEM_64x128_T0>>>(p);

  // 8. f = h @ ff_w2 + ff_b2 (into y, reuse)
  reset();
  p.A = h; p.lda = F;
  p.Bm = w2r; p.ldb = D;
  p.bias = w.b2 + (long long)layer * D;
  p.C = y; p.ldc = D;
  p.M = M; p.N = D; p.K = F;
  if (M <= 1024)
    tmma_k<32, 128, 16, 32, 0, 0>
        <<<dim3(cdiv(D, 128), cdiv(M, 32), 1), 256, SMEM_32x128_T0>>>(p);
  else
    tmma_k<64, 128, 32, 32, 0, 0>
        <<<dim3(cdiv(D, 128), cdiv(M, 64), 1), 256, SMEM_64x128_T0>>>(p);

  // 9. out = LN2(x1 + f); final layer's output must stay unrounded
  if (layer == L - 1)
    add_ln_k<false><<<M, 256>>>(x1, y, w.l2g + (long long)layer * D,
                                w.l2b + (long long)layer * D, out);
  else
    add_ln_k<true><<<M, 256>>>(x1, y, w.l2g + (long long)layer * D,
                               w.l2b + (long long)layer * D, out);
}

extern "C" void kernel_launch(void* const* d_in, const int* in_sizes, int n_in,
                              void* d_out, int out_size) {
  (void)in_sizes; (void)n_in; (void)out_size;
  float* sc = nullptr;
  cudaGetSymbolAddress((void**)&sc, g_scratch);

  // raise dynamic smem limits (host-side, not captured; idempotent)
  cudaFuncSetAttribute((const void*)tmma_k<128, 64, 32, 32, 0, 4>,
                       cudaFuncAttributeMaxDynamicSharedMemorySize,
                       SMEM_128x64_T0);
  cudaFuncSetAttribute((const void*)tmma_k<128, 64, 32, 32, 0, 3>,
                       cudaFuncAttributeMaxDynamicSharedMemorySize,
                       SMEM_128x64_T0);
  cudaFuncSetAttribute((const void*)tmma_k<128, 128, 64, 32, 1, 2>,
                       cudaFuncAttributeMaxDynamicSharedMemorySize,
                       SMEM_128x128_T1);
  cudaFuncSetAttribute((const void*)tmma_k<64, 128, 32, 32, 0, 0>,
                       cudaFuncAttributeMaxDynamicSharedMemorySize,
                       SMEM_64x128_T0);
  cudaFuncSetAttribute((const void*)tmma_k<64, 128, 32, 32, 0, 1>,
                       cudaFuncAttributeMaxDynamicSharedMemorySize,
                       SMEM_64x128_T0);
  cudaFuncSetAttribute((const void*)tmma_k<32, 128, 16, 32, 0, 0>,
                       cudaFuncAttributeMaxDynamicSharedMemorySize,
                       SMEM_32x128_T0);

  const float* x_in = (const float*)d_in[0];
  Wts w;
  w.ew = (const float*)d_in[1];  w.eb = (const float*)d_in[2];
  w.rw = (const float*)d_in[3];  w.rb = (const float*)d_in[4];
  w.ow = (const float*)d_in[5];  w.ob = (const float*)d_in[6];
  w.l1g = (const float*)d_in[7]; w.l1b = (const float*)d_in[8];
  w.w1 = (const float*)d_in[9];  w.b1 = (const float*)d_in[10];
  w.w2 = (const float*)d_in[11]; w.b2 = (const float*)d_in[12];
  w.l2g = (const float*)d_in[13]; w.l2b = (const float*)d_in[14];

  // One-launch weight prep (repack ew + round ow/w1/w2)
  {
    const long long tot = (long long)L * E * D * TH_P + (long long)L * D * D +
                          (long long)L * D * F + (long long)L * F * D;
    prep_k<<<(int)((tot + 255) / 256), 256>>>(sc, w.ew, w.ow, w.w1, w.w2);
  }

  // x = round(input)
  copy_round_k<<<cdiv((int)NX, 256), 256>>>(sc + OFF_X, x_in, NX);

  run_block(sc, sc + OFF_X, sc + OFF_X, 0, S, w);

  for (int c = 0; c < CYCLES; c++) {
    zero_k<<<cdiv((int)NX, 256), 256>>>(sc + OFF_XNEW, NX);
    for (int j = 0; j < 4; j++) {
      int nseg = SEG_N[j];
      int tot = B * nseg * D;
      gather_k<<<cdiv(tot, 256), 256>>>(sc + OFF_T, sc + OFF_X, nseg, SEG_ST[j],
                                        SEG_P1[j]);
      run_block(sc, sc + OFF_T, sc + OFF_A, 1 + 4 * c + j, nseg, w);
      scatter_add_k<<<cdiv(tot, 256), 256>>>(sc + OFF_XNEW, sc + OFF_A, nseg,
                                             SEG_ST[j], SEG_P1[j]);
    }
    div_counts_k<<<cdiv((int)NX, 256), 256>>>(sc + OFF_X, sc + OFF_XNEW);
  }

  run_block(sc, sc + OFF_X, (float*)d_out, 13, S, w);
}

// round 11
// speedup vs baseline: 1.6037x; 1.4055x over previous
#include <cuda_runtime.h>
#include <math.h>
#include <stdint.h>

// ---------------------------------------------------------------------------
// SLAMv2: 14-layer MoE-attention transformer, segmented schedule.
// Round 11: R7/R10 base + MEGA-BATCHED segments: all 4 independent segments
// of a cycle run as single z-extended launches (z=160 attention, z=4 linear),
// per-seg layer weights via seg = z/zSeg, per-seg M/N/K from constant table,
// padded rows zero-filled (inert). scatter+div -> one fixed-order combine.
// Numerics bit-identical to R7 (rel_err must remain 7.0038e-4).
// ---------------------------------------------------------------------------

namespace {
constexpr int B = 2, S = 1024, D = 1000, E = 20, HD = 50, TH = 3 * HD;
constexpr int HD_P = 52;
constexpr int TH_P = 160;
constexpr int F = 2048, CYCLES = 3, L = 14;
constexpr int NP = 460;       // padded segment length
constexpr int ZS = B * E;     // 40 z per segment

constexpr long long NX = (long long)B * S * D;
constexpr long long OFF_X    = 0;
constexpr long long OFF_XNEW = OFF_X + NX;
constexpr long long OFF_T    = OFF_XNEW + NX;
constexpr long long OFF_X1   = OFF_T + NX;
constexpr long long OFF_Y    = OFF_X1 + NX;
constexpr long long OFF_A    = OFF_Y + NX;
constexpr long long OFF_ROUT = OFF_A + NX;
constexpr long long OFF_H    = OFF_ROUT + (long long)B * S * E;
constexpr long long OFF_QKV  = OFF_H + (long long)B * S * F;
constexpr long long OFF_SC   = OFF_QKV + (long long)B * E * 3 * S * HD_P;
constexpr long long OFF_EWP  = OFF_SC + (long long)B * E * S * S;
constexpr long long OFF_OWR  = OFF_EWP + (long long)L * E * D * TH_P;
constexpr long long OFF_W1R  = OFF_OWR + (long long)L * D * D;
constexpr long long OFF_W2R  = OFF_W1R + (long long)L * D * F;
// segment-batched buffers
constexpr long long N_ROWS4  = 4LL * B * NP;            // 3680 rows
constexpr long long OFF_T4   = OFF_W2R + (long long)L * F * D;
constexpr long long OFF_R4   = OFF_T4 + N_ROWS4 * D;
constexpr long long OFF_QKV4 = OFF_R4 + N_ROWS4 * E;    // 160*3*NP*HD_P
constexpr long long OFF_Y4   = OFF_QKV4 + 160LL * 3 * NP * HD_P;
constexpr long long OFF_A4   = OFF_Y4 + N_ROWS4 * D;
constexpr long long OFF_X14  = OFF_A4 + N_ROWS4 * D;
constexpr long long OFF_H4   = OFF_X14 + N_ROWS4 * D;
constexpr long long OFF_O4   = OFF_H4 + N_ROWS4 * F;
constexpr long long TOTAL    = OFF_O4 + N_ROWS4 * D;
// sco4 (160 * NP * NP = 33.86M) reuses OFF_SC region (41.9M) — checked.

constexpr int SEG_ST[4] = {0, 256, 460, 665};
constexpr int SEG_N[4]  = {460, 409, 410, 410};
constexpr int SEG_P1[4] = {460, 409, 410, 359};
}  // namespace

__device__ float g_scratch[TOTAL];
__device__ const int c_segN[4]  = {460, 409, 410, 410};
__device__ const int c_segST[4] = {0, 256, 460, 665};
__device__ const int c_segP1[4] = {460, 409, 410, 359};

struct GemmP {
  const float* A; const float* Bm; const float* bias; float* C;
  int M, N, K, lda, ldb, ldc;
  int aDiv; long long as1, as2;
  int bDiv; long long bs1, bs2;
  int cDiv; long long cs1, cs2;
  int biasDiv; long long biasS;
  long long splitStride;
  float scale;
  const float* rout; int routN;
  int zSeg;            // z's per segment (0 = no segment batching)
  long long bSeg;      // extra B offset per segment (layer stride)
  long long biasSeg;   // extra bias offset per segment
  int segFlags;        // 1: M=segN, 2: N=segN, 4: K=segN
};

__device__ __forceinline__ float to_tf32(float x) {
  asm("cvt.rna.tf32.f32 %0, %0;" : "+f"(x));
  return x;
}

__device__ __forceinline__ void cp16(uint32_t dst, const float* src, int bytes) {
  asm volatile("cp.async.cg.shared.global [%0], [%1], 16, %2;\n"
               :: "r"(dst), "l"(src), "r"(bytes));
}
__device__ __forceinline__ void cp_commit() {
  asm volatile("cp.async.commit_group;\n");
}
template <int N>
__device__ __forceinline__ void cp_wait() {
  asm volatile("cp.async.wait_group %0;\n" :: "n"(N));
}

// ---------------------------------------------------------------------------
// TF32 tensor-core GEMM; cp.async 4-stage ring; k-slot remap fragments.
// ---------------------------------------------------------------------------
template <int BM, int BN, int WM, int WN, int BTRANS, int EPI>
__global__ __launch_bounds__(256) void tmma_k(GemmP p) {
  constexpr int BK = 16, ST = 4;
  constexpr int SKA = BK + 4;
  constexpr int LDB0 = BN + 4;
  constexpr int ASZ = BM * SKA;
  constexpr int BSZ = BTRANS ? BN * SKA : BK * LDB0;
  constexpr int NWN = BN / WN;
  constexpr int MT = WM / 16, NT = WN / 8;
  constexpr int ACH = BM * 4;
  constexpr int AV_ = (ACH + 255) / 256;
  constexpr int BV_ = BN / 64;
  static_assert((BM / WM) * (BN / WN) == 8, "need 8 warps");

  extern __shared__ float sm[];
  float* As = sm;
  float* Bs = sm + ST * ASZ;
  const uint32_t a_u32 = (uint32_t)__cvta_generic_to_shared(As);
  const uint32_t b_u32 = (uint32_t)__cvta_generic_to_shared(Bs);

  const int z = blockIdx.z;
  int seg = 0;
  if (p.zSeg) seg = z / p.zSeg;
  const int Mloc = (p.segFlags & 1) ? c_segN[seg] : p.M;
  const int Nloc = (p.segFlags & 2) ? c_segN[seg] : p.N;
  const int Kloc = (p.segFlags & 4) ? c_segN[seg] : p.K;

  const float* Ab =
      p.A + (long long)(z / p.aDiv) * p.as1 + (long long)(z % p.aDiv) * p.as2;
  const float* Bb =
      p.Bm + (long long)(z / p.bDiv) * p.bs1 + (long long)(z % p.bDiv) * p.bs2 +
      (long long)seg * p.bSeg;
  float* Cb =
      p.C + (long long)(z / p.cDiv) * p.cs1 + (long long)(z % p.cDiv) * p.cs2;

  const int m0 = blockIdx.y * BM, n0 = blockIdx.x * BN;
  const int tid = threadIdx.x;
  const int warp = tid >> 5, lane = tid & 31;
  const int g = lane >> 2, t = lane & 3;
  const int wm = (warp / NWN) * WM, wn = (warp % NWN) * WN;

  auto issue = [&](int it) {
    const int s = it % ST;
    const int kb = it * BK;
#pragma unroll
    for (int v = 0; v < AV_; v++) {
      int idx = tid + v * 256;
      if ((ACH % 256) != 0 && idx >= ACH) break;
      int m = idx >> 2, c4 = (idx & 3) * 4;
      int gm = m0 + m, gk = kb + c4;
      int by = 0;
      if (gm < Mloc) {
        int rem = (Kloc - gk) * 4;
        by = rem > 16 ? 16 : (rem > 0 ? rem : 0);
      }
      const float* src = Ab + (long long)(by ? gm : 0) * p.lda + (by ? gk : 0);
      cp16(a_u32 + (uint32_t)(s * ASZ + m * SKA + c4) * 4u, src, by);
    }
    if (BTRANS == 0) {
#pragma unroll
      for (int v = 0; v < BV_; v++) {
        int idx = tid + v * 256;
        int kk = idx / (BN / 4), n4 = (idx % (BN / 4)) * 4;
        int gk = kb + kk, gn = n0 + n4;
        int by = 0;
        if (gk < Kloc) {
          int rem = (Nloc - gn) * 4;
          by = rem > 16 ? 16 : (rem > 0 ? rem : 0);
        }
        const float* src = Bb + (long long)(by ? gk : 0) * p.ldb + (by ? gn : 0);
        cp16(b_u32 + (uint32_t)(s * BSZ + kk * LDB0 + n4) * 4u, src, by);
      }
    } else {
#pragma unroll
      for (int v = 0; v < BV_; v++) {
        int idx = tid + v * 256;
        int n = idx >> 2, c4 = (idx & 3) * 4;
        int gn = n0 + n, gk = kb + c4;
        int by = 0;
        if (gn < Nloc) {
          int rem = (Kloc - gk) * 4;
          by = rem > 16 ? 16 : (rem > 0 ? rem : 0);
        }
        const float* src = Bb + (long long)(by ? gn : 0) * p.ldb + (by ? gk : 0);
        cp16(b_u32 + (uint32_t)(s * BSZ + n * SKA + c4) * 4u, src, by);
      }
    }
  };

  float c[MT][NT][4];
#pragma unroll
  for (int i = 0; i < MT; i++)
#pragma unroll
    for (int j = 0; j < NT; j++)
#pragma unroll
      for (int r = 0; r < 4; r++) c[i][j][r] = 0.f;

  auto comp = [&](int s) {
    const float* Asb = As + s * ASZ;
    const float* Bsb = Bs + s * BSZ;
#pragma unroll
    for (int kq = 0; kq < 2; kq++) {
      const int ko = kq * 8 + 2 * t;
      float2 af[MT][2];
#pragma unroll
      for (int mt = 0; mt < MT; mt++) {
        int r0 = wm + mt * 16 + g;
        af[mt][0] = *reinterpret_cast<const float2*>(&Asb[r0 * SKA + ko]);
        af[mt][1] = *reinterpret_cast<const float2*>(&Asb[(r0 + 8) * SKA + ko]);
      }
      float bx[NT], by_[NT];
#pragma unroll
      for (int nt = 0; nt < NT; nt++) {
        int col = wn + nt * 8 + g;
        if (BTRANS == 1) {
          float2 bb = *reinterpret_cast<const float2*>(&Bsb[col * SKA + ko]);
          bx[nt] = bb.x;
          by_[nt] = bb.y;
        } else {
          bx[nt] = Bsb[ko * LDB0 + col];
          by_[nt] = Bsb[(ko + 1) * LDB0 + col];
        }
      }
#pragma unroll
      for (int mt = 0; mt < MT; mt++)
#pragma unroll
        for (int nt = 0; nt < NT; nt++) {
          asm volatile(
              "mma.sync.aligned.m16n8k8.row.col.f32.tf32.tf32.f32 "
              "{%0,%1,%2,%3}, {%4,%5,%6,%7}, {%8,%9}, {%0,%1,%2,%3};"
              : "+f"(c[mt][nt][0]), "+f"(c[mt][nt][1]), "+f"(c[mt][nt][2]),
                "+f"(c[mt][nt][3])
              : "r"(__float_as_uint(af[mt][0].x)),
                "r"(__float_as_uint(af[mt][1].x)),
                "r"(__float_as_uint(af[mt][0].y)),
                "r"(__float_as_uint(af[mt][1].y)),
                "r"(__float_as_uint(bx[nt])), "r"(__float_as_uint(by_[nt])));
        }
    }
  };

  const int iters = (Kloc + BK - 1) / BK;
#pragma unroll
  for (int s = 0; s < ST - 1; s++) {
    if (s < iters) issue(s);
    cp_commit();
  }
  for (int it = 0; it < iters; it++) {
    cp_wait<ST - 2>();
    __syncthreads();
    if (it + ST - 1 < iters) issue(it + ST - 1);
    cp_commit();
    comp(it % ST);
  }

  const float* biasb = nullptr;
  if ((EPI == 0 || EPI == 1 || EPI == 4) && p.bias)
    biasb = p.bias + (long long)(z % p.biasDiv) * p.biasS +
            (long long)seg * p.biasSeg;

#pragma unroll
  for (int mt = 0; mt < MT; mt++)
#pragma unroll
    for (int nt = 0; nt < NT; nt++)
#pragma unroll
      for (int r = 0; r < 4; r++) {
        int row = m0 + wm + mt * 16 + g + ((r >> 1) ? 8 : 0);
        int col = n0 + wn + nt * 8 + 2 * t + (r & 1);
        if (row >= Mloc || col >= Nloc) continue;
        float v = c[mt][nt][r];
        if (biasb) v += biasb[col];
        if (EPI == 1) {
          v = 0.5f * v * (1.f + erff(v * 0.70710678118654752f));
          v = to_tf32(v);
        }
        if (EPI == 2) v *= p.scale;
        if (EPI == 3) {
          v *= p.rout[((long long)(z / p.cDiv) * p.routN + row) * E +
                      (z % p.cDiv)];
          v = to_tf32(v);
        }
        if (EPI == 4) {
          v = to_tf32(v);
          int h = col / HD, s2 = col - h * HD;
          Cb[(long long)h * p.splitStride + (long long)row * p.ldc + s2] = v;
        } else {
          Cb[(long long)row * p.ldc + col] = v;
        }
      }
}

// ---------------------------------------------------------------------------
// SIMT SGEMM (routing GEMM, N=20; fp32). z-batched via as1/bs1/cs1/biasS.
// ---------------------------------------------------------------------------
template <int BM, int BN, int BK, int TM, int TN>
__global__ __launch_bounds__((BM / TM) * (BN / TN)) void sgemm2_k(GemmP p) {
  constexpr int NTHR = (BM / TM) * (BN / TN);
  constexpr int TX = BN / TN;
  __shared__ float As[BK][BM + 4];
  __shared__ float Bs[BK][BN + 4];

  const int z = blockIdx.z;
  const float* Ab = p.A + (long long)z * p.as1;
  const float* Bb = p.Bm + (long long)z * p.bs1;
  float* Cb = p.C + (long long)z * p.cs1;
  const float* bias = p.bias ? p.bias + (long long)z * p.biasS : nullptr;

  const int m0 = blockIdx.y * BM, n0 = blockIdx.x * BN;
  const int tid = threadIdx.x;
  const int tx = tid % TX, ty = tid / TX;

  float acc[TM][TN];
#pragma unroll
  for (int i = 0; i < TM; i++)
#pragma unroll
    for (int j = 0; j < TN; j++) acc[i][j] = 0.f;

  for (int k0 = 0; k0 < p.K; k0 += BK) {
    for (int idx = tid; idx < BM * BK; idx += NTHR) {
      int m = idx / BK, kk = idx % BK;
      int gm = m0 + m, gk = k0 + kk;
      As[kk][m] = (gm < p.M && gk < p.K) ? Ab[(long long)gm * p.lda + gk] : 0.f;
    }
    for (int idx = tid; idx < BK * BN; idx += NTHR) {
      int kk = idx / BN, nn = idx % BN;
      int gk = k0 + kk, gn = n0 + nn;
      Bs[kk][nn] = (gk < p.K && gn < p.N) ? Bb[(long long)gk * p.ldb + gn] : 0.f;
    }
    __syncthreads();
#pragma unroll
    for (int kk = 0; kk < BK; kk++) {
      float a[TM], b[TN];
#pragma unroll
      for (int i = 0; i < TM; i++) a[i] = As[kk][ty * TM + i];
#pragma unroll
      for (int j = 0; j < TN; j++) b[j] = Bs[kk][tx * TN + j];
#pragma unroll
      for (int i = 0; i < TM; i++)
#pragma unroll
        for (int j = 0; j < TN; j++) acc[i][j] += a[i] * b[j];
    }
    __syncthreads();
  }

#pragma unroll
  for (int i = 0; i < TM; i++) {
    int row = m0 + ty * TM + i;
    if (row >= p.M) continue;
#pragma unroll
    for (int j = 0; j < TN; j++) {
      int col = n0 + tx * TN + j;
      if (col >= p.N) continue;
      float v = acc[i][j] + (bias ? bias[col] : 0.f);
      Cb[(long long)row * p.ldc + col] = v;
    }
  }
}

// ---------------------------------------------------------------------------
// One-launch weight prep (identical numerics to R7 prep kernels)
// ---------------------------------------------------------------------------
__global__ void prep_k(float* sc, const float* ew, const float* ow,
                       const float* w1, const float* w2) {
  const long long n_ewp = (long long)L * E * D * TH_P;
  const long long n_ow = (long long)L * D * D;
  const long long n_w1 = (long long)L * D * F;
  const long long n_w2 = (long long)L * F * D;
  long long i = (long long)blockIdx.x * blockDim.x + threadIdx.x;
  if (i < n_ewp) {
    int col = (int)(i % TH_P);
    long long base = i / TH_P;
    sc[OFF_EWP + i] = (col < TH) ? to_tf32(ew[base * TH + col]) : 0.f;
    return;
  }
  i -= n_ewp;
  if (i < n_ow) { sc[OFF_OWR + i] = to_tf32(ow[i]); return; }
  i -= n_ow;
  if (i < n_w1) { sc[OFF_W1R + i] = to_tf32(w1[i]); return; }
  i -= n_w1;
  if (i < n_w2) { sc[OFF_W2R + i] = to_tf32(w2[i]); }
}

// ---------------------------------------------------------------------------
// Small kernels
// ---------------------------------------------------------------------------
__global__ void copy_round_k(float* dst, const float* src, long long n) {
  long long i = (long long)blockIdx.x * blockDim.x + threadIdx.x;
  if (i < n) dst[i] = to_tf32(src[i]);
}

// gather all 4 segments into t4 [(seg*B+b)*NP + i][D]
__global__ void gather4_k(float* t4, const float* x) {
  long long idx = (long long)blockIdx.x * blockDim.x + threadIdx.x;
  long long tot = N_ROWS4 * D;
  if (idx >= tot) return;
  int d = (int)(idx % D);
  long long r = idx / D;
  int i = (int)(r % NP);
  int b = (int)((r / NP) % B);
  int j = (int)(r / ((long long)NP * B));
  if (i >= c_segN[j]) return;
  int si = (i < c_segP1[j]) ? c_segST[j] + i : i - c_segP1[j];
  t4[idx] = x[((long long)b * S + si) * D + d];
}

__device__ __forceinline__ float seg_cnt(int i) {
  float c = 0.f;
  c += (i < 460);
  c += (i >= 256 && i < 665);
  c += (i >= 460 && i < 870);
  c += (i >= 665);
  c += (i < 51);
  return c;
}

// x[b,i,d] = to_tf32( (sum_j o4 contributions in j order) / count(i) )
__global__ void combine_k(float* x, const float* o4) {
  long long idx = (long long)blockIdx.x * blockDim.x + threadIdx.x;
  if (idx >= NX) return;
  int d = (int)(idx % D);
  long long r = idx / D;
  int i = (int)(r % S);
  int b = (int)(r / S);
  float s = 0.f;
  if (i < 460) s += o4[(((0 * B + b) * (long long)NP + i) * D) + d];
  if (i >= 256 && i < 665)
    s += o4[(((1 * B + b) * (long long)NP + (i - 256)) * D) + d];
  if (i >= 460 && i < 870)
    s += o4[(((2 * B + b) * (long long)NP + (i - 460)) * D) + d];
  if (i >= 665) s += o4[(((3 * B + b) * (long long)NP + (i - 665)) * D) + d];
  if (i < 51) s += o4[(((3 * B + b) * (long long)NP + (359 + i)) * D) + d];
  x[idx] = to_tf32(s / seg_cnt(i));
}

__global__ void zero_k(float* dst, long long n) {
  long long i = (long long)blockIdx.x * blockDim.x + threadIdx.x;
  if (i < n) dst[i] = 0.f;
}

__global__ void gather_k(float* dst, const float* src, int nseg, int st, int p1) {
  long long i = (long long)blockIdx.x * blockDim.x + threadIdx.x;
  long long tot = (long long)B * nseg * D;
  if (i >= tot) return;
  int d = (int)(i % D);
  long long r = i / D;
  int ii = (int)(r % nseg);
  int b_ = (int)(r / nseg);
  int si = (ii < p1) ? (st + ii) : (ii - p1);
  dst[i] = src[((long long)b_ * S + si) * D + d];
}

__global__ void softmaxE_k(float* r, int rows) {
  int i = blockIdx.x * blockDim.x + threadIdx.x;
  if (i >= rows) return;
  float* p = r + (long long)i * E;
  float m = -1e30f;
  for (int e = 0; e < E; e++) m = fmaxf(m, p[e]);
  float s = 0.f;
  for (int e = 0; e < E; e++) {
    float v = __expf(p[e] - m);
    p[e] = v;
    s += v;
  }
  float inv = 1.f / s;
  for (int e = 0; e < E; e++) p[e] *= inv;
}

// row softmax, full-block version (n rows per z, stride ld)
__device__ __forceinline__ void softmax_row_body(float* row, int n) {
  __shared__ float red[32];
  __shared__ float bcast;
  int tid = threadIdx.x;
  int nw = blockDim.x >> 5;

  float m = -1e30f;
  for (int j = tid; j < n; j += blockDim.x) m = fmaxf(m, row[j]);
  for (int o = 16; o; o >>= 1) m = fmaxf(m, __shfl_xor_sync(0xffffffffu, m, o));
  if ((tid & 31) == 0) red[tid >> 5] = m;
  __syncthreads();
  if (tid < 32) {
    float v = (tid < nw) ? red[tid] : -1e30f;
    for (int o = 16; o; o >>= 1) v = fmaxf(v, __shfl_xor_sync(0xffffffffu, v, o));
    if (tid == 0) bcast = v;
  }
  __syncthreads();
  m = bcast;

  float sum = 0.f;
  for (int j = tid; j < n; j += blockDim.x) {
    float e = __expf(row[j] - m);
    row[j] = e;
    sum += e;
  }
  for (int o = 16; o; o >>= 1) sum += __shfl_xor_sync(0xffffffffu, sum, o);
  if ((tid & 31) == 0) red[tid >> 5] = sum;
  __syncthreads();
  if (tid < 32) {
    float v = (tid < nw) ? red[tid] : 0.f;
    for (int o = 16; o; o >>= 1) v += __shfl_xor_sync(0xffffffffu, v, o);
    if (tid == 0) bcast = v;
  }
  __syncthreads();
  float inv = 1.f / bcast;
  for (int j = tid; j < n; j += blockDim.x) row[j] = to_tf32(row[j] * inv);
}

__global__ void softmax_rows_k(float* s, int n, int ld) {
  float* row = s + (long long)blockIdx.y * n * ld + (long long)blockIdx.x * ld;
  softmax_row_body(row, n);
}

// segment-batched row softmax: grid (NP, 160); per-z seg length from table
__global__ void softmax_rows4_k(float* s) {
  int z = blockIdx.y;
  int seg = z / ZS;
  int n = c_segN[seg];
  int row = blockIdx.x;
  if (row >= n) return;
  float* rp = s + (long long)z * NP * NP + (long long)row * NP;
  softmax_row_body(rp, n);
}

// out = layernorm(x + r) * g + b; CVT rounds output to tf32.
// SEGROWS > 0: per-seg g/b selection (seg = row / SEGROWS, stride D).
template <bool CVT, int SEGROWS>
__global__ void add_ln_k(const float* x, const float* r, const float* g,
                         const float* b, float* out) {
  long long base = (long long)blockIdx.x * D;
  if (SEGROWS > 0) {
    int seg = blockIdx.x / SEGROWS;
    g += (long long)seg * D;
    b += (long long)seg * D;
  }
  __shared__ float buf[D];
  __shared__ float redA[32], redB[32];
  __shared__ float sh_m, sh_inv;
  int tid = threadIdx.x;
  int nw = blockDim.x >> 5;

  float s = 0.f, s2 = 0.f;
  for (int d = tid; d < D; d += blockDim.x) {
    float v = x[base + d] + r[base + d];
    buf[d] = v;
    s += v;
    s2 += v * v;
  }
  for (int o = 16; o; o >>= 1) {
    s += __shfl_xor_sync(0xffffffffu, s, o);
    s2 += __shfl_xor_sync(0xffffffffu, s2, o);
  }
  if ((tid & 31) == 0) { redA[tid >> 5] = s; redB[tid >> 5] = s2; }
  __syncthreads();
  if (tid < 32) {
    float a2 = (tid < nw) ? redA[tid] : 0.f;
    float b2 = (tid < nw) ? redB[tid] : 0.f;
    for (int o = 16; o; o >>= 1) {
      a2 += __shfl_xor_sync(0xffffffffu, a2, o);
      b2 += __shfl_xor_sync(0xffffffffu, b2, o);
    }
    if (tid == 0) {
      float mean = a2 / D;
      float var = b2 / D - mean * mean;
      sh_m = mean;
      sh_inv = rsqrtf(var + 1e-5f);
    }
  }
  __syncthreads();
  float mean = sh_m, inv = sh_inv;
  for (int d = tid; d < D; d += blockDim.x) {
    float v = (buf[d] - mean) * inv * g[d] + b[d];
    out[base + d] = CVT ? to_tf32(v) : v;
  }
}

// ---------------------------------------------------------------------------
// Host-side driver
// ---------------------------------------------------------------------------
static inline int cdiv(int a, int b) { return (a + b - 1) / b; }

struct Wts {
  const float *ew, *eb, *rw, *rb, *ow, *ob, *l1g, *l1b, *w1, *b1, *w2, *b2,
      *l2g, *l2b;
};

constexpr int SMEM_128x64_T0 = 4 * (128 * 20 + 16 * 68) * 4;
constexpr int SMEM_128x128_T1 = 4 * (128 * 20 + 128 * 20) * 4;
constexpr int SMEM_64x128_T0 = 4 * (64 * 20 + 16 * 132) * 4;
constexpr int SMEM_32x128_T0 = 4 * (32 * 20 + 16 * 132) * 4;

// -------------------- full-sequence block (layers 0 and 13) ----------------
static void run_block(float* sc, const float* t, float* out, int layer, int n,
                      const Wts& w) {
  const int M = B * n;
  const int n4 = (n + 3) & ~3;
  float* rout = sc + OFF_ROUT;
  float* qkv = sc + OFF_QKV;
  float* sco = sc + OFF_SC;
  float* y = sc + OFF_Y;
  float* a = sc + OFF_A;
  float* x1 = sc + OFF_X1;
  float* h = sc + OFF_H;
  const float* ewp = sc + OFF_EWP + (long long)layer * E * D * TH_P;
  const float* owr = sc + OFF_OWR + (long long)layer * D * D;
  const float* w1r = sc + OFF_W1R + (long long)layer * D * F;
  const float* w2r = sc + OFF_W2R + (long long)layer * F * D;

  GemmP p;
  auto reset = [&]() {
    p = GemmP{};
    p.aDiv = p.bDiv = p.cDiv = p.biasDiv = 1;
    p.scale = 1.f;
  };

  reset();
  p.A = t; p.Bm = w.rw + (long long)layer * D * E;
  p.bias = w.rb + (long long)layer * E; p.C = rout;
  p.M = M; p.N = E; p.K = D; p.lda = D; p.ldb = E; p.ldc = E;
  sgemm2_k<64, 64, 16, 4, 4><<<dim3(1, cdiv(M, 64), 1), 256>>>(p);
  softmaxE_k<<<cdiv(M, 256), 256>>>(rout, M);

  reset();
  p.A = t; p.lda = D; p.aDiv = E; p.as1 = (long long)n * D;
  p.Bm = ewp; p.ldb = TH_P;
  p.bDiv = E; p.bs2 = (long long)D * TH_P;
  p.bias = w.eb + (long long)layer * E * TH; p.biasDiv = E; p.biasS = TH;
  p.C = qkv; p.ldc = HD_P; p.cs1 = 3LL * n * HD_P;
  p.splitStride = (long long)n * HD_P;
  p.M = n; p.N = TH; p.K = D;
  tmma_k<128, 64, 32, 32, 0, 4>
      <<<dim3(3, cdiv(n, 128), B * E), 256, SMEM_128x64_T0>>>(p);

  reset();
  p.A = qkv; p.lda = HD_P; p.as1 = 3LL * n * HD_P;
  p.Bm = qkv + (long long)n * HD_P; p.ldb = HD_P; p.bs1 = 3LL * n * HD_P;
  p.C = sco; p.ldc = n4; p.cs1 = (long long)n * n4;
  p.M = n; p.N = n; p.K = HD;
  p.scale = 0.14142135623730950488f;
  tmma_k<128, 128, 64, 32, 1, 2>
      <<<dim3(cdiv(n, 128), cdiv(n, 128), B * E), 256, SMEM_128x128_T1>>>(p);

  softmax_rows_k<<<dim3(n, B * E), 256>>>(sco, n, n4);

  reset();
  p.A = sco; p.lda = n4; p.as1 = (long long)n * n4;
  p.Bm = qkv + 2LL * n * HD_P; p.ldb = HD_P; p.bs1 = 3LL * n * HD_P;
  p.C = y; p.ldc = D; p.cDiv = E; p.cs1 = (long long)n * D; p.cs2 = HD;
  p.M = n; p.N = HD; p.K = n;
  p.rout = rout; p.routN = n;
  tmma_k<128, 64, 32, 32, 0, 3>
      <<<dim3(1, cdiv(n, 128), B * E), 256, SMEM_128x64_T0>>>(p);

  reset();
  p.A = y; p.lda = D;
  p.Bm = owr; p.ldb = D;
  p.bias = w.ob + (long long)layer * D;
  p.C = a; p.ldc = D;
  p.M = M; p.N = D; p.K = D;
  tmma_k<64, 128, 32, 32, 0, 0>
      <<<dim3(cdiv(D, 128), cdiv(M, 64), 1), 256, SMEM_64x128_T0>>>(p);

  add_ln_k<true, 0><<<M, 256>>>(t, a, w.l1g + (long long)layer * D,
                                w.l1b + (long long)layer * D, x1);

  reset();
  p.A = x1; p.lda = D;
  p.Bm = w1r; p.ldb = F;
  p.bias = w.b1 + (long long)layer * F;
  p.C = h; p.ldc = F;
  p.M = M; p.N = F; p.K = D;
  tmma_k<64, 128, 32, 32, 0, 1>
      <<<dim3(cdiv(F, 128), cdiv(M, 64), 1), 256, SMEM_64x128_T0>>>(p);

  reset();
  p.A = h; p.lda = F;
  p.Bm = w2r; p.ldb = D;
  p.bias = w.b2 + (long long)layer * D;
  p.C = y; p.ldc = D;
  p.M = M; p.N = D; p.K = F;
  tmma_k<64, 128, 32, 32, 0, 0>
      <<<dim3(cdiv(D, 128), cdiv(M, 64), 1), 256, SMEM_64x128_T0>>>(p);

  if (layer == L - 1)
    add_ln_k<false, 0><<<M, 256>>>(x1, y, w.l2g + (long long)layer * D,
                                   w.l2b + (long long)layer * D, out);
  else
    add_ln_k<true, 0><<<M, 256>>>(x1, y, w.l2g + (long long)layer * D,
                                  w.l2b + (long long)layer * D, out);
}

// -------------------- mega-batched 4-segment cycle --------------------------
static void run_segs(float* sc, int cyc, const Wts& w) {
  const int layerBase = 1 + 4 * cyc;
  const int MROWS = B * NP;          // 920 rows per segment
  const int NR4 = 4 * MROWS;         // 3680 rows total
  float* t4 = sc + OFF_T4;
  float* r4 = sc + OFF_R4;
  float* qkv4 = sc + OFF_QKV4;
  float* sco4 = sc + OFF_SC;
  float* y4 = sc + OFF_Y4;
  float* a4 = sc + OFF_A4;
  float* x14 = sc + OFF_X14;
  float* h4 = sc + OFF_H4;
  float* o4 = sc + OFF_O4;

  gather4_k<<<(int)((N_ROWS4 * D + 255) / 256), 256>>>(t4, sc + OFF_X);

  GemmP p;
  auto reset = [&]() {
    p = GemmP{};
    p.aDiv = p.bDiv = p.cDiv = p.biasDiv = 1;
    p.scale = 1.f;
  };

  // routing (z = 4 segments)
  reset();
  p.A = t4; p.lda = D; p.as1 = (long long)MROWS * D;
  p.Bm = w.rw + (long long)layerBase * D * E; p.ldb = E; p.bs1 = (long long)D * E;
  p.bias = w.rb + (long long)layerBase * E; p.biasS = E;
  p.C = r4; p.ldc = E; p.cs1 = (long long)MROWS * E;
  p.M = MROWS; p.N = E; p.K = D;
  sgemm2_k<64, 64, 16, 4, 4><<<dim3(1, cdiv(MROWS, 64), 4), 256>>>(p);
  softmaxE_k<<<cdiv(NR4, 256), 256>>>(r4, NR4);

  // qkv (z = 160)
  reset();
  p.A = t4; p.lda = D; p.aDiv = E; p.as1 = (long long)NP * D;
  p.Bm = sc + OFF_EWP + (long long)layerBase * E * D * TH_P; p.ldb = TH_P;
  p.bDiv = E; p.bs2 = (long long)D * TH_P;
  p.bias = w.eb + (long long)layerBase * E * TH; p.biasDiv = E; p.biasS = TH;
  p.C = qkv4; p.ldc = HD_P; p.cs1 = 3LL * NP * HD_P;
  p.splitStride = (long long)NP * HD_P;
  p.N = TH; p.K = D;
  p.zSeg = ZS; p.bSeg = (long long)E * D * TH_P; p.biasSeg = (long long)E * TH;
  p.segFlags = 1;
  tmma_k<128, 64, 32, 32, 0, 4>
      <<<dim3(3, cdiv(NP, 128), 4 * ZS), 256, SMEM_128x64_T0>>>(p);

  // scores (z = 160)
  reset();
  p.A = qkv4; p.lda = HD_P; p.as1 = 3LL * NP * HD_P;
  p.Bm = qkv4 + (long long)NP * HD_P; p.ldb = HD_P; p.bs1 = 3LL * NP * HD_P;
  p.C = sco4; p.ldc = NP; p.cs1 = (long long)NP * NP;
  p.K = HD;
  p.scale = 0.14142135623730950488f;
  p.zSeg = ZS; p.segFlags = 1 | 2;
  tmma_k<128, 128, 64, 32, 1, 2>
      <<<dim3(cdiv(NP, 128), cdiv(NP, 128), 4 * ZS), 256, SMEM_128x128_T1>>>(p);

  softmax_rows4_k<<<dim3(NP, 4 * ZS), 256>>>(sco4);

  // AV (z = 160)
  reset();
  p.A = sco4; p.lda = NP; p.as1 = (long long)NP * NP;
  p.Bm = qkv4 + 2LL * NP * HD_P; p.ldb = HD_P; p.bs1 = 3LL * NP * HD_P;
  p.C = y4; p.ldc = D; p.cDiv = E; p.cs1 = (long long)NP * D; p.cs2 = HD;
  p.N = HD;
  p.rout = r4; p.routN = NP;
  p.zSeg = ZS; p.segFlags = 1 | 4;
  tmma_k<128, 64, 32, 32, 0, 3>
      <<<dim3(1, cdiv(NP, 128), 4 * ZS), 256, SMEM_128x64_T0>>>(p);

  // out projection (z = 4)
  reset();
  p.A = y4; p.lda = D; p.as1 = (long long)MROWS * D;
  p.Bm = sc + OFF_OWR + (long long)layerBase * D * D; p.ldb = D;
  p.bias = w.ob + (long long)layerBase * D;
  p.C = a4; p.ldc = D; p.cs1 = (long long)MROWS * D;
  p.M = MROWS; p.N = D; p.K = D;
  p.zSeg = 1; p.bSeg = (long long)D * D; p.biasSeg = D;
  tmma_k<32, 128, 16, 32, 0, 0>
      <<<dim3(cdiv(D, 128), cdiv(MROWS, 32), 4), 256, SMEM_32x128_T0>>>(p);

  add_ln_k<true, B * NP><<<NR4, 256>>>(
      t4, a4, w.l1g + (long long)layerBase * D, w.l1b + (long long)layerBase * D,
      x14);

  // FF1 (z = 4)
  reset();
  p.A = x14; p.lda = D; p.as1 = (long long)MROWS * D;
  p.Bm = sc + OFF_W1R + (long long)layerBase * D * F; p.ldb = F;
  p.bias = w.b1 + (long long)layerBase * F;
  p.C = h4; p.ldc = F; p.cs1 = (long long)MROWS * F;
  p.M = MROWS; p.N = F; p.K = D;
  p.zSeg = 1; p.bSeg = (long long)D * F; p.biasSeg = F;
  tmma_k<64, 128, 32, 32, 0, 1>
      <<<dim3(cdiv(F, 128), cdiv(MROWS, 64), 4), 256, SMEM_64x128_T0>>>(p);

  // FF2 (z = 4) -> y4 (free after out projection)
  reset();
  p.A = h4; p.lda = F; p.as1 = (long long)MROWS * F;
  p.Bm = sc + OFF_W2R + (long long)layerBase * F * D; p.ldb = D;
  p.bias = w.b2 + (long long)layerBase * D;
  p.C = y4; p.ldc = D; p.cs1 = (long long)MROWS * D;
  p.M = MROWS; p.N = D; p.K = F;
  p.zSeg = 1; p.bSeg = (long long)F * D; p.biasSeg = D;
  tmma_k<32, 128, 16, 32, 0, 0>
      <<<dim3(cdiv(D, 128), cdiv(MROWS, 32), 4), 256, SMEM_32x128_T0>>>(p);

  add_ln_k<true, B * NP><<<NR4, 256>>>(
      x14, y4, w.l2g + (long long)layerBase * D,
      w.l2b + (long long)layerBase * D, o4);

  combine_k<<<cdiv((int)NX, 256), 256>>>(sc + OFF_X, o4);
}

extern "C" void kernel_launch(void* const* d_in, const int* in_sizes, int n_in,
                              void* d_out, int out_size) {
  (void)in_sizes; (void)n_in; (void)out_size;
  float* sc = nullptr;
  cudaGetSymbolAddress((void**)&sc, g_scratch);

  cudaFuncSetAttribute((const void*)tmma_k<128, 64, 32, 32, 0, 4>,
                       cudaFuncAttributeMaxDynamicSharedMemorySize,
                       SMEM_128x64_T0);
  cudaFuncSetAttribute((const void*)tmma_k<128, 64, 32, 32, 0, 3>,
                       cudaFuncAttributeMaxDynamicSharedMemorySize,
                       SMEM_128x64_T0);
  cudaFuncSetAttribute((const void*)tmma_k<128, 128, 64, 32, 1, 2>,
                       cudaFuncAttributeMaxDynamicSharedMemorySize,
                       SMEM_128x128_T1);
  cudaFuncSetAttribute((const void*)tmma_k<64, 128, 32, 32, 0, 0>,
                       cudaFuncAttributeMaxDynamicSharedMemorySize,
                       SMEM_64x128_T0);
  cudaFuncSetAttribute((const void*)tmma_k<64, 128, 32, 32, 0, 1>,
                       cudaFuncAttributeMaxDynamicSharedMemorySize,
                       SMEM_64x128_T0);
  cudaFuncSetAttribute((const void*)tmma_k<32, 128, 16, 32, 0, 0>,
                       cudaFuncAttributeMaxDynamicSharedMemorySize,
                       SMEM_32x128_T0);

  const float* x_in = (const float*)d_in[0];
  Wts w;
  w.ew = (const float*)d_in[1];  w.eb = (const float*)d_in[2];
  w.rw = (const float*)d_in[3];  w.rb = (const float*)d_in[4];
  w.ow = (const float*)d_in[5];  w.ob = (const float*)d_in[6];
  w.l1g = (const float*)d_in[7]; w.l1b = (const float*)d_in[8];
  w.w1 = (const float*)d_in[9];  w.b1 = (const float*)d_in[10];
  w.w2 = (const float*)d_in[11]; w.b2 = (const float*)d_in[12];
  w.l2g = (const float*)d_in[13]; w.l2b = (const float*)d_in[14];

  {
    const long long tot = (long long)L * E * D * TH_P + (long long)L * D * D +
                          (long long)L * D * F + (long long)L * F * D;
    prep_k<<<(int)((tot + 255) / 256), 256>>>(sc, w.ew, w.ow, w.w1, w.w2);
  }

  copy_round_k<<<cdiv((int)NX, 256), 256>>>(sc + OFF_X, x_in, NX);

  run_block(sc, sc + OFF_X, sc + OFF_X, 0, S, w);

  for (int c = 0; c < CYCLES; c++) run_segs(sc, c, w);

  run_block(sc, sc + OFF_X, (float*)d_out, 13, S, w);
}

// round 12
// speedup vs baseline: 1.6470x; 1.0270x over previous
#include <cuda_runtime.h>
#include <math.h>
#include <stdint.h>

// ---------------------------------------------------------------------------
// SLAMv2: 14-layer MoE-attention transformer, segmented schedule.
// Round 12: R11 (mega-batched segments) + smem-bandwidth fix: all linear
// GEMMs (out/FF1/FF2) use 128x128 blocks with 64x32 warp tiles (2x register
// reuse per smem byte). Attention GEMMs unchanged. Numerics bit-identical.
// ---------------------------------------------------------------------------

namespace {
constexpr int B = 2, S = 1024, D = 1000, E = 20, HD = 50, TH = 3 * HD;
constexpr int HD_P = 52;
constexpr int TH_P = 160;
constexpr int F = 2048, CYCLES = 3, L = 14;
constexpr int NP = 460;       // padded segment length
constexpr int ZS = B * E;     // 40 z per segment

constexpr long long NX = (long long)B * S * D;
constexpr long long OFF_X    = 0;
constexpr long long OFF_XNEW = OFF_X + NX;
constexpr long long OFF_T    = OFF_XNEW + NX;
constexpr long long OFF_X1   = OFF_T + NX;
constexpr long long OFF_Y    = OFF_X1 + NX;
constexpr long long OFF_A    = OFF_Y + NX;
constexpr long long OFF_ROUT = OFF_A + NX;
constexpr long long OFF_H    = OFF_ROUT + (long long)B * S * E;
constexpr long long OFF_QKV  = OFF_H + (long long)B * S * F;
constexpr long long OFF_SC   = OFF_QKV + (long long)B * E * 3 * S * HD_P;
constexpr long long OFF_EWP  = OFF_SC + (long long)B * E * S * S;
constexpr long long OFF_OWR  = OFF_EWP + (long long)L * E * D * TH_P;
constexpr long long OFF_W1R  = OFF_OWR + (long long)L * D * D;
constexpr long long OFF_W2R  = OFF_W1R + (long long)L * D * F;
constexpr long long N_ROWS4  = 4LL * B * NP;            // 3680 rows
constexpr long long OFF_T4   = OFF_W2R + (long long)L * F * D;
constexpr long long OFF_R4   = OFF_T4 + N_ROWS4 * D;
constexpr long long OFF_QKV4 = OFF_R4 + N_ROWS4 * E;
constexpr long long OFF_Y4   = OFF_QKV4 + 160LL * 3 * NP * HD_P;
constexpr long long OFF_A4   = OFF_Y4 + N_ROWS4 * D;
constexpr long long OFF_X14  = OFF_A4 + N_ROWS4 * D;
constexpr long long OFF_H4   = OFF_X14 + N_ROWS4 * D;
constexpr long long OFF_O4   = OFF_H4 + N_ROWS4 * F;
constexpr long long TOTAL    = OFF_O4 + N_ROWS4 * D;
// sco4 (160 * NP * NP = 33.86M) reuses OFF_SC region (41.9M) — checked.
}  // namespace

__device__ float g_scratch[TOTAL];
__device__ const int c_segN[4]  = {460, 409, 410, 410};
__device__ const int c_segST[4] = {0, 256, 460, 665};
__device__ const int c_segP1[4] = {460, 409, 410, 359};

struct GemmP {
  const float* A; const float* Bm; const float* bias; float* C;
  int M, N, K, lda, ldb, ldc;
  int aDiv; long long as1, as2;
  int bDiv; long long bs1, bs2;
  int cDiv; long long cs1, cs2;
  int biasDiv; long long biasS;
  long long splitStride;
  float scale;
  const float* rout; int routN;
  int zSeg;            // z's per segment (0 = no segment batching)
  long long bSeg;      // extra B offset per segment (layer stride)
  long long biasSeg;   // extra bias offset per segment
  int segFlags;        // 1: M=segN, 2: N=segN, 4: K=segN
};

__device__ __forceinline__ float to_tf32(float x) {
  asm("cvt.rna.tf32.f32 %0, %0;" : "+f"(x));
  return x;
}

__device__ __forceinline__ void cp16(uint32_t dst, const float* src, int bytes) {
  asm volatile("cp.async.cg.shared.global [%0], [%1], 16, %2;\n"
               :: "r"(dst), "l"(src), "r"(bytes));
}
__device__ __forceinline__ void cp_commit() {
  asm volatile("cp.async.commit_group;\n");
}
template <int N>
__device__ __forceinline__ void cp_wait() {
  asm volatile("cp.async.wait_group %0;\n" :: "n"(N));
}

// ---------------------------------------------------------------------------
// TF32 tensor-core GEMM; cp.async 4-stage ring; k-slot remap fragments.
// ---------------------------------------------------------------------------
template <int BM, int BN, int WM, int WN, int BTRANS, int EPI>
__global__ __launch_bounds__(256) void tmma_k(GemmP p) {
  constexpr int BK = 16, ST = 4;
  constexpr int SKA = BK + 4;
  constexpr int LDB0 = BN + 4;
  constexpr int ASZ = BM * SKA;
  constexpr int BSZ = BTRANS ? BN * SKA : BK * LDB0;
  constexpr int NWN = BN / WN;
  constexpr int MT = WM / 16, NT = WN / 8;
  constexpr int ACH = BM * 4;
  constexpr int AV_ = (ACH + 255) / 256;
  constexpr int BV_ = BN / 64;
  static_assert((BM / WM) * (BN / WN) == 8, "need 8 warps");

  extern __shared__ float sm[];
  float* As = sm;
  float* Bs = sm + ST * ASZ;
  const uint32_t a_u32 = (uint32_t)__cvta_generic_to_shared(As);
  const uint32_t b_u32 = (uint32_t)__cvta_generic_to_shared(Bs);

  const int z = blockIdx.z;
  int seg = 0;
  if (p.zSeg) seg = z / p.zSeg;
  const int Mloc = (p.segFlags & 1) ? c_segN[seg] : p.M;
  const int Nloc = (p.segFlags & 2) ? c_segN[seg] : p.N;
  const int Kloc = (p.segFlags & 4) ? c_segN[seg] : p.K;

  const float* Ab =
      p.A + (long long)(z / p.aDiv) * p.as1 + (long long)(z % p.aDiv) * p.as2;
  const float* Bb =
      p.Bm + (long long)(z / p.bDiv) * p.bs1 + (long long)(z % p.bDiv) * p.bs2 +
      (long long)seg * p.bSeg;
  float* Cb =
      p.C + (long long)(z / p.cDiv) * p.cs1 + (long long)(z % p.cDiv) * p.cs2;

  const int m0 = blockIdx.y * BM, n0 = blockIdx.x * BN;
  const int tid = threadIdx.x;
  const int warp = tid >> 5, lane = tid & 31;
  const int g = lane >> 2, t = lane & 3;
  const int wm = (warp / NWN) * WM, wn = (warp % NWN) * WN;

  auto issue = [&](int it) {
    const int s = it % ST;
    const int kb = it * BK;
#pragma unroll
    for (int v = 0; v < AV_; v++) {
      int idx = tid + v * 256;
      if ((ACH % 256) != 0 && idx >= ACH) break;
      int m = idx >> 2, c4 = (idx & 3) * 4;
      int gm = m0 + m, gk = kb + c4;
      int by = 0;
      if (gm < Mloc) {
        int rem = (Kloc - gk) * 4;
        by = rem > 16 ? 16 : (rem > 0 ? rem : 0);
      }
      const float* src = Ab + (long long)(by ? gm : 0) * p.lda + (by ? gk : 0);
      cp16(a_u32 + (uint32_t)(s * ASZ + m * SKA + c4) * 4u, src, by);
    }
    if (BTRANS == 0) {
#pragma unroll
      for (int v = 0; v < BV_; v++) {
        int idx = tid + v * 256;
        int kk = idx / (BN / 4), n4 = (idx % (BN / 4)) * 4;
        int gk = kb + kk, gn = n0 + n4;
        int by = 0;
        if (gk < Kloc) {
          int rem = (Nloc - gn) * 4;
          by = rem > 16 ? 16 : (rem > 0 ? rem : 0);
        }
        const float* src = Bb + (long long)(by ? gk : 0) * p.ldb + (by ? gn : 0);
        cp16(b_u32 + (uint32_t)(s * BSZ + kk * LDB0 + n4) * 4u, src, by);
      }
    } else {
#pragma unroll
      for (int v = 0; v < BV_; v++) {
        int idx = tid + v * 256;
        int n = idx >> 2, c4 = (idx & 3) * 4;
        int gn = n0 + n, gk = kb + c4;
        int by = 0;
        if (gn < Nloc) {
          int rem = (Kloc - gk) * 4;
          by = rem > 16 ? 16 : (rem > 0 ? rem : 0);
        }
        const float* src = Bb + (long long)(by ? gn : 0) * p.ldb + (by ? gk : 0);
        cp16(b_u32 + (uint32_t)(s * BSZ + n * SKA + c4) * 4u, src, by);
      }
    }
  };

  float c[MT][NT][4];
#pragma unroll
  for (int i = 0; i < MT; i++)
#pragma unroll
    for (int j = 0; j < NT; j++)
#pragma unroll
      for (int r = 0; r < 4; r++) c[i][j][r] = 0.f;

  auto comp = [&](int s) {
    const float* Asb = As + s * ASZ;
    const float* Bsb = Bs + s * BSZ;
#pragma unroll
    for (int kq = 0; kq < 2; kq++) {
      const int ko = kq * 8 + 2 * t;
      float2 af[MT][2];
#pragma unroll
      for (int mt = 0; mt < MT; mt++) {
        int r0 = wm + mt * 16 + g;
        af[mt][0] = *reinterpret_cast<const float2*>(&Asb[r0 * SKA + ko]);
        af[mt][1] = *reinterpret_cast<const float2*>(&Asb[(r0 + 8) * SKA + ko]);
      }
      float bx[NT], by_[NT];
#pragma unroll
      for (int nt = 0; nt < NT; nt++) {
        int col = wn + nt * 8 + g;
        if (BTRANS == 1) {
          float2 bb = *reinterpret_cast<const float2*>(&Bsb[col * SKA + ko]);
          bx[nt] = bb.x;
          by_[nt] = bb.y;
        } else {
          bx[nt] = Bsb[ko * LDB0 + col];
          by_[nt] = Bsb[(ko + 1) * LDB0 + col];
        }
      }
#pragma unroll
      for (int mt = 0; mt < MT; mt++)
#pragma unroll
        for (int nt = 0; nt < NT; nt++) {
          asm volatile(
              "mma.sync.aligned.m16n8k8.row.col.f32.tf32.tf32.f32 "
              "{%0,%1,%2,%3}, {%4,%5,%6,%7}, {%8,%9}, {%0,%1,%2,%3};"
              : "+f"(c[mt][nt][0]), "+f"(c[mt][nt][1]), "+f"(c[mt][nt][2]),
                "+f"(c[mt][nt][3])
              : "r"(__float_as_uint(af[mt][0].x)),
                "r"(__float_as_uint(af[mt][1].x)),
                "r"(__float_as_uint(af[mt][0].y)),
                "r"(__float_as_uint(af[mt][1].y)),
                "r"(__float_as_uint(bx[nt])), "r"(__float_as_uint(by_[nt])));
        }
    }
  };

  const int iters = (Kloc + BK - 1) / BK;
#pragma unroll
  for (int s = 0; s < ST - 1; s++) {
    if (s < iters) issue(s);
    cp_commit();
  }
  for (int it = 0; it < iters; it++) {
    cp_wait<ST - 2>();
    __syncthreads();
    if (it + ST - 1 < iters) issue(it + ST - 1);
    cp_commit();
    comp(it % ST);
  }

  const float* biasb = nullptr;
  if ((EPI == 0 || EPI == 1 || EPI == 4) && p.bias)
    biasb = p.bias + (long long)(z % p.biasDiv) * p.biasS +
            (long long)seg * p.biasSeg;

#pragma unroll
  for (int mt = 0; mt < MT; mt++)
#pragma unroll
    for (int nt = 0; nt < NT; nt++)
#pragma unroll
      for (int r = 0; r < 4; r++) {
        int row = m0 + wm + mt * 16 + g + ((r >> 1) ? 8 : 0);
        int col = n0 + wn + nt * 8 + 2 * t + (r & 1);
        if (row >= Mloc || col >= Nloc) continue;
        float v = c[mt][nt][r];
        if (biasb) v += biasb[col];
        if (EPI == 1) {
          v = 0.5f * v * (1.f + erff(v * 0.70710678118654752f));
          v = to_tf32(v);
        }
        if (EPI == 2) v *= p.scale;
        if (EPI == 3) {
          v *= p.rout[((long long)(z / p.cDiv) * p.routN + row) * E +
                      (z % p.cDiv)];
          v = to_tf32(v);
        }
        if (EPI == 4) {
          v = to_tf32(v);
          int h = col / HD, s2 = col - h * HD;
          Cb[(long long)h * p.splitStride + (long long)row * p.ldc + s2] = v;
        } else {
          Cb[(long long)row * p.ldc + col] = v;
        }
      }
}

// ---------------------------------------------------------------------------
// SIMT SGEMM (routing GEMM, N=20; fp32). z-batched via as1/bs1/cs1/biasS.
// ---------------------------------------------------------------------------
template <int BM, int BN, int BK, int TM, int TN>
__global__ __launch_bounds__((BM / TM) * (BN / TN)) void sgemm2_k(GemmP p) {
  constexpr int NTHR = (BM / TM) * (BN / TN);
  constexpr int TX = BN / TN;
  __shared__ float As[BK][BM + 4];
  __shared__ float Bs[BK][BN + 4];

  const int z = blockIdx.z;
  const float* Ab = p.A + (long long)z * p.as1;
  const float* Bb = p.Bm + (long long)z * p.bs1;
  float* Cb = p.C + (long long)z * p.cs1;
  const float* bias = p.bias ? p.bias + (long long)z * p.biasS : nullptr;

  const int m0 = blockIdx.y * BM, n0 = blockIdx.x * BN;
  const int tid = threadIdx.x;
  const int tx = tid % TX, ty = tid / TX;

  float acc[TM][TN];
#pragma unroll
  for (int i = 0; i < TM; i++)
#pragma unroll
    for (int j = 0; j < TN; j++) acc[i][j] = 0.f;

  for (int k0 = 0; k0 < p.K; k0 += BK) {
    for (int idx = tid; idx < BM * BK; idx += NTHR) {
      int m = idx / BK, kk = idx % BK;
      int gm = m0 + m, gk = k0 + kk;
      As[kk][m] = (gm < p.M && gk < p.K) ? Ab[(long long)gm * p.lda + gk] : 0.f;
    }
    for (int idx = tid; idx < BK * BN; idx += NTHR) {
      int kk = idx / BN, nn = idx % BN;
      int gk = k0 + kk, gn = n0 + nn;
      Bs[kk][nn] = (gk < p.K && gn < p.N) ? Bb[(long long)gk * p.ldb + gn] : 0.f;
    }
    __syncthreads();
#pragma unroll
    for (int kk = 0; kk < BK; kk++) {
      float a[TM], b[TN];
#pragma unroll
      for (int i = 0; i < TM; i++) a[i] = As[kk][ty * TM + i];
#pragma unroll
      for (int j = 0; j < TN; j++) b[j] = Bs[kk][tx * TN + j];
#pragma unroll
      for (int i = 0; i < TM; i++)
#pragma unroll
        for (int j = 0; j < TN; j++) acc[i][j] += a[i] * b[j];
    }
    __syncthreads();
  }

#pragma unroll
  for (int i = 0; i < TM; i++) {
    int row = m0 + ty * TM + i;
    if (row >= p.M) continue;
#pragma unroll
    for (int j = 0; j < TN; j++) {
      int col = n0 + tx * TN + j;
      if (col >= p.N) continue;
      float v = acc[i][j] + (bias ? bias[col] : 0.f);
      Cb[(long long)row * p.ldc + col] = v;
    }
  }
}

// ---------------------------------------------------------------------------
// One-launch weight prep (identical numerics to R7 prep kernels)
// ---------------------------------------------------------------------------
__global__ void prep_k(float* sc, const float* ew, const float* ow,
                       const float* w1, const float* w2) {
  const long long n_ewp = (long long)L * E * D * TH_P;
  const long long n_ow = (long long)L * D * D;
  const long long n_w1 = (long long)L * D * F;
  const long long n_w2 = (long long)L * F * D;
  long long i = (long long)blockIdx.x * blockDim.x + threadIdx.x;
  if (i < n_ewp) {
    int col = (int)(i % TH_P);
    long long base = i / TH_P;
    sc[OFF_EWP + i] = (col < TH) ? to_tf32(ew[base * TH + col]) : 0.f;
    return;
  }
  i -= n_ewp;
  if (i < n_ow) { sc[OFF_OWR + i] = to_tf32(ow[i]); return; }
  i -= n_ow;
  if (i < n_w1) { sc[OFF_W1R + i] = to_tf32(w1[i]); return; }
  i -= n_w1;
  if (i < n_w2) { sc[OFF_W2R + i] = to_tf32(w2[i]); }
}

// ---------------------------------------------------------------------------
// Small kernels
// ---------------------------------------------------------------------------
__global__ void copy_round_k(float* dst, const float* src, long long n) {
  long long i = (long long)blockIdx.x * blockDim.x + threadIdx.x;
  if (i < n) dst[i] = to_tf32(src[i]);
}

__global__ void gather4_k(float* t4, const float* x) {
  long long idx = (long long)blockIdx.x * blockDim.x + threadIdx.x;
  long long tot = N_ROWS4 * D;
  if (idx >= tot) return;
  int d = (int)(idx % D);
  long long r = idx / D;
  int i = (int)(r % NP);
  int b = (int)((r / NP) % B);
  int j = (int)(r / ((long long)NP * B));
  if (i >= c_segN[j]) return;
  int si = (i < c_segP1[j]) ? c_segST[j] + i : i - c_segP1[j];
  t4[idx] = x[((long long)b * S + si) * D + d];
}

__device__ __forceinline__ float seg_cnt(int i) {
  float c = 0.f;
  c += (i < 460);
  c += (i >= 256 && i < 665);
  c += (i >= 460 && i < 870);
  c += (i >= 665);
  c += (i < 51);
  return c;
}

__global__ void combine_k(float* x, const float* o4) {
  long long idx = (long long)blockIdx.x * blockDim.x + threadIdx.x;
  if (idx >= NX) return;
  int d = (int)(idx % D);
  long long r = idx / D;
  int i = (int)(r % S);
  int b = (int)(r / S);
  float s = 0.f;
  if (i < 460) s += o4[(((0 * B + b) * (long long)NP + i) * D) + d];
  if (i >= 256 && i < 665)
    s += o4[(((1 * B + b) * (long long)NP + (i - 256)) * D) + d];
  if (i >= 460 && i < 870)
    s += o4[(((2 * B + b) * (long long)NP + (i - 460)) * D) + d];
  if (i >= 665) s += o4[(((3 * B + b) * (long long)NP + (i - 665)) * D) + d];
  if (i < 51) s += o4[(((3 * B + b) * (long long)NP + (359 + i)) * D) + d];
  x[idx] = to_tf32(s / seg_cnt(i));
}

__global__ void softmaxE_k(float* r, int rows) {
  int i = blockIdx.x * blockDim.x + threadIdx.x;
  if (i >= rows) return;
  float* p = r + (long long)i * E;
  float m = -1e30f;
  for (int e = 0; e < E; e++) m = fmaxf(m, p[e]);
  float s = 0.f;
  for (int e = 0; e < E; e++) {
    float v = __expf(p[e] - m);
    p[e] = v;
    s += v;
  }
  float inv = 1.f / s;
  for (int e = 0; e < E; e++) p[e] *= inv;
}

__device__ __forceinline__ void softmax_row_body(float* row, int n) {
  __shared__ float red[32];
  __shared__ float bcast;
  int tid = threadIdx.x;
  int nw = blockDim.x >> 5;

  float m = -1e30f;
  for (int j = tid; j < n; j += blockDim.x) m = fmaxf(m, row[j]);
  for (int o = 16; o; o >>= 1) m = fmaxf(m, __shfl_xor_sync(0xffffffffu, m, o));
  if ((tid & 31) == 0) red[tid >> 5] = m;
  __syncthreads();
  if (tid < 32) {
    float v = (tid < nw) ? red[tid] : -1e30f;
    for (int o = 16; o; o >>= 1) v = fmaxf(v, __shfl_xor_sync(0xffffffffu, v, o));
    if (tid == 0) bcast = v;
  }
  __syncthreads();
  m = bcast;

  float sum = 0.f;
  for (int j = tid; j < n; j += blockDim.x) {
    float e = __expf(row[j] - m);
    row[j] = e;
    sum += e;
  }
  for (int o = 16; o; o >>= 1) sum += __shfl_xor_sync(0xffffffffu, sum, o);
  if ((tid & 31) == 0) red[tid >> 5] = sum;
  __syncthreads();
  if (tid < 32) {
    float v = (tid < nw) ? red[tid] : 0.f;
    for (int o = 16; o; o >>= 1) v += __shfl_xor_sync(0xffffffffu, v, o);
    if (tid == 0) bcast = v;
  }
  __syncthreads();
  float inv = 1.f / bcast;
  for (int j = tid; j < n; j += blockDim.x) row[j] = to_tf32(row[j] * inv);
}

__global__ void softmax_rows_k(float* s, int n, int ld) {
  float* row = s + (long long)blockIdx.y * n * ld + (long long)blockIdx.x * ld;
  softmax_row_body(row, n);
}

__global__ void softmax_rows4_k(float* s) {
  int z = blockIdx.y;
  int seg = z / ZS;
  int n = c_segN[seg];
  int row = blockIdx.x;
  if (row >= n) return;
  float* rp = s + (long long)z * NP * NP + (long long)row * NP;
  softmax_row_body(rp, n);
}

template <bool CVT, int SEGROWS>
__global__ void add_ln_k(const float* x, const float* r, const float* g,
                         const float* b, float* out) {
  long long base = (long long)blockIdx.x * D;
  if (SEGROWS > 0) {
    int seg = blockIdx.x / SEGROWS;
    g += (long long)seg * D;
    b += (long long)seg * D;
  }
  __shared__ float buf[D];
  __shared__ float redA[32], redB[32];
  __shared__ float sh_m, sh_inv;
  int tid = threadIdx.x;
  int nw = blockDim.x >> 5;

  float s = 0.f, s2 = 0.f;
  for (int d = tid; d < D; d += blockDim.x) {
    float v = x[base + d] + r[base + d];
    buf[d] = v;
    s += v;
    s2 += v * v;
  }
  for (int o = 16; o; o >>= 1) {
    s += __shfl_xor_sync(0xffffffffu, s, o);
    s2 += __shfl_xor_sync(0xffffffffu, s2, o);
  }
  if ((tid & 31) == 0) { redA[tid >> 5] = s; redB[tid >> 5] = s2; }
  __syncthreads();
  if (tid < 32) {
    float a2 = (tid < nw) ? redA[tid] : 0.f;
    float b2 = (tid < nw) ? redB[tid] : 0.f;
    for (int o = 16; o; o >>= 1) {
      a2 += __shfl_xor_sync(0xffffffffu, a2, o);
      b2 += __shfl_xor_sync(0xffffffffu, b2, o);
    }
    if (tid == 0) {
      float mean = a2 / D;
      float var = b2 / D - mean * mean;
      sh_m = mean;
      sh_inv = rsqrtf(var + 1e-5f);
    }
  }
  __syncthreads();
  float mean = sh_m, inv = sh_inv;
  for (int d = tid; d < D; d += blockDim.x) {
    float v = (buf[d] - mean) * inv * g[d] + b[d];
    out[base + d] = CVT ? to_tf32(v) : v;
  }
}

// ---------------------------------------------------------------------------
// Host-side driver
// ---------------------------------------------------------------------------
static inline int cdiv(int a, int b) { return (a + b - 1) / b; }

struct Wts {
  const float *ew, *eb, *rw, *rb, *ow, *ob, *l1g, *l1b, *w1, *b1, *w2, *b2,
      *l2g, *l2b;
};

constexpr int SMEM_128x64_T0 = 4 * (128 * 20 + 16 * 68) * 4;     // 58368
constexpr int SMEM_128x128_T1 = 4 * (128 * 20 + 128 * 20) * 4;   // 81920
constexpr int SMEM_128x128_T0 = 4 * (128 * 20 + 16 * 132) * 4;   // 74752

// -------------------- full-sequence block (layers 0 and 13) ----------------
static void run_block(float* sc, const float* t, float* out, int layer, int n,
                      const Wts& w) {
  const int M = B * n;
  const int n4 = (n + 3) & ~3;
  float* rout = sc + OFF_ROUT;
  float* qkv = sc + OFF_QKV;
  float* sco = sc + OFF_SC;
  float* y = sc + OFF_Y;
  float* a = sc + OFF_A;
  float* x1 = sc + OFF_X1;
  float* h = sc + OFF_H;
  const float* ewp = sc + OFF_EWP + (long long)layer * E * D * TH_P;
  const float* owr = sc + OFF_OWR + (long long)layer * D * D;
  const float* w1r = sc + OFF_W1R + (long long)layer * D * F;
  const float* w2r = sc + OFF_W2R + (long long)layer * F * D;

  GemmP p;
  auto reset = [&]() {
    p = GemmP{};
    p.aDiv = p.bDiv = p.cDiv = p.biasDiv = 1;
    p.scale = 1.f;
  };

  reset();
  p.A = t; p.Bm = w.rw + (long long)layer * D * E;
  p.bias = w.rb + (long long)layer * E; p.C = rout;
  p.M = M; p.N = E; p.K = D; p.lda = D; p.ldb = E; p.ldc = E;
  sgemm2_k<64, 64, 16, 4, 4><<<dim3(1, cdiv(M, 64), 1), 256>>>(p);
  softmaxE_k<<<cdiv(M, 256), 256>>>(rout, M);

  reset();
  p.A = t; p.lda = D; p.aDiv = E; p.as1 = (long long)n * D;
  p.Bm = ewp; p.ldb = TH_P;
  p.bDiv = E; p.bs2 = (long long)D * TH_P;
  p.bias = w.eb + (long long)layer * E * TH; p.biasDiv = E; p.biasS = TH;
  p.C = qkv; p.ldc = HD_P; p.cs1 = 3LL * n * HD_P;
  p.splitStride = (long long)n * HD_P;
  p.M = n; p.N = TH; p.K = D;
  tmma_k<128, 64, 32, 32, 0, 4>
      <<<dim3(3, cdiv(n, 128), B * E), 256, SMEM_128x64_T0>>>(p);

  reset();
  p.A = qkv; p.lda = HD_P; p.as1 = 3LL * n * HD_P;
  p.Bm = qkv + (long long)n * HD_P; p.ldb = HD_P; p.bs1 = 3LL * n * HD_P;
  p.C = sco; p.ldc = n4; p.cs1 = (long long)n * n4;
  p.M = n; p.N = n; p.K = HD;
  p.scale = 0.14142135623730950488f;
  tmma_k<128, 128, 64, 32, 1, 2>
      <<<dim3(cdiv(n, 128), cdiv(n, 128), B * E), 256, SMEM_128x128_T1>>>(p);

  softmax_rows_k<<<dim3(n, B * E), 256>>>(sco, n, n4);

  reset();
  p.A = sco; p.lda = n4; p.as1 = (long long)n * n4;
  p.Bm = qkv + 2LL * n * HD_P; p.ldb = HD_P; p.bs1 = 3LL * n * HD_P;
  p.C = y; p.ldc = D; p.cDiv = E; p.cs1 = (long long)n * D; p.cs2 = HD;
  p.M = n; p.N = HD; p.K = n;
  p.rout = rout; p.routN = n;
  tmma_k<128, 64, 32, 32, 0, 3>
      <<<dim3(1, cdiv(n, 128), B * E), 256, SMEM_128x64_T0>>>(p);

  reset();
  p.A = y; p.lda = D;
  p.Bm = owr; p.ldb = D;
  p.bias = w.ob + (long long)layer * D;
  p.C = a; p.ldc = D;
  p.M = M; p.N = D; p.K = D;
  tmma_k<128, 128, 64, 32, 0, 0>
      <<<dim3(cdiv(D, 128), cdiv(M, 128), 1), 256, SMEM_128x128_T0>>>(p);

  add_ln_k<true, 0><<<M, 256>>>(t, a, w.l1g + (long long)layer * D,
                                w.l1b + (long long)layer * D, x1);

  reset();
  p.A = x1; p.lda = D;
  p.Bm = w1r; p.ldb = F;
  p.bias = w.b1 + (long long)layer * F;
  p.C = h; p.ldc = F;
  p.M = M; p.N = F; p.K = D;
  tmma_k<128, 128, 64, 32, 0, 1>
      <<<dim3(cdiv(F, 128), cdiv(M, 128), 1), 256, SMEM_128x128_T0>>>(p);

  reset();
  p.A = h; p.lda = F;
  p.Bm = w2r; p.ldb = D;
  p.bias = w.b2 + (long long)layer * D;
  p.C = y; p.ldc = D;
  p.M = M; p.N = D; p.K = F;
  tmma_k<128, 128, 64, 32, 0, 0>
      <<<dim3(cdiv(D, 128), cdiv(M, 128), 1), 256, SMEM_128x128_T0>>>(p);

  if (layer == L - 1)
    add_ln_k<false, 0><<<M, 256>>>(x1, y, w.l2g + (long long)layer * D,
                                   w.l2b + (long long)layer * D, out);
  else
    add_ln_k<true, 0><<<M, 256>>>(x1, y, w.l2g + (long long)layer * D,
                                  w.l2b + (long long)layer * D, out);
}

// -------------------- mega-batched 4-segment cycle --------------------------
static void run_segs(float* sc, int cyc, const Wts& w) {
  const int layerBase = 1 + 4 * cyc;
  const int MROWS = B * NP;          // 920 rows per segment
  const int NR4 = 4 * MROWS;         // 3680 rows total
  float* t4 = sc + OFF_T4;
  float* r4 = sc + OFF_R4;
  float* qkv4 = sc + OFF_QKV4;
  float* sco4 = sc + OFF_SC;
  float* y4 = sc + OFF_Y4;
  float* a4 = sc + OFF_A4;
  float* x14 = sc + OFF_X14;
  float* h4 = sc + OFF_H4;
  float* o4 = sc + OFF_O4;

  gather4_k<<<(int)((N_ROWS4 * D + 255) / 256), 256>>>(t4, sc + OFF_X);

  GemmP p;
  auto reset = [&]() {
    p = GemmP{};
    p.aDiv = p.bDiv = p.cDiv = p.biasDiv = 1;
    p.scale = 1.f;
  };

  // routing (z = 4 segments)
  reset();
  p.A = t4; p.lda = D; p.as1 = (long long)MROWS * D;
  p.Bm = w.rw + (long long)layerBase * D * E; p.ldb = E; p.bs1 = (long long)D * E;
  p.bias = w.rb + (long long)layerBase * E; p.biasS = E;
  p.C = r4; p.ldc = E; p.cs1 = (long long)MROWS * E;
  p.M = MROWS; p.N = E; p.K = D;
  sgemm2_k<64, 64, 16, 4, 4><<<dim3(1, cdiv(MROWS, 64), 4), 256>>>(p);
  softmaxE_k<<<cdiv(NR4, 256), 256>>>(r4, NR4);

  // qkv (z = 160)
  reset();
  p.A = t4; p.lda = D; p.aDiv = E; p.as1 = (long long)NP * D;
  p.Bm = sc + OFF_EWP + (long long)layerBase * E * D * TH_P; p.ldb = TH_P;
  p.bDiv = E; p.bs2 = (long long)D * TH_P;
  p.bias = w.eb + (long long)layerBase * E * TH; p.biasDiv = E; p.biasS = TH;
  p.C = qkv4; p.ldc = HD_P; p.cs1 = 3LL * NP * HD_P;
  p.splitStride = (long long)NP * HD_P;
  p.N = TH; p.K = D;
  p.zSeg = ZS; p.bSeg = (long long)E * D * TH_P; p.biasSeg = (long long)E * TH;
  p.segFlags = 1;
  tmma_k<128, 64, 32, 32, 0, 4>
      <<<dim3(3, cdiv(NP, 128), 4 * ZS), 256, SMEM_128x64_T0>>>(p);

  // scores (z = 160)
  reset();
  p.A = qkv4; p.lda = HD_P; p.as1 = 3LL * NP * HD_P;
  p.Bm = qkv4 + (long long)NP * HD_P; p.ldb = HD_P; p.bs1 = 3LL * NP * HD_P;
  p.C = sco4; p.ldc = NP; p.cs1 = (long long)NP * NP;
  p.K = HD;
  p.scale = 0.14142135623730950488f;
  p.zSeg = ZS; p.segFlags = 1 | 2;
  tmma_k<128, 128, 64, 32, 1, 2>
      <<<dim3(cdiv(NP, 128), cdiv(NP, 128), 4 * ZS), 256, SMEM_128x128_T1>>>(p);

  softmax_rows4_k<<<dim3(NP, 4 * ZS), 256>>>(sco4);

  // AV (z = 160)
  reset();
  p.A = sco4; p.lda = NP; p.as1 = (long long)NP * NP;
  p.Bm = qkv4 + 2LL * NP * HD_P; p.ldb = HD_P; p.bs1 = 3LL * NP * HD_P;
  p.C = y4; p.ldc = D; p.cDiv = E; p.cs1 = (long long)NP * D; p.cs2 = HD;
  p.N = HD;
  p.rout = r4; p.routN = NP;
  p.zSeg = ZS; p.segFlags = 1 | 4;
  tmma_k<128, 64, 32, 32, 0, 3>
      <<<dim3(1, cdiv(NP, 128), 4 * ZS), 256, SMEM_128x64_T0>>>(p);

  // out projection (z = 4)
  reset();
  p.A = y4; p.lda = D; p.as1 = (long long)MROWS * D;
  p.Bm = sc + OFF_OWR + (long long)layerBase * D * D; p.ldb = D;
  p.bias = w.ob + (long long)layerBase * D;
  p.C = a4; p.ldc = D; p.cs1 = (long long)MROWS * D;
  p.M = MROWS; p.N = D; p.K = D;
  p.zSeg = 1; p.bSeg = (long long)D * D; p.biasSeg = D;
  tmma_k<128, 128, 64, 32, 0, 0>
      <<<dim3(cdiv(D, 128), cdiv(MROWS, 128), 4), 256, SMEM_128x128_T0>>>(p);

  add_ln_k<true, B * NP><<<NR4, 256>>>(
      t4, a4, w.l1g + (long long)layerBase * D, w.l1b + (long long)layerBase * D,
      x14);

  // FF1 (z = 4)
  reset();
  p.A = x14; p.lda = D; p.as1 = (long long)MROWS * D;
  p.Bm = sc + OFF_W1R + (long long)layerBase * D * F; p.ldb = F;
  p.bias = w.b1 + (long long)layerBase * F;
  p.C = h4; p.ldc = F; p.cs1 = (long long)MROWS * F;
  p.M = MROWS; p.N = F; p.K = D;
  p.zSeg = 1; p.bSeg = (long long)D * F; p.biasSeg = F;
  tmma_k<128, 128, 64, 32, 0, 1>
      <<<dim3(cdiv(F, 128), cdiv(MROWS, 128), 4), 256, SMEM_128x128_T0>>>(p);

  // FF2 (z = 4) -> y4 (free after out projection)
  reset();
  p.A = h4; p.lda = F; p.as1 = (long long)MROWS * F;
  p.Bm = sc + OFF_W2R + (long long)layerBase * F * D; p.ldb = D;
  p.bias = w.b2 + (long long)layerBase * D;
  p.C = y4; p.ldc = D; p.cs1 = (long long)MROWS * D;
  p.M = MROWS; p.N = D; p.K = F;
  p.zSeg = 1; p.bSeg = (long long)F * D; p.biasSeg = D;
  tmma_k<128, 128, 64, 32, 0, 0>
      <<<dim3(cdiv(D, 128), cdiv(MROWS, 128), 4), 256, SMEM_128x128_T0>>>(p);

  add_ln_k<true, B * NP><<<NR4, 256>>>(
      x14, y4, w.l2g + (long long)layerBase * D,
      w.l2b + (long long)layerBase * D, o4);

  combine_k<<<cdiv((int)NX, 256), 256>>>(sc + OFF_X, o4);
}

extern "C" void kernel_launch(void* const* d_in, const int* in_sizes, int n_in,
                              void* d_out, int out_size) {
  (void)in_sizes; (void)n_in; (void)out_size;
  float* sc = nullptr;
  cudaGetSymbolAddress((void**)&sc, g_scratch);

  cudaFuncSetAttribute((const void*)tmma_k<128, 64, 32, 32, 0, 4>,
                       cudaFuncAttributeMaxDynamicSharedMemorySize,
                       SMEM_128x64_T0);
  cudaFuncSetAttribute((const void*)tmma_k<128, 64, 32, 32, 0, 3>,
                       cudaFuncAttributeMaxDynamicSharedMemorySize,
                       SMEM_128x64_T0);
  cudaFuncSetAttribute((const void*)tmma_k<128, 128, 64, 32, 1, 2>,
                       cudaFuncAttributeMaxDynamicSharedMemorySize,
                       SMEM_128x128_T1);
  cudaFuncSetAttribute((const void*)tmma_k<128, 128, 64, 32, 0, 0>,
                       cudaFuncAttributeMaxDynamicSharedMemorySize,
                       SMEM_128x128_T0);
  cudaFuncSetAttribute((const void*)tmma_k<128, 128, 64, 32, 0, 1>,
                       cudaFuncAttributeMaxDynamicSharedMemorySize,
                       SMEM_128x128_T0);

  const float* x_in = (const float*)d_in[0];
  Wts w;
  w.ew = (const float*)d_in[1];  w.eb = (const float*)d_in[2];
  w.rw = (const float*)d_in[3];  w.rb = (const float*)d_in[4];
  w.ow = (const float*)d_in[5];  w.ob = (const float*)d_in[6];
  w.l1g = (const float*)d_in[7]; w.l1b = (const float*)d_in[8];
  w.w1 = (const float*)d_in[9];  w.b1 = (const float*)d_in[10];
  w.w2 = (const float*)d_in[11]; w.b2 = (const float*)d_in[12];
  w.l2g = (const float*)d_in[13]; w.l2b = (const float*)d_in[14];

  {
    const long long tot = (long long)L * E * D * TH_P + (long long)L * D * D +
                          (long long)L * D * F + (long long)L * F * D;
    prep_k<<<(int)((tot + 255) / 256), 256>>>(sc, w.ew, w.ow, w.w1, w.w2);
  }

  copy_round_k<<<cdiv((int)NX, 256), 256>>>(sc + OFF_X, x_in, NX);

  run_block(sc, sc + OFF_X, sc + OFF_X, 0, S, w);

  for (int c = 0; c < CYCLES; c++) run_segs(sc, c, w);

  run_block(sc, sc + OFF_X, (float*)d_out, 13, S, w);
}

// round 13
// speedup vs baseline: 1.7073x; 1.0366x over previous
#include <cuda_runtime.h>
#include <math.h>
#include <stdint.h>

// ---------------------------------------------------------------------------
// SLAMv2: 14-layer MoE-attention transformer, segmented schedule.
// Round 13: R12 + qkv reshaped to ONE wide GEMM (N = E*TH = 3000) on the
// 128x128/64x32 path: expert weights repacked [D][E*TH], EPI=6 epilogue
// scatters to the unchanged Q/K/V split layout. Removes 28% N-padding waste
// and E-fold A reloads. Numerics bit-identical (rel_err 7.0038e-4 checksum).
// ---------------------------------------------------------------------------

namespace {
constexpr int B = 2, S = 1024, D = 1000, E = 20, HD = 50, TH = 3 * HD;
constexpr int HD_P = 52;
constexpr int EN = E * TH;    // 3000 — wide qkv N
constexpr int F = 2048, CYCLES = 3, L = 14;
constexpr int NP = 460;       // padded segment length
constexpr int ZS = B * E;     // 40 z per segment

constexpr long long NX = (long long)B * S * D;
constexpr long long OFF_X    = 0;
constexpr long long OFF_XNEW = OFF_X + NX;
constexpr long long OFF_T    = OFF_XNEW + NX;
constexpr long long OFF_X1   = OFF_T + NX;
constexpr long long OFF_Y    = OFF_X1 + NX;
constexpr long long OFF_A    = OFF_Y + NX;
constexpr long long OFF_ROUT = OFF_A + NX;
constexpr long long OFF_H    = OFF_ROUT + (long long)B * S * E;
constexpr long long OFF_QKV  = OFF_H + (long long)B * S * F;
constexpr long long OFF_SC   = OFF_QKV + (long long)B * E * 3 * S * HD_P;
constexpr long long OFF_EWP  = OFF_SC + (long long)B * E * S * S;  // [L][D][EN]
constexpr long long OFF_OWR  = OFF_EWP + (long long)L * D * EN;
constexpr long long OFF_W1R  = OFF_OWR + (long long)L * D * D;
constexpr long long OFF_W2R  = OFF_W1R + (long long)L * D * F;
constexpr long long N_ROWS4  = 4LL * B * NP;            // 3680 rows
constexpr long long OFF_T4   = OFF_W2R + (long long)L * F * D;
constexpr long long OFF_R4   = OFF_T4 + N_ROWS4 * D;
constexpr long long OFF_QKV4 = OFF_R4 + N_ROWS4 * E;
constexpr long long OFF_Y4   = OFF_QKV4 + 160LL * 3 * NP * HD_P;
constexpr long long OFF_A4   = OFF_Y4 + N_ROWS4 * D;
constexpr long long OFF_X14  = OFF_A4 + N_ROWS4 * D;
constexpr long long OFF_H4   = OFF_X14 + N_ROWS4 * D;
constexpr long long OFF_O4   = OFF_H4 + N_ROWS4 * F;
constexpr long long TOTAL    = OFF_O4 + N_ROWS4 * D;
// sco4 (160 * NP * NP = 33.86M) reuses OFF_SC region (41.9M) — checked.
}  // namespace

__device__ float g_scratch[TOTAL];
__device__ const int c_segN[4]  = {460, 409, 410, 410};
__device__ const int c_segST[4] = {0, 256, 460, 665};
__device__ const int c_segP1[4] = {460, 409, 410, 359};

struct GemmP {
  const float* A; const float* Bm; const float* bias; float* C;
  int M, N, K, lda, ldb, ldc;
  int aDiv; long long as1, as2;
  int bDiv; long long bs1, bs2;
  int cDiv; long long cs1, cs2;
  int biasDiv; long long biasS;
  long long splitStride;
  float scale;
  const float* rout; int routN;
  int zSeg;            // z's per segment (0 = no segment batching)
  long long bSeg;      // extra B offset per segment (layer stride)
  long long biasSeg;   // extra bias offset per segment
  int segFlags;        // 1: M=segN, 2: N=segN, 4: K=segN
};

__device__ __forceinline__ float to_tf32(float x) {
  asm("cvt.rna.tf32.f32 %0, %0;" : "+f"(x));
  return x;
}

__device__ __forceinline__ void cp16(uint32_t dst, const float* src, int bytes) {
  asm volatile("cp.async.cg.shared.global [%0], [%1], 16, %2;\n"
               :: "r"(dst), "l"(src), "r"(bytes));
}
__device__ __forceinline__ void cp_commit() {
  asm volatile("cp.async.commit_group;\n");
}
template <int N>
__device__ __forceinline__ void cp_wait() {
  asm volatile("cp.async.wait_group %0;\n" :: "n"(N));
}

// ---------------------------------------------------------------------------
// TF32 tensor-core GEMM; cp.async 4-stage ring; k-slot remap fragments.
// EPI: 0 +bias; 1 +bias,GELU(round); 2 *scale; 3 *routing(round);
//      4 +bias,split-QKV(round); 6 +bias, wide-N qkv scatter (round).
// ---------------------------------------------------------------------------
template <int BM, int BN, int WM, int WN, int BTRANS, int EPI>
__global__ __launch_bounds__(256) void tmma_k(GemmP p) {
  constexpr int BK = 16, ST = 4;
  constexpr int SKA = BK + 4;
  constexpr int LDB0 = BN + 4;
  constexpr int ASZ = BM * SKA;
  constexpr int BSZ = BTRANS ? BN * SKA : BK * LDB0;
  constexpr int NWN = BN / WN;
  constexpr int MT = WM / 16, NT = WN / 8;
  constexpr int ACH = BM * 4;
  constexpr int AV_ = (ACH + 255) / 256;
  constexpr int BV_ = BN / 64;
  static_assert((BM / WM) * (BN / WN) == 8, "need 8 warps");

  extern __shared__ float sm[];
  float* As = sm;
  float* Bs = sm + ST * ASZ;
  const uint32_t a_u32 = (uint32_t)__cvta_generic_to_shared(As);
  const uint32_t b_u32 = (uint32_t)__cvta_generic_to_shared(Bs);

  const int z = blockIdx.z;
  int seg = 0;
  if (p.zSeg) seg = z / p.zSeg;
  const int Mloc = (p.segFlags & 1) ? c_segN[seg] : p.M;
  const int Nloc = (p.segFlags & 2) ? c_segN[seg] : p.N;
  const int Kloc = (p.segFlags & 4) ? c_segN[seg] : p.K;

  const float* Ab =
      p.A + (long long)(z / p.aDiv) * p.as1 + (long long)(z % p.aDiv) * p.as2;
  const float* Bb =
      p.Bm + (long long)(z / p.bDiv) * p.bs1 + (long long)(z % p.bDiv) * p.bs2 +
      (long long)seg * p.bSeg;
  float* Cb =
      p.C + (long long)(z / p.cDiv) * p.cs1 + (long long)(z % p.cDiv) * p.cs2;

  const int m0 = blockIdx.y * BM, n0 = blockIdx.x * BN;
  const int tid = threadIdx.x;
  const int warp = tid >> 5, lane = tid & 31;
  const int g = lane >> 2, t = lane & 3;
  const int wm = (warp / NWN) * WM, wn = (warp % NWN) * WN;

  auto issue = [&](int it) {
    const int s = it % ST;
    const int kb = it * BK;
#pragma unroll
    for (int v = 0; v < AV_; v++) {
      int idx = tid + v * 256;
      if ((ACH % 256) != 0 && idx >= ACH) break;
      int m = idx >> 2, c4 = (idx & 3) * 4;
      int gm = m0 + m, gk = kb + c4;
      int by = 0;
      if (gm < Mloc) {
        int rem = (Kloc - gk) * 4;
        by = rem > 16 ? 16 : (rem > 0 ? rem : 0);
      }
      const float* src = Ab + (long long)(by ? gm : 0) * p.lda + (by ? gk : 0);
      cp16(a_u32 + (uint32_t)(s * ASZ + m * SKA + c4) * 4u, src, by);
    }
    if (BTRANS == 0) {
#pragma unroll
      for (int v = 0; v < BV_; v++) {
        int idx = tid + v * 256;
        int kk = idx / (BN / 4), n4 = (idx % (BN / 4)) * 4;
        int gk = kb + kk, gn = n0 + n4;
        int by = 0;
        if (gk < Kloc) {
          int rem = (Nloc - gn) * 4;
          by = rem > 16 ? 16 : (rem > 0 ? rem : 0);
        }
        const float* src = Bb + (long long)(by ? gk : 0) * p.ldb + (by ? gn : 0);
        cp16(b_u32 + (uint32_t)(s * BSZ + kk * LDB0 + n4) * 4u, src, by);
      }
    } else {
#pragma unroll
      for (int v = 0; v < BV_; v++) {
        int idx = tid + v * 256;
        int n = idx >> 2, c4 = (idx & 3) * 4;
        int gn = n0 + n, gk = kb + c4;
        int by = 0;
        if (gn < Nloc) {
          int rem = (Kloc - gk) * 4;
          by = rem > 16 ? 16 : (rem > 0 ? rem : 0);
        }
        const float* src = Bb + (long long)(by ? gn : 0) * p.ldb + (by ? gk : 0);
        cp16(b_u32 + (uint32_t)(s * BSZ + n * SKA + c4) * 4u, src, by);
      }
    }
  };

  float c[MT][NT][4];
#pragma unroll
  for (int i = 0; i < MT; i++)
#pragma unroll
    for (int j = 0; j < NT; j++)
#pragma unroll
      for (int r = 0; r < 4; r++) c[i][j][r] = 0.f;

  auto comp = [&](int s) {
    const float* Asb = As + s * ASZ;
    const float* Bsb = Bs + s * BSZ;
#pragma unroll
    for (int kq = 0; kq < 2; kq++) {
      const int ko = kq * 8 + 2 * t;
      float2 af[MT][2];
#pragma unroll
      for (int mt = 0; mt < MT; mt++) {
        int r0 = wm + mt * 16 + g;
        af[mt][0] = *reinterpret_cast<const float2*>(&Asb[r0 * SKA + ko]);
        af[mt][1] = *reinterpret_cast<const float2*>(&Asb[(r0 + 8) * SKA + ko]);
      }
      float bx[NT], by_[NT];
#pragma unroll
      for (int nt = 0; nt < NT; nt++) {
        int col = wn + nt * 8 + g;
        if (BTRANS == 1) {
          float2 bb = *reinterpret_cast<const float2*>(&Bsb[col * SKA + ko]);
          bx[nt] = bb.x;
          by_[nt] = bb.y;
        } else {
          bx[nt] = Bsb[ko * LDB0 + col];
          by_[nt] = Bsb[(ko + 1) * LDB0 + col];
        }
      }
#pragma unroll
      for (int mt = 0; mt < MT; mt++)
#pragma unroll
        for (int nt = 0; nt < NT; nt++) {
          asm volatile(
              "mma.sync.aligned.m16n8k8.row.col.f32.tf32.tf32.f32 "
              "{%0,%1,%2,%3}, {%4,%5,%6,%7}, {%8,%9}, {%0,%1,%2,%3};"
              : "+f"(c[mt][nt][0]), "+f"(c[mt][nt][1]), "+f"(c[mt][nt][2]),
                "+f"(c[mt][nt][3])
              : "r"(__float_as_uint(af[mt][0].x)),
                "r"(__float_as_uint(af[mt][1].x)),
                "r"(__float_as_uint(af[mt][0].y)),
                "r"(__float_as_uint(af[mt][1].y)),
                "r"(__float_as_uint(bx[nt])), "r"(__float_as_uint(by_[nt])));
        }
    }
  };

  const int iters = (Kloc + BK - 1) / BK;
#pragma unroll
  for (int s = 0; s < ST - 1; s++) {
    if (s < iters) issue(s);
    cp_commit();
  }
  for (int it = 0; it < iters; it++) {
    cp_wait<ST - 2>();
    __syncthreads();
    if (it + ST - 1 < iters) issue(it + ST - 1);
    cp_commit();
    comp(it % ST);
  }

  const float* biasb = nullptr;
  if ((EPI == 0 || EPI == 1 || EPI == 4 || EPI == 6) && p.bias)
    biasb = p.bias + (long long)(z % p.biasDiv) * p.biasS +
            (long long)seg * p.biasSeg;

#pragma unroll
  for (int mt = 0; mt < MT; mt++)
#pragma unroll
    for (int nt = 0; nt < NT; nt++)
#pragma unroll
      for (int r = 0; r < 4; r++) {
        int row = m0 + wm + mt * 16 + g + ((r >> 1) ? 8 : 0);
        int col = n0 + wn + nt * 8 + 2 * t + (r & 1);
        if (row >= Mloc || col >= Nloc) continue;
        float v = c[mt][nt][r];
        if (biasb) v += biasb[col];
        if (EPI == 1) {
          v = 0.5f * v * (1.f + erff(v * 0.70710678118654752f));
          v = to_tf32(v);
        }
        if (EPI == 2) v *= p.scale;
        if (EPI == 3) {
          v *= p.rout[((long long)(z / p.cDiv) * p.routN + row) * E +
                      (z % p.cDiv)];
          v = to_tf32(v);
        }
        if (EPI == 4) {
          v = to_tf32(v);
          int h = col / HD, s2 = col - h * HD;
          Cb[(long long)h * p.splitStride + (long long)row * p.ldc + s2] = v;
        } else if (EPI == 6) {
          // wide-N qkv scatter: col -> (e, h, s2); row -> (b, i).
          v = to_tf32(v);
          int e = col / TH;
          int th = col - e * TH;
          int h = th / HD;
          int s2 = th - h * HD;
          int b = row / p.routN;
          int i = row - b * p.routN;
          Cb[(long long)(b * E + e) * 3 * p.splitStride +
             (long long)h * p.splitStride + (long long)i * p.ldc + s2] = v;
        } else {
          Cb[(long long)row * p.ldc + col] = v;
        }
      }
}

// ---------------------------------------------------------------------------
// SIMT SGEMM (routing GEMM, N=20; fp32). z-batched via as1/bs1/cs1/biasS.
// ---------------------------------------------------------------------------
template <int BM, int BN, int BK, int TM, int TN>
__global__ __launch_bounds__((BM / TM) * (BN / TN)) void sgemm2_k(GemmP p) {
  constexpr int NTHR = (BM / TM) * (BN / TN);
  constexpr int TX = BN / TN;
  __shared__ float As[BK][BM + 4];
  __shared__ float Bs[BK][BN + 4];

  const int z = blockIdx.z;
  const float* Ab = p.A + (long long)z * p.as1;
  const float* Bb = p.Bm + (long long)z * p.bs1;
  float* Cb = p.C + (long long)z * p.cs1;
  const float* bias = p.bias ? p.bias + (long long)z * p.biasS : nullptr;

  const int m0 = blockIdx.y * BM, n0 = blockIdx.x * BN;
  const int tid = threadIdx.x;
  const int tx = tid % TX, ty = tid / TX;

  float acc[TM][TN];
#pragma unroll
  for (int i = 0; i < TM; i++)
#pragma unroll
    for (int j = 0; j < TN; j++) acc[i][j] = 0.f;

  for (int k0 = 0; k0 < p.K; k0 += BK) {
    for (int idx = tid; idx < BM * BK; idx += NTHR) {
      int m = idx / BK, kk = idx % BK;
      int gm = m0 + m, gk = k0 + kk;
      As[kk][m] = (gm < p.M && gk < p.K) ? Ab[(long long)gm * p.lda + gk] : 0.f;
    }
    for (int idx = tid; idx < BK * BN; idx += NTHR) {
      int kk = idx / BN, nn = idx % BN;
      int gk = k0 + kk, gn = n0 + nn;
      Bs[kk][nn] = (gk < p.K && gn < p.N) ? Bb[(long long)gk * p.ldb + gn] : 0.f;
    }
    __syncthreads();
#pragma unroll
    for (int kk = 0; kk < BK; kk++) {
      float a[TM], b[TN];
#pragma unroll
      for (int i = 0; i < TM; i++) a[i] = As[kk][ty * TM + i];
#pragma unroll
      for (int j = 0; j < TN; j++) b[j] = Bs[kk][tx * TN + j];
#pragma unroll
      for (int i = 0; i < TM; i++)
#pragma unroll
        for (int j = 0; j < TN; j++) acc[i][j] += a[i] * b[j];
    }
    __syncthreads();
  }

#pragma unroll
  for (int i = 0; i < TM; i++) {
    int row = m0 + ty * TM + i;
    if (row >= p.M) continue;
#pragma unroll
    for (int j = 0; j < TN; j++) {
      int col = n0 + tx * TN + j;
      if (col >= p.N) continue;
      float v = acc[i][j] + (bias ? bias[col] : 0.f);
      Cb[(long long)row * p.ldc + col] = v;
    }
  }
}

// ---------------------------------------------------------------------------
// One-launch weight prep: ew [L][E][D][TH] -> [L][D][E*TH] (tf32-rounded);
// ow/w1/w2 rounded in place layout.
// ---------------------------------------------------------------------------
__global__ void prep_k(float* sc, const float* ew, const float* ow,
                       const float* w1, const float* w2) {
  const long long n_ewp = (long long)L * D * EN;
  const long long n_ow = (long long)L * D * D;
  const long long n_w1 = (long long)L * D * F;
  const long long n_w2 = (long long)L * F * D;
  long long i = (long long)blockIdx.x * blockDim.x + threadIdx.x;
  if (i < n_ewp) {
    int col = (int)(i % EN);
    long long r = i / EN;
    int d = (int)(r % D);
    int l = (int)(r / D);
    int e = col / TH, th = col - e * TH;
    sc[OFF_EWP + i] =
        to_tf32(ew[(((long long)l * E + e) * D + d) * TH + th]);
    return;
  }
  i -= n_ewp;
  if (i < n_ow) { sc[OFF_OWR + i] = to_tf32(ow[i]); return; }
  i -= n_ow;
  if (i < n_w1) { sc[OFF_W1R + i] = to_tf32(w1[i]); return; }
  i -= n_w1;
  if (i < n_w2) { sc[OFF_W2R + i] = to_tf32(w2[i]); }
}

// ---------------------------------------------------------------------------
// Small kernels
// ---------------------------------------------------------------------------
__global__ void copy_round_k(float* dst, const float* src, long long n) {
  long long i = (long long)blockIdx.x * blockDim.x + threadIdx.x;
  if (i < n) dst[i] = to_tf32(src[i]);
}

__global__ void gather4_k(float* t4, const float* x) {
  long long idx = (long long)blockIdx.x * blockDim.x + threadIdx.x;
  long long tot = N_ROWS4 * D;
  if (idx >= tot) return;
  int d = (int)(idx % D);
  long long r = idx / D;
  int i = (int)(r % NP);
  int b = (int)((r / NP) % B);
  int j = (int)(r / ((long long)NP * B));
  if (i >= c_segN[j]) return;
  int si = (i < c_segP1[j]) ? c_segST[j] + i : i - c_segP1[j];
  t4[idx] = x[((long long)b * S + si) * D + d];
}

__device__ __forceinline__ float seg_cnt(int i) {
  float c = 0.f;
  c += (i < 460);
  c += (i >= 256 && i < 665);
  c += (i >= 460 && i < 870);
  c += (i >= 665);
  c += (i < 51);
  return c;
}

__global__ void combine_k(float* x, const float* o4) {
  long long idx = (long long)blockIdx.x * blockDim.x + threadIdx.x;
  if (idx >= NX) return;
  int d = (int)(idx % D);
  long long r = idx / D;
  int i = (int)(r % S);
  int b = (int)(r / S);
  float s = 0.f;
  if (i < 460) s += o4[(((0 * B + b) * (long long)NP + i) * D) + d];
  if (i >= 256 && i < 665)
    s += o4[(((1 * B + b) * (long long)NP + (i - 256)) * D) + d];
  if (i >= 460 && i < 870)
    s += o4[(((2 * B + b) * (long long)NP + (i - 460)) * D) + d];
  if (i >= 665) s += o4[(((3 * B + b) * (long long)NP + (i - 665)) * D) + d];
  if (i < 51) s += o4[(((3 * B + b) * (long long)NP + (359 + i)) * D) + d];
  x[idx] = to_tf32(s / seg_cnt(i));
}

__global__ void softmaxE_k(float* r, int rows) {
  int i = blockIdx.x * blockDim.x + threadIdx.x;
  if (i >= rows) return;
  float* p = r + (long long)i * E;
  float m = -1e30f;
  for (int e = 0; e < E; e++) m = fmaxf(m, p[e]);
  float s = 0.f;
  for (int e = 0; e < E; e++) {
    float v = __expf(p[e] - m);
    p[e] = v;
    s += v;
  }
  float inv = 1.f / s;
  for (int e = 0; e < E; e++) p[e] *= inv;
}

__device__ __forceinline__ void softmax_row_body(float* row, int n) {
  __shared__ float red[32];
  __shared__ float bcast;
  int tid = threadIdx.x;
  int nw = blockDim.x >> 5;

  float m = -1e30f;
  for (int j = tid; j < n; j += blockDim.x) m = fmaxf(m, row[j]);
  for (int o = 16; o; o >>= 1) m = fmaxf(m, __shfl_xor_sync(0xffffffffu, m, o));
  if ((tid & 31) == 0) red[tid >> 5] = m;
  __syncthreads();
  if (tid < 32) {
    float v = (tid < nw) ? red[tid] : -1e30f;
    for (int o = 16; o; o >>= 1) v = fmaxf(v, __shfl_xor_sync(0xffffffffu, v, o));
    if (tid == 0) bcast = v;
  }
  __syncthreads();
  m = bcast;

  float sum = 0.f;
  for (int j = tid; j < n; j += blockDim.x) {
    float e = __expf(row[j] - m);
    row[j] = e;
    sum += e;
  }
  for (int o = 16; o; o >>= 1) sum += __shfl_xor_sync(0xffffffffu, sum, o);
  if ((tid & 31) == 0) red[tid >> 5] = sum;
  __syncthreads();
  if (tid < 32) {
    float v = (tid < nw) ? red[tid] : 0.f;
    for (int o = 16; o; o >>= 1) v += __shfl_xor_sync(0xffffffffu, v, o);
    if (tid == 0) bcast = v;
  }
  __syncthreads();
  float inv = 1.f / bcast;
  for (int j = tid; j < n; j += blockDim.x) row[j] = to_tf32(row[j] * inv);
}

__global__ void softmax_rows_k(float* s, int n, int ld) {
  float* row = s + (long long)blockIdx.y * n * ld + (long long)blockIdx.x * ld;
  softmax_row_body(row, n);
}

__global__ void softmax_rows4_k(float* s) {
  int z = blockIdx.y;
  int seg = z / ZS;
  int n = c_segN[seg];
  int row = blockIdx.x;
  if (row >= n) return;
  float* rp = s + (long long)z * NP * NP + (long long)row * NP;
  softmax_row_body(rp, n);
}

template <bool CVT, int SEGROWS>
__global__ void add_ln_k(const float* x, const float* r, const float* g,
                         const float* b, float* out) {
  long long base = (long long)blockIdx.x * D;
  if (SEGROWS > 0) {
    int seg = blockIdx.x / SEGROWS;
    g += (long long)seg * D;
    b += (long long)seg * D;
  }
  __shared__ float buf[D];
  __shared__ float redA[32], redB[32];
  __shared__ float sh_m, sh_inv;
  int tid = threadIdx.x;
  int nw = blockDim.x >> 5;

  float s = 0.f, s2 = 0.f;
  for (int d = tid; d < D; d += blockDim.x) {
    float v = x[base + d] + r[base + d];
    buf[d] = v;
    s += v;
    s2 += v * v;
  }
  for (int o = 16; o; o >>= 1) {
    s += __shfl_xor_sync(0xffffffffu, s, o);
    s2 += __shfl_xor_sync(0xffffffffu, s2, o);
  }
  if ((tid & 31) == 0) { redA[tid >> 5] = s; redB[tid >> 5] = s2; }
  __syncthreads();
  if (tid < 32) {
    float a2 = (tid < nw) ? redA[tid] : 0.f;
    float b2 = (tid < nw) ? redB[tid] : 0.f;
    for (int o = 16; o; o >>= 1) {
      a2 += __shfl_xor_sync(0xffffffffu, a2, o);
      b2 += __shfl_xor_sync(0xffffffffu, b2, o);
    }
    if (tid == 0) {
      float mean = a2 / D;
      float var = b2 / D - mean * mean;
      sh_m = mean;
      sh_inv = rsqrtf(var + 1e-5f);
    }
  }
  __syncthreads();
  float mean = sh_m, inv = sh_inv;
  for (int d = tid; d < D; d += blockDim.x) {
    float v = (buf[d] - mean) * inv * g[d] + b[d];
    out[base + d] = CVT ? to_tf32(v) : v;
  }
}

// ---------------------------------------------------------------------------
// Host-side driver
// ---------------------------------------------------------------------------
static inline int cdiv(int a, int b) { return (a + b - 1) / b; }

struct Wts {
  const float *ew, *eb, *rw, *rb, *ow, *ob, *l1g, *l1b, *w1, *b1, *w2, *b2,
      *l2g, *l2b;
};

constexpr int SMEM_128x64_T0 = 4 * (128 * 20 + 16 * 68) * 4;     // 58368
constexpr int SMEM_128x128_T1 = 4 * (128 * 20 + 128 * 20) * 4;   // 81920
constexpr int SMEM_128x128_T0 = 4 * (128 * 20 + 16 * 132) * 4;   // 74752

// -------------------- full-sequence block (layers 0 and 13) ----------------
static void run_block(float* sc, const float* t, float* out, int layer, int n,
                      const Wts& w) {
  const int M = B * n;
  const int n4 = (n + 3) & ~3;
  float* rout = sc + OFF_ROUT;
  float* qkv = sc + OFF_QKV;
  float* sco = sc + OFF_SC;
  float* y = sc + OFF_Y;
  float* a = sc + OFF_A;
  float* x1 = sc + OFF_X1;
  float* h = sc + OFF_H;
  const float* ewp = sc + OFF_EWP + (long long)layer * D * EN;
  const float* owr = sc + OFF_OWR + (long long)layer * D * D;
  const float* w1r = sc + OFF_W1R + (long long)layer * D * F;
  const float* w2r = sc + OFF_W2R + (long long)layer * F * D;

  GemmP p;
  auto reset = [&]() {
    p = GemmP{};
    p.aDiv = p.bDiv = p.cDiv = p.biasDiv = 1;
    p.scale = 1.f;
  };

  reset();
  p.A = t; p.Bm = w.rw + (long long)layer * D * E;
  p.bias = w.rb + (long long)layer * E; p.C = rout;
  p.M = M; p.N = E; p.K = D; p.lda = D; p.ldb = E; p.ldc = E;
  sgemm2_k<64, 64, 16, 4, 4><<<dim3(1, cdiv(M, 64), 1), 256>>>(p);
  softmaxE_k<<<cdiv(M, 256), 256>>>(rout, M);

  // qkv wide-N: [M, EN] = t @ ewp[layer] + eb, scattered to Q/K/V split
  reset();
  p.A = t; p.lda = D;
  p.Bm = ewp; p.ldb = EN;
  p.bias = w.eb + (long long)layer * E * TH;
  p.C = qkv; p.ldc = HD_P;
  p.splitStride = (long long)n * HD_P;
  p.routN = n;
  p.M = M; p.N = EN; p.K = D;
  tmma_k<128, 128, 64, 32, 0, 6>
      <<<dim3(cdiv(EN, 128), cdiv(M, 128), 1), 256, SMEM_128x128_T0>>>(p);

  reset();
  p.A = qkv; p.lda = HD_P; p.as1 = 3LL * n * HD_P;
  p.Bm = qkv + (long long)n * HD_P; p.ldb = HD_P; p.bs1 = 3LL * n * HD_P;
  p.C = sco; p.ldc = n4; p.cs1 = (long long)n * n4;
  p.M = n; p.N = n; p.K = HD;
  p.scale = 0.14142135623730950488f;
  tmma_k<128, 128, 64, 32, 1, 2>
      <<<dim3(cdiv(n, 128), cdiv(n, 128), B * E), 256, SMEM_128x128_T1>>>(p);

  softmax_rows_k<<<dim3(n, B * E), 256>>>(sco, n, n4);

  reset();
  p.A = sco; p.lda = n4; p.as1 = (long long)n * n4;
  p.Bm = qkv + 2LL * n * HD_P; p.ldb = HD_P; p.bs1 = 3LL * n * HD_P;
  p.C = y; p.ldc = D; p.cDiv = E; p.cs1 = (long long)n * D; p.cs2 = HD;
  p.M = n; p.N = HD; p.K = n;
  p.rout = rout; p.routN = n;
  tmma_k<128, 64, 32, 32, 0, 3>
      <<<dim3(1, cdiv(n, 128), B * E), 256, SMEM_128x64_T0>>>(p);

  reset();
  p.A = y; p.lda = D;
  p.Bm = owr; p.ldb = D;
  p.bias = w.ob + (long long)layer * D;
  p.C = a; p.ldc = D;
  p.M = M; p.N = D; p.K = D;
  tmma_k<128, 128, 64, 32, 0, 0>
      <<<dim3(cdiv(D, 128), cdiv(M, 128), 1), 256, SMEM_128x128_T0>>>(p);

  add_ln_k<true, 0><<<M, 256>>>(t, a, w.l1g + (long long)layer * D,
                                w.l1b + (long long)layer * D, x1);

  reset();
  p.A = x1; p.lda = D;
  p.Bm = w1r; p.ldb = F;
  p.bias = w.b1 + (long long)layer * F;
  p.C = h; p.ldc = F;
  p.M = M; p.N = F; p.K = D;
  tmma_k<128, 128, 64, 32, 0, 1>
      <<<dim3(cdiv(F, 128), cdiv(M, 128), 1), 256, SMEM_128x128_T0>>>(p);

  reset();
  p.A = h; p.lda = F;
  p.Bm = w2r; p.ldb = D;
  p.bias = w.b2 + (long long)layer * D;
  p.C = y; p.ldc = D;
  p.M = M; p.N = D; p.K = F;
  tmma_k<128, 128, 64, 32, 0, 0>
      <<<dim3(cdiv(D, 128), cdiv(M, 128), 1), 256, SMEM_128x128_T0>>>(p);

  if (layer == L - 1)
    add_ln_k<false, 0><<<M, 256>>>(x1, y, w.l2g + (long long)layer * D,
                                   w.l2b + (long long)layer * D, out);
  else
    add_ln_k<true, 0><<<M, 256>>>(x1, y, w.l2g + (long long)layer * D,
                                  w.l2b + (long long)layer * D, out);
}

// -------------------- mega-batched 4-segment cycle --------------------------
static void run_segs(float* sc, int cyc, const Wts& w) {
  const int layerBase = 1 + 4 * cyc;
  const int MROWS = B * NP;          // 920 rows per segment
  const int NR4 = 4 * MROWS;         // 3680 rows total
  float* t4 = sc + OFF_T4;
  float* r4 = sc + OFF_R4;
  float* qkv4 = sc + OFF_QKV4;
  float* sco4 = sc + OFF_SC;
  float* y4 = sc + OFF_Y4;
  float* a4 = sc + OFF_A4;
  float* x14 = sc + OFF_X14;
  float* h4 = sc + OFF_H4;
  float* o4 = sc + OFF_O4;

  gather4_k<<<(int)((N_ROWS4 * D + 255) / 256), 256>>>(t4, sc + OFF_X);

  GemmP p;
  auto reset = [&]() {
    p = GemmP{};
    p.aDiv = p.bDiv = p.cDiv = p.biasDiv = 1;
    p.scale = 1.f;
  };

  // routing (z = 4 segments)
  reset();
  p.A = t4; p.lda = D; p.as1 = (long long)MROWS * D;
  p.Bm = w.rw + (long long)layerBase * D * E; p.ldb = E; p.bs1 = (long long)D * E;
  p.bias = w.rb + (long long)layerBase * E; p.biasS = E;
  p.C = r4; p.ldc = E; p.cs1 = (long long)MROWS * E;
  p.M = MROWS; p.N = E; p.K = D;
  sgemm2_k<64, 64, 16, 4, 4><<<dim3(1, cdiv(MROWS, 64), 4), 256>>>(p);
  softmaxE_k<<<cdiv(NR4, 256), 256>>>(r4, NR4);

  // qkv wide-N (z = 4 segments); garbage pad-rows write to never-read slots
  reset();
  p.A = t4; p.lda = D; p.as1 = (long long)MROWS * D;
  p.Bm = sc + OFF_EWP + (long long)layerBase * D * EN; p.ldb = EN;
  p.bias = w.eb + (long long)layerBase * E * TH;
  p.C = qkv4; p.ldc = HD_P; p.cs1 = (long long)ZS * 3 * NP * HD_P;
  p.splitStride = (long long)NP * HD_P;
  p.routN = NP;
  p.M = MROWS; p.N = EN; p.K = D;
  p.zSeg = 1; p.bSeg = (long long)D * EN; p.biasSeg = (long long)E * TH;
  tmma_k<128, 128, 64, 32, 0, 6>
      <<<dim3(cdiv(EN, 128), cdiv(MROWS, 128), 4), 256, SMEM_128x128_T0>>>(p);

  // scores (z = 160)
  reset();
  p.A = qkv4; p.lda = HD_P; p.as1 = 3LL * NP * HD_P;
  p.Bm = qkv4 + (long long)NP * HD_P; p.ldb = HD_P; p.bs1 = 3LL * NP * HD_P;
  p.C = sco4; p.ldc = NP; p.cs1 = (long long)NP * NP;
  p.K = HD;
  p.scale = 0.14142135623730950488f;
  p.zSeg = ZS; p.segFlags = 1 | 2;
  tmma_k<128, 128, 64, 32, 1, 2>
      <<<dim3(cdiv(NP, 128), cdiv(NP, 128), 4 * ZS), 256, SMEM_128x128_T1>>>(p);

  softmax_rows4_k<<<dim3(NP, 4 * ZS), 256>>>(sco4);

  // AV (z = 160)
  reset();
  p.A = sco4; p.lda = NP; p.as1 = (long long)NP * NP;
  p.Bm = qkv4 + 2LL * NP * HD_P; p.ldb = HD_P; p.bs1 = 3LL * NP * HD_P;
  p.C = y4; p.ldc = D; p.cDiv = E; p.cs1 = (long long)NP * D; p.cs2 = HD;
  p.N = HD;
  p.rout = r4; p.routN = NP;
  p.zSeg = ZS; p.segFlags = 1 | 4;
  tmma_k<128, 64, 32, 32, 0, 3>
      <<<dim3(1, cdiv(NP, 128), 4 * ZS), 256, SMEM_128x64_T0>>>(p);

  // out projection (z = 4)
  reset();
  p.A = y4; p.lda = D; p.as1 = (long long)MROWS * D;
  p.Bm = sc + OFF_OWR + (long long)layerBase * D * D; p.ldb = D;
  p.bias = w.ob + (long long)layerBase * D;
  p.C = a4; p.ldc = D; p.cs1 = (long long)MROWS * D;
  p.M = MROWS; p.N = D; p.K = D;
  p.zSeg = 1; p.bSeg = (long long)D * D; p.biasSeg = D;
  tmma_k<128, 128, 64, 32, 0, 0>
      <<<dim3(cdiv(D, 128), cdiv(MROWS, 128), 4), 256, SMEM_128x128_T0>>>(p);

  add_ln_k<true, B * NP><<<NR4, 256>>>(
      t4, a4, w.l1g + (long long)layerBase * D, w.l1b + (long long)layerBase * D,
      x14);

  // FF1 (z = 4)
  reset();
  p.A = x14; p.lda = D; p.as1 = (long long)MROWS * D;
  p.Bm = sc + OFF_W1R + (long long)layerBase * D * F; p.ldb = F;
  p.bias = w.b1 + (long long)layerBase * F;
  p.C = h4; p.ldc = F; p.cs1 = (long long)MROWS * F;
  p.M = MROWS; p.N = F; p.K = D;
  p.zSeg = 1; p.bSeg = (long long)D * F; p.biasSeg = F;
  tmma_k<128, 128, 64, 32, 0, 1>
      <<<dim3(cdiv(F, 128), cdiv(MROWS, 128), 4), 256, SMEM_128x128_T0>>>(p);

  // FF2 (z = 4) -> y4 (free after out projection)
  reset();
  p.A = h4; p.lda = F; p.as1 = (long long)MROWS * F;
  p.Bm = sc + OFF_W2R + (long long)layerBase * F * D; p.ldb = D;
  p.bias = w.b2 + (long long)layerBase * D;
  p.C = y4; p.ldc = D; p.cs1 = (long long)MROWS * D;
  p.M = MROWS; p.N = D; p.K = F;
  p.zSeg = 1; p.bSeg = (long long)F * D; p.biasSeg = D;
  tmma_k<128, 128, 64, 32, 0, 0>
      <<<dim3(cdiv(D, 128), cdiv(MROWS, 128), 4), 256, SMEM_128x128_T0>>>(p);

  add_ln_k<true, B * NP><<<NR4, 256>>>(
      x14, y4, w.l2g + (long long)layerBase * D,
      w.l2b + (long long)layerBase * D, o4);

  combine_k<<<cdiv((int)NX, 256), 256>>>(sc + OFF_X, o4);
}

extern "C" void kernel_launch(void* const* d_in, const int* in_sizes, int n_in,
                              void* d_out, int out_size) {
  (void)in_sizes; (void)n_in; (void)out_size;
  float* sc = nullptr;
  cudaGetSymbolAddress((void**)&sc, g_scratch);

  cudaFuncSetAttribute((const void*)tmma_k<128, 64, 32, 32, 0, 3>,
                       cudaFuncAttributeMaxDynamicSharedMemorySize,
                       SMEM_128x64_T0);
  cudaFuncSetAttribute((const void*)tmma_k<128, 128, 64, 32, 1, 2>,
                       cudaFuncAttributeMaxDynamicSharedMemorySize,
                       SMEM_128x128_T1);
  cudaFuncSetAttribute((const void*)tmma_k<128, 128, 64, 32, 0, 0>,
                       cudaFuncAttributeMaxDynamicSharedMemorySize,
                       SMEM_128x128_T0);
  cudaFuncSetAttribute((const void*)tmma_k<128, 128, 64, 32, 0, 1>,
                       cudaFuncAttributeMaxDynamicSharedMemorySize,
                       SMEM_128x128_T0);
  cudaFuncSetAttribute((const void*)tmma_k<128, 128, 64, 32, 0, 6>,
                       cudaFuncAttributeMaxDynamicSharedMemorySize,
                       SMEM_128x128_T0);

  const float* x_in = (const float*)d_in[0];
  Wts w;
  w.ew = (const float*)d_in[1];  w.eb = (const float*)d_in[2];
  w.rw = (const float*)d_in[3];  w.rb = (const float*)d_in[4];
  w.ow = (const float*)d_in[5];  w.ob = (const float*)d_in[6];
  w.l1g = (const float*)d_in[7]; w.l1b = (const float*)d_in[8];
  w.w1 = (const float*)d_in[9];  w.b1 = (const float*)d_in[10];
  w.w2 = (const float*)d_in[11]; w.b2 = (const float*)d_in[12];
  w.l2g = (const float*)d_in[13]; w.l2b = (const float*)d_in[14];

  {
    const long long tot = (long long)L * D * EN + (long long)L * D * D +
                          (long long)L * D * F + (long long)L * F * D;
    prep_k<<<(int)((tot + 255) / 256), 256>>>(sc, w.ew, w.ow, w.w1, w.w2);
  }

  copy_round_k<<<cdiv((int)NX, 256), 256>>>(sc + OFF_X, x_in, NX);

  run_block(sc, sc + OFF_X, sc + OFF_X, 0, S, w);

  for (int c = 0; c < CYCLES; c++) run_segs(sc, c, w);

  run_block(sc, sc + OFF_X, (float*)d_out, 13, S, w);
}

// round 14
// speedup vs baseline: 1.7890x; 1.0479x over previous
#include <cuda_runtime.h>
#include <math.h>
#include <stdint.h>

// ---------------------------------------------------------------------------
// SLAMv2: 14-layer MoE-attention transformer, segmented schedule.
// Round 14: R13 + register-cached row softmax (1 read + 1 write per element
// instead of 3R+2W; identical op order -> bit-identical numerics).
// ---------------------------------------------------------------------------

namespace {
constexpr int B = 2, S = 1024, D = 1000, E = 20, HD = 50, TH = 3 * HD;
constexpr int HD_P = 52;
constexpr int EN = E * TH;    // 3000 — wide qkv N
constexpr int F = 2048, CYCLES = 3, L = 14;
constexpr int NP = 460;       // padded segment length
constexpr int ZS = B * E;     // 40 z per segment

constexpr long long NX = (long long)B * S * D;
constexpr long long OFF_X    = 0;
constexpr long long OFF_XNEW = OFF_X + NX;
constexpr long long OFF_T    = OFF_XNEW + NX;
constexpr long long OFF_X1   = OFF_T + NX;
constexpr long long OFF_Y    = OFF_X1 + NX;
constexpr long long OFF_A    = OFF_Y + NX;
constexpr long long OFF_ROUT = OFF_A + NX;
constexpr long long OFF_H    = OFF_ROUT + (long long)B * S * E;
constexpr long long OFF_QKV  = OFF_H + (long long)B * S * F;
constexpr long long OFF_SC   = OFF_QKV + (long long)B * E * 3 * S * HD_P;
constexpr long long OFF_EWP  = OFF_SC + (long long)B * E * S * S;  // [L][D][EN]
constexpr long long OFF_OWR  = OFF_EWP + (long long)L * D * EN;
constexpr long long OFF_W1R  = OFF_OWR + (long long)L * D * D;
constexpr long long OFF_W2R  = OFF_W1R + (long long)L * D * F;
constexpr long long N_ROWS4  = 4LL * B * NP;            // 3680 rows
constexpr long long OFF_T4   = OFF_W2R + (long long)L * F * D;
constexpr long long OFF_R4   = OFF_T4 + N_ROWS4 * D;
constexpr long long OFF_QKV4 = OFF_R4 + N_ROWS4 * E;
constexpr long long OFF_Y4   = OFF_QKV4 + 160LL * 3 * NP * HD_P;
constexpr long long OFF_A4   = OFF_Y4 + N_ROWS4 * D;
constexpr long long OFF_X14  = OFF_A4 + N_ROWS4 * D;
constexpr long long OFF_H4   = OFF_X14 + N_ROWS4 * D;
constexpr long long OFF_O4   = OFF_H4 + N_ROWS4 * F;
constexpr long long TOTAL    = OFF_O4 + N_ROWS4 * D;
// sco4 (160 * NP * NP = 33.86M) reuses OFF_SC region (41.9M) — checked.
}  // namespace

__device__ float g_scratch[TOTAL];
__device__ const int c_segN[4]  = {460, 409, 410, 410};
__device__ const int c_segST[4] = {0, 256, 460, 665};
__device__ const int c_segP1[4] = {460, 409, 410, 359};

struct GemmP {
  const float* A; const float* Bm; const float* bias; float* C;
  int M, N, K, lda, ldb, ldc;
  int aDiv; long long as1, as2;
  int bDiv; long long bs1, bs2;
  int cDiv; long long cs1, cs2;
  int biasDiv; long long biasS;
  long long splitStride;
  float scale;
  const float* rout; int routN;
  int zSeg;            // z's per segment (0 = no segment batching)
  long long bSeg;      // extra B offset per segment (layer stride)
  long long biasSeg;   // extra bias offset per segment
  int segFlags;        // 1: M=segN, 2: N=segN, 4: K=segN
};

__device__ __forceinline__ float to_tf32(float x) {
  asm("cvt.rna.tf32.f32 %0, %0;" : "+f"(x));
  return x;
}

__device__ __forceinline__ void cp16(uint32_t dst, const float* src, int bytes) {
  asm volatile("cp.async.cg.shared.global [%0], [%1], 16, %2;\n"
               :: "r"(dst), "l"(src), "r"(bytes));
}
__device__ __forceinline__ void cp_commit() {
  asm volatile("cp.async.commit_group;\n");
}
template <int N>
__device__ __forceinline__ void cp_wait() {
  asm volatile("cp.async.wait_group %0;\n" :: "n"(N));
}

// ---------------------------------------------------------------------------
// TF32 tensor-core GEMM; cp.async 4-stage ring; k-slot remap fragments.
// EPI: 0 +bias; 1 +bias,GELU(round); 2 *scale; 3 *routing(round);
//      4 +bias,split-QKV(round); 6 +bias, wide-N qkv scatter (round).
// ---------------------------------------------------------------------------
template <int BM, int BN, int WM, int WN, int BTRANS, int EPI>
__global__ __launch_bounds__(256) void tmma_k(GemmP p) {
  constexpr int BK = 16, ST = 4;
  constexpr int SKA = BK + 4;
  constexpr int LDB0 = BN + 4;
  constexpr int ASZ = BM * SKA;
  constexpr int BSZ = BTRANS ? BN * SKA : BK * LDB0;
  constexpr int NWN = BN / WN;
  constexpr int MT = WM / 16, NT = WN / 8;
  constexpr int ACH = BM * 4;
  constexpr int AV_ = (ACH + 255) / 256;
  constexpr int BV_ = BN / 64;
  static_assert((BM / WM) * (BN / WN) == 8, "need 8 warps");

  extern __shared__ float sm[];
  float* As = sm;
  float* Bs = sm + ST * ASZ;
  const uint32_t a_u32 = (uint32_t)__cvta_generic_to_shared(As);
  const uint32_t b_u32 = (uint32_t)__cvta_generic_to_shared(Bs);

  const int z = blockIdx.z;
  int seg = 0;
  if (p.zSeg) seg = z / p.zSeg;
  const int Mloc = (p.segFlags & 1) ? c_segN[seg] : p.M;
  const int Nloc = (p.segFlags & 2) ? c_segN[seg] : p.N;
  const int Kloc = (p.segFlags & 4) ? c_segN[seg] : p.K;

  const float* Ab =
      p.A + (long long)(z / p.aDiv) * p.as1 + (long long)(z % p.aDiv) * p.as2;
  const float* Bb =
      p.Bm + (long long)(z / p.bDiv) * p.bs1 + (long long)(z % p.bDiv) * p.bs2 +
      (long long)seg * p.bSeg;
  float* Cb =
      p.C + (long long)(z / p.cDiv) * p.cs1 + (long long)(z % p.cDiv) * p.cs2;

  const int m0 = blockIdx.y * BM, n0 = blockIdx.x * BN;
  const int tid = threadIdx.x;
  const int warp = tid >> 5, lane = tid & 31;
  const int g = lane >> 2, t = lane & 3;
  const int wm = (warp / NWN) * WM, wn = (warp % NWN) * WN;

  auto issue = [&](int it) {
    const int s = it % ST;
    const int kb = it * BK;
#pragma unroll
    for (int v = 0; v < AV_; v++) {
      int idx = tid + v * 256;
      if ((ACH % 256) != 0 && idx >= ACH) break;
      int m = idx >> 2, c4 = (idx & 3) * 4;
      int gm = m0 + m, gk = kb + c4;
      int by = 0;
      if (gm < Mloc) {
        int rem = (Kloc - gk) * 4;
        by = rem > 16 ? 16 : (rem > 0 ? rem : 0);
      }
      const float* src = Ab + (long long)(by ? gm : 0) * p.lda + (by ? gk : 0);
      cp16(a_u32 + (uint32_t)(s * ASZ + m * SKA + c4) * 4u, src, by);
    }
    if (BTRANS == 0) {
#pragma unroll
      for (int v = 0; v < BV_; v++) {
        int idx = tid + v * 256;
        int kk = idx / (BN / 4), n4 = (idx % (BN / 4)) * 4;
        int gk = kb + kk, gn = n0 + n4;
        int by = 0;
        if (gk < Kloc) {
          int rem = (Nloc - gn) * 4;
          by = rem > 16 ? 16 : (rem > 0 ? rem : 0);
        }
        const float* src = Bb + (long long)(by ? gk : 0) * p.ldb + (by ? gn : 0);
        cp16(b_u32 + (uint32_t)(s * BSZ + kk * LDB0 + n4) * 4u, src, by);
      }
    } else {
#pragma unroll
      for (int v = 0; v < BV_; v++) {
        int idx = tid + v * 256;
        int n = idx >> 2, c4 = (idx & 3) * 4;
        int gn = n0 + n, gk = kb + c4;
        int by = 0;
        if (gn < Nloc) {
          int rem = (Kloc - gk) * 4;
          by = rem > 16 ? 16 : (rem > 0 ? rem : 0);
        }
        const float* src = Bb + (long long)(by ? gn : 0) * p.ldb + (by ? gk : 0);
        cp16(b_u32 + (uint32_t)(s * BSZ + n * SKA + c4) * 4u, src, by);
      }
    }
  };

  float c[MT][NT][4];
#pragma unroll
  for (int i = 0; i < MT; i++)
#pragma unroll
    for (int j = 0; j < NT; j++)
#pragma unroll
      for (int r = 0; r < 4; r++) c[i][j][r] = 0.f;

  auto comp = [&](int s) {
    const float* Asb = As + s * ASZ;
    const float* Bsb = Bs + s * BSZ;
#pragma unroll
    for (int kq = 0; kq < 2; kq++) {
      const int ko = kq * 8 + 2 * t;
      float2 af[MT][2];
#pragma unroll
      for (int mt = 0; mt < MT; mt++) {
        int r0 = wm + mt * 16 + g;
        af[mt][0] = *reinterpret_cast<const float2*>(&Asb[r0 * SKA + ko]);
        af[mt][1] = *reinterpret_cast<const float2*>(&Asb[(r0 + 8) * SKA + ko]);
      }
      float bx[NT], by_[NT];
#pragma unroll
      for (int nt = 0; nt < NT; nt++) {
        int col = wn + nt * 8 + g;
        if (BTRANS == 1) {
          float2 bb = *reinterpret_cast<const float2*>(&Bsb[col * SKA + ko]);
          bx[nt] = bb.x;
          by_[nt] = bb.y;
        } else {
          bx[nt] = Bsb[ko * LDB0 + col];
          by_[nt] = Bsb[(ko + 1) * LDB0 + col];
        }
      }
#pragma unroll
      for (int mt = 0; mt < MT; mt++)
#pragma unroll
        for (int nt = 0; nt < NT; nt++) {
          asm volatile(
              "mma.sync.aligned.m16n8k8.row.col.f32.tf32.tf32.f32 "
              "{%0,%1,%2,%3}, {%4,%5,%6,%7}, {%8,%9}, {%0,%1,%2,%3};"
              : "+f"(c[mt][nt][0]), "+f"(c[mt][nt][1]), "+f"(c[mt][nt][2]),
                "+f"(c[mt][nt][3])
              : "r"(__float_as_uint(af[mt][0].x)),
                "r"(__float_as_uint(af[mt][1].x)),
                "r"(__float_as_uint(af[mt][0].y)),
                "r"(__float_as_uint(af[mt][1].y)),
                "r"(__float_as_uint(bx[nt])), "r"(__float_as_uint(by_[nt])));
        }
    }
  };

  const int iters = (Kloc + BK - 1) / BK;
#pragma unroll
  for (int s = 0; s < ST - 1; s++) {
    if (s < iters) issue(s);
    cp_commit();
  }
  for (int it = 0; it < iters; it++) {
    cp_wait<ST - 2>();
    __syncthreads();
    if (it + ST - 1 < iters) issue(it + ST - 1);
    cp_commit();
    comp(it % ST);
  }

  const float* biasb = nullptr;
  if ((EPI == 0 || EPI == 1 || EPI == 4 || EPI == 6) && p.bias)
    biasb = p.bias + (long long)(z % p.biasDiv) * p.biasS +
            (long long)seg * p.biasSeg;

#pragma unroll
  for (int mt = 0; mt < MT; mt++)
#pragma unroll
    for (int nt = 0; nt < NT; nt++)
#pragma unroll
      for (int r = 0; r < 4; r++) {
        int row = m0 + wm + mt * 16 + g + ((r >> 1) ? 8 : 0);
        int col = n0 + wn + nt * 8 + 2 * t + (r & 1);
        if (row >= Mloc || col >= Nloc) continue;
        float v = c[mt][nt][r];
        if (biasb) v += biasb[col];
        if (EPI == 1) {
          v = 0.5f * v * (1.f + erff(v * 0.70710678118654752f));
          v = to_tf32(v);
        }
        if (EPI == 2) v *= p.scale;
        if (EPI == 3) {
          v *= p.rout[((long long)(z / p.cDiv) * p.routN + row) * E +
                      (z % p.cDiv)];
          v = to_tf32(v);
        }
        if (EPI == 4) {
          v = to_tf32(v);
          int h = col / HD, s2 = col - h * HD;
          Cb[(long long)h * p.splitStride + (long long)row * p.ldc + s2] = v;
        } else if (EPI == 6) {
          // wide-N qkv scatter: col -> (e, h, s2); row -> (b, i).
          v = to_tf32(v);
          int e = col / TH;
          int th = col - e * TH;
          int h = th / HD;
          int s2 = th - h * HD;
          int b = row / p.routN;
          int i = row - b * p.routN;
          Cb[(long long)(b * E + e) * 3 * p.splitStride +
             (long long)h * p.splitStride + (long long)i * p.ldc + s2] = v;
        } else {
          Cb[(long long)row * p.ldc + col] = v;
        }
      }
}

// ---------------------------------------------------------------------------
// SIMT SGEMM (routing GEMM, N=20; fp32). z-batched via as1/bs1/cs1/biasS.
// ---------------------------------------------------------------------------
template <int BM, int BN, int BK, int TM, int TN>
__global__ __launch_bounds__((BM / TM) * (BN / TN)) void sgemm2_k(GemmP p) {
  constexpr int NTHR = (BM / TM) * (BN / TN);
  constexpr int TX = BN / TN;
  __shared__ float As[BK][BM + 4];
  __shared__ float Bs[BK][BN + 4];

  const int z = blockIdx.z;
  const float* Ab = p.A + (long long)z * p.as1;
  const float* Bb = p.Bm + (long long)z * p.bs1;
  float* Cb = p.C + (long long)z * p.cs1;
  const float* bias = p.bias ? p.bias + (long long)z * p.biasS : nullptr;

  const int m0 = blockIdx.y * BM, n0 = blockIdx.x * BN;
  const int tid = threadIdx.x;
  const int tx = tid % TX, ty = tid / TX;

  float acc[TM][TN];
#pragma unroll
  for (int i = 0; i < TM; i++)
#pragma unroll
    for (int j = 0; j < TN; j++) acc[i][j] = 0.f;

  for (int k0 = 0; k0 < p.K; k0 += BK) {
    for (int idx = tid; idx < BM * BK; idx += NTHR) {
      int m = idx / BK, kk = idx % BK;
      int gm = m0 + m, gk = k0 + kk;
      As[kk][m] = (gm < p.M && gk < p.K) ? Ab[(long long)gm * p.lda + gk] : 0.f;
    }
    for (int idx = tid; idx < BK * BN; idx += NTHR) {
      int kk = idx / BN, nn = idx % BN;
      int gk = k0 + kk, gn = n0 + nn;
      Bs[kk][nn] = (gk < p.K && gn < p.N) ? Bb[(long long)gk * p.ldb + gn] : 0.f;
    }
    __syncthreads();
#pragma unroll
    for (int kk = 0; kk < BK; kk++) {
      float a[TM], b[TN];
#pragma unroll
      for (int i = 0; i < TM; i++) a[i] = As[kk][ty * TM + i];
#pragma unroll
      for (int j = 0; j < TN; j++) b[j] = Bs[kk][tx * TN + j];
#pragma unroll
      for (int i = 0; i < TM; i++)
#pragma unroll
        for (int j = 0; j < TN; j++) acc[i][j] += a[i] * b[j];
    }
    __syncthreads();
  }

#pragma unroll
  for (int i = 0; i < TM; i++) {
    int row = m0 + ty * TM + i;
    if (row >= p.M) continue;
#pragma unroll
    for (int j = 0; j < TN; j++) {
      int col = n0 + tx * TN + j;
      if (col >= p.N) continue;
      float v = acc[i][j] + (bias ? bias[col] : 0.f);
      Cb[(long long)row * p.ldc + col] = v;
    }
  }
}

// ---------------------------------------------------------------------------
// One-launch weight prep: ew [L][E][D][TH] -> [L][D][E*TH] (tf32-rounded);
// ow/w1/w2 rounded in place layout.
// ---------------------------------------------------------------------------
__global__ void prep_k(float* sc, const float* ew, const float* ow,
                       const float* w1, const float* w2) {
  const long long n_ewp = (long long)L * D * EN;
  const long long n_ow = (long long)L * D * D;
  const long long n_w1 = (long long)L * D * F;
  const long long n_w2 = (long long)L * F * D;
  long long i = (long long)blockIdx.x * blockDim.x + threadIdx.x;
  if (i < n_ewp) {
    int col = (int)(i % EN);
    long long r = i / EN;
    int d = (int)(r % D);
    int l = (int)(r / D);
    int e = col / TH, th = col - e * TH;
    sc[OFF_EWP + i] =
        to_tf32(ew[(((long long)l * E + e) * D + d) * TH + th]);
    return;
  }
  i -= n_ewp;
  if (i < n_ow) { sc[OFF_OWR + i] = to_tf32(ow[i]); return; }
  i -= n_ow;
  if (i < n_w1) { sc[OFF_W1R + i] = to_tf32(w1[i]); return; }
  i -= n_w1;
  if (i < n_w2) { sc[OFF_W2R + i] = to_tf32(w2[i]); }
}

// ---------------------------------------------------------------------------
// Small kernels
// ---------------------------------------------------------------------------
__global__ void copy_round_k(float* dst, const float* src, long long n) {
  long long i = (long long)blockIdx.x * blockDim.x + threadIdx.x;
  if (i < n) dst[i] = to_tf32(src[i]);
}

__global__ void gather4_k(float* t4, const float* x) {
  long long idx = (long long)blockIdx.x * blockDim.x + threadIdx.x;
  long long tot = N_ROWS4 * D;
  if (idx >= tot) return;
  int d = (int)(idx % D);
  long long r = idx / D;
  int i = (int)(r % NP);
  int b = (int)((r / NP) % B);
  int j = (int)(r / ((long long)NP * B));
  if (i >= c_segN[j]) return;
  int si = (i < c_segP1[j]) ? c_segST[j] + i : i - c_segP1[j];
  t4[idx] = x[((long long)b * S + si) * D + d];
}

__device__ __forceinline__ float seg_cnt(int i) {
  float c = 0.f;
  c += (i < 460);
  c += (i >= 256 && i < 665);
  c += (i >= 460 && i < 870);
  c += (i >= 665);
  c += (i < 51);
  return c;
}

__global__ void combine_k(float* x, const float* o4) {
  long long idx = (long long)blockIdx.x * blockDim.x + threadIdx.x;
  if (idx >= NX) return;
  int d = (int)(idx % D);
  long long r = idx / D;
  int i = (int)(r % S);
  int b = (int)(r / S);
  float s = 0.f;
  if (i < 460) s += o4[(((0 * B + b) * (long long)NP + i) * D) + d];
  if (i >= 256 && i < 665)
    s += o4[(((1 * B + b) * (long long)NP + (i - 256)) * D) + d];
  if (i >= 460 && i < 870)
    s += o4[(((2 * B + b) * (long long)NP + (i - 460)) * D) + d];
  if (i >= 665) s += o4[(((3 * B + b) * (long long)NP + (i - 665)) * D) + d];
  if (i < 51) s += o4[(((3 * B + b) * (long long)NP + (359 + i)) * D) + d];
  x[idx] = to_tf32(s / seg_cnt(i));
}

__global__ void softmaxE_k(float* r, int rows) {
  int i = blockIdx.x * blockDim.x + threadIdx.x;
  if (i >= rows) return;
  float* p = r + (long long)i * E;
  float m = -1e30f;
  for (int e = 0; e < E; e++) m = fmaxf(m, p[e]);
  float s = 0.f;
  for (int e = 0; e < E; e++) {
    float v = __expf(p[e] - m);
    p[e] = v;
    s += v;
  }
  float inv = 1.f / s;
  for (int e = 0; e < E; e++) p[e] *= inv;
}

// Register-cached row softmax: ONE global read + ONE global write per element.
// Per-thread strided assignment, reduction trees, and op order identical to
// the previous version -> bit-identical output. n <= 1024, blockDim == 256.
__device__ __forceinline__ void softmax_row_body(float* row, int n) {
  __shared__ float red[32];
  __shared__ float bcast;
  const int tid = threadIdx.x;
  const int nw = 256 >> 5;

  float v[4];
  const int cnt = (n - tid + 255) / 256;  // elements this thread owns
#pragma unroll
  for (int c = 0; c < 4; c++) {
    int j = tid + c * 256;
    if (c < cnt) v[c] = row[j];
  }

  float m = -1e30f;
#pragma unroll
  for (int c = 0; c < 4; c++)
    if (c < cnt) m = fmaxf(m, v[c]);
  for (int o = 16; o; o >>= 1) m = fmaxf(m, __shfl_xor_sync(0xffffffffu, m, o));
  if ((tid & 31) == 0) red[tid >> 5] = m;
  __syncthreads();
  if (tid < 32) {
    float x = (tid < nw) ? red[tid] : -1e30f;
    for (int o = 16; o; o >>= 1) x = fmaxf(x, __shfl_xor_sync(0xffffffffu, x, o));
    if (tid == 0) bcast = x;
  }
  __syncthreads();
  m = bcast;

  float sum = 0.f;
#pragma unroll
  for (int c = 0; c < 4; c++)
    if (c < cnt) {
      v[c] = __expf(v[c] - m);
      sum += v[c];
    }
  for (int o = 16; o; o >>= 1) sum += __shfl_xor_sync(0xffffffffu, sum, o);
  if ((tid & 31) == 0) red[tid >> 5] = sum;
  __syncthreads();
  if (tid < 32) {
    float x = (tid < nw) ? red[tid] : 0.f;
    for (int o = 16; o; o >>= 1) x += __shfl_xor_sync(0xffffffffu, x, o);
    if (tid == 0) bcast = x;
  }
  __syncthreads();
  const float inv = 1.f / bcast;
#pragma unroll
  for (int c = 0; c < 4; c++) {
    int j = tid + c * 256;
    if (c < cnt) row[j] = to_tf32(v[c] * inv);
  }
}

__global__ void softmax_rows_k(float* s, int n, int ld) {
  float* row = s + (long long)blockIdx.y * n * ld + (long long)blockIdx.x * ld;
  softmax_row_body(row, n);
}

__global__ void softmax_rows4_k(float* s) {
  int z = blockIdx.y;
  int seg = z / ZS;
  int n = c_segN[seg];
  int row = blockIdx.x;
  if (row >= n) return;
  float* rp = s + (long long)z * NP * NP + (long long)row * NP;
  softmax_row_body(rp, n);
}

template <bool CVT, int SEGROWS>
__global__ void add_ln_k(const float* x, const float* r, const float* g,
                         const float* b, float* out) {
  long long base = (long long)blockIdx.x * D;
  if (SEGROWS > 0) {
    int seg = blockIdx.x / SEGROWS;
    g += (long long)seg * D;
    b += (long long)seg * D;
  }
  __shared__ float buf[D];
  __shared__ float redA[32], redB[32];
  __shared__ float sh_m, sh_inv;
  int tid = threadIdx.x;
  int nw = blockDim.x >> 5;

  float s = 0.f, s2 = 0.f;
  for (int d = tid; d < D; d += blockDim.x) {
    float v = x[base + d] + r[base + d];
    buf[d] = v;
    s += v;
    s2 += v * v;
  }
  for (int o = 16; o; o >>= 1) {
    s += __shfl_xor_sync(0xffffffffu, s, o);
    s2 += __shfl_xor_sync(0xffffffffu, s2, o);
  }
  if ((tid & 31) == 0) { redA[tid >> 5] = s; redB[tid >> 5] = s2; }
  __syncthreads();
  if (tid < 32) {
    float a2 = (tid < nw) ? redA[tid] : 0.f;
    float b2 = (tid < nw) ? redB[tid] : 0.f;
    for (int o = 16; o; o >>= 1) {
      a2 += __shfl_xor_sync(0xffffffffu, a2, o);
      b2 += __shfl_xor_sync(0xffffffffu, b2, o);
    }
    if (tid == 0) {
      float mean = a2 / D;
      float var = b2 / D - mean * mean;
      sh_m = mean;
      sh_inv = rsqrtf(var + 1e-5f);
    }
  }
  __syncthreads();
  float mean = sh_m, inv = sh_inv;
  for (int d = tid; d < D; d += blockDim.x) {
    float v = (buf[d] - mean) * inv * g[d] + b[d];
    out[base + d] = CVT ? to_tf32(v) : v;
  }
}

// ---------------------------------------------------------------------------
// Host-side driver
// ---------------------------------------------------------------------------
static inline int cdiv(int a, int b) { return (a + b - 1) / b; }

struct Wts {
  const float *ew, *eb, *rw, *rb, *ow, *ob, *l1g, *l1b, *w1, *b1, *w2, *b2,
      *l2g, *l2b;
};

constexpr int SMEM_128x64_T0 = 4 * (128 * 20 + 16 * 68) * 4;     // 58368
constexpr int SMEM_128x128_T1 = 4 * (128 * 20 + 128 * 20) * 4;   // 81920
constexpr int SMEM_128x128_T0 = 4 * (128 * 20 + 16 * 132) * 4;   // 74752

// -------------------- full-sequence block (layers 0 and 13) ----------------
static void run_block(float* sc, const float* t, float* out, int layer, int n,
                      const Wts& w) {
  const int M = B * n;
  const int n4 = (n + 3) & ~3;
  float* rout = sc + OFF_ROUT;
  float* qkv = sc + OFF_QKV;
  float* sco = sc + OFF_SC;
  float* y = sc + OFF_Y;
  float* a = sc + OFF_A;
  float* x1 = sc + OFF_X1;
  float* h = sc + OFF_H;
  const float* ewp = sc + OFF_EWP + (long long)layer * D * EN;
  const float* owr = sc + OFF_OWR + (long long)layer * D * D;
  const float* w1r = sc + OFF_W1R + (long long)layer * D * F;
  const float* w2r = sc + OFF_W2R + (long long)layer * F * D;

  GemmP p;
  auto reset = [&]() {
    p = GemmP{};
    p.aDiv = p.bDiv = p.cDiv = p.biasDiv = 1;
    p.scale = 1.f;
  };

  reset();
  p.A = t; p.Bm = w.rw + (long long)layer * D * E;
  p.bias = w.rb + (long long)layer * E; p.C = rout;
  p.M = M; p.N = E; p.K = D; p.lda = D; p.ldb = E; p.ldc = E;
  sgemm2_k<64, 64, 16, 4, 4><<<dim3(1, cdiv(M, 64), 1), 256>>>(p);
  softmaxE_k<<<cdiv(M, 256), 256>>>(rout, M);

  // qkv wide-N: [M, EN] = t @ ewp[layer] + eb, scattered to Q/K/V split
  reset();
  p.A = t; p.lda = D;
  p.Bm = ewp; p.ldb = EN;
  p.bias = w.eb + (long long)layer * E * TH;
  p.C = qkv; p.ldc = HD_P;
  p.splitStride = (long long)n * HD_P;
  p.routN = n;
  p.M = M; p.N = EN; p.K = D;
  tmma_k<128, 128, 64, 32, 0, 6>
      <<<dim3(cdiv(EN, 128), cdiv(M, 128), 1), 256, SMEM_128x128_T0>>>(p);

  reset();
  p.A = qkv; p.lda = HD_P; p.as1 = 3LL * n * HD_P;
  p.Bm = qkv + (long long)n * HD_P; p.ldb = HD_P; p.bs1 = 3LL * n * HD_P;
  p.C = sco; p.ldc = n4; p.cs1 = (long long)n * n4;
  p.M = n; p.N = n; p.K = HD;
  p.scale = 0.14142135623730950488f;
  tmma_k<128, 128, 64, 32, 1, 2>
      <<<dim3(cdiv(n, 128), cdiv(n, 128), B * E), 256, SMEM_128x128_T1>>>(p);

  softmax_rows_k<<<dim3(n, B * E), 256>>>(sco, n, n4);

  reset();
  p.A = sco; p.lda = n4; p.as1 = (long long)n * n4;
  p.Bm = qkv + 2LL * n * HD_P; p.ldb = HD_P; p.bs1 = 3LL * n * HD_P;
  p.C = y; p.ldc = D; p.cDiv = E; p.cs1 = (long long)n * D; p.cs2 = HD;
  p.M = n; p.N = HD; p.K = n;
  p.rout = rout; p.routN = n;
  tmma_k<128, 64, 32, 32, 0, 3>
      <<<dim3(1, cdiv(n, 128), B * E), 256, SMEM_128x64_T0>>>(p);

  reset();
  p.A = y; p.lda = D;
  p.Bm = owr; p.ldb = D;
  p.bias = w.ob + (long long)layer * D;
  p.C = a; p.ldc = D;
  p.M = M; p.N = D; p.K = D;
  tmma_k<128, 128, 64, 32, 0, 0>
      <<<dim3(cdiv(D, 128), cdiv(M, 128), 1), 256, SMEM_128x128_T0>>>(p);

  add_ln_k<true, 0><<<M, 256>>>(t, a, w.l1g + (long long)layer * D,
                                w.l1b + (long long)layer * D, x1);

  reset();
  p.A = x1; p.lda = D;
  p.Bm = w1r; p.ldb = F;
  p.bias = w.b1 + (long long)layer * F;
  p.C = h; p.ldc = F;
  p.M = M; p.N = F; p.K = D;
  tmma_k<128, 128, 64, 32, 0, 1>
      <<<dim3(cdiv(F, 128), cdiv(M, 128), 1), 256, SMEM_128x128_T0>>>(p);

  reset();
  p.A = h; p.lda = F;
  p.Bm = w2r; p.ldb = D;
  p.bias = w.b2 + (long long)layer * D;
  p.C = y; p.ldc = D;
  p.M = M; p.N = D; p.K = F;
  tmma_k<128, 128, 64, 32, 0, 0>
      <<<dim3(cdiv(D, 128), cdiv(M, 128), 1), 256, SMEM_128x128_T0>>>(p);

  if (layer == L - 1)
    add_ln_k<false, 0><<<M, 256>>>(x1, y, w.l2g + (long long)layer * D,
                                   w.l2b + (long long)layer * D, out);
  else
    add_ln_k<true, 0><<<M, 256>>>(x1, y, w.l2g + (long long)layer * D,
                                  w.l2b + (long long)layer * D, out);
}

// -------------------- mega-batched 4-segment cycle --------------------------
static void run_segs(float* sc, int cyc, const Wts& w) {
  const int layerBase = 1 + 4 * cyc;
  const int MROWS = B * NP;          // 920 rows per segment
  const int NR4 = 4 * MROWS;         // 3680 rows total
  float* t4 = sc + OFF_T4;
  float* r4 = sc + OFF_R4;
  float* qkv4 = sc + OFF_QKV4;
  float* sco4 = sc + OFF_SC;
  float* y4 = sc + OFF_Y4;
  float* a4 = sc + OFF_A4;
  float* x14 = sc + OFF_X14;
  float* h4 = sc + OFF_H4;
  float* o4 = sc + OFF_O4;

  gather4_k<<<(int)((N_ROWS4 * D + 255) / 256), 256>>>(t4, sc + OFF_X);

  GemmP p;
  auto reset = [&]() {
    p = GemmP{};
    p.aDiv = p.bDiv = p.cDiv = p.biasDiv = 1;
    p.scale = 1.f;
  };

  // routing (z = 4 segments)
  reset();
  p.A = t4; p.lda = D; p.as1 = (long long)MROWS * D;
  p.Bm = w.rw + (long long)layerBase * D * E; p.ldb = E; p.bs1 = (long long)D * E;
  p.bias = w.rb + (long long)layerBase * E; p.biasS = E;
  p.C = r4; p.ldc = E; p.cs1 = (long long)MROWS * E;
  p.M = MROWS; p.N = E; p.K = D;
  sgemm2_k<64, 64, 16, 4, 4><<<dim3(1, cdiv(MROWS, 64), 4), 256>>>(p);
  softmaxE_k<<<cdiv(NR4, 256), 256>>>(r4, NR4);

  // qkv wide-N (z = 4 segments)
  reset();
  p.A = t4; p.lda = D; p.as1 = (long long)MROWS * D;
  p.Bm = sc + OFF_EWP + (long long)layerBase * D * EN; p.ldb = EN;
  p.bias = w.eb + (long long)layerBase * E * TH;
  p.C = qkv4; p.ldc = HD_P; p.cs1 = (long long)ZS * 3 * NP * HD_P;
  p.splitStride = (long long)NP * HD_P;
  p.routN = NP;
  p.M = MROWS; p.N = EN; p.K = D;
  p.zSeg = 1; p.bSeg = (long long)D * EN; p.biasSeg = (long long)E * TH;
  tmma_k<128, 128, 64, 32, 0, 6>
      <<<dim3(cdiv(EN, 128), cdiv(MROWS, 128), 4), 256, SMEM_128x128_T0>>>(p);

  // scores (z = 160)
  reset();
  p.A = qkv4; p.lda = HD_P; p.as1 = 3LL * NP * HD_P;
  p.Bm = qkv4 + (long long)NP * HD_P; p.ldb = HD_P; p.bs1 = 3LL * NP * HD_P;
  p.C = sco4; p.ldc = NP; p.cs1 = (long long)NP * NP;
  p.K = HD;
  p.scale = 0.14142135623730950488f;
  p.zSeg = ZS; p.segFlags = 1 | 2;
  tmma_k<128, 128, 64, 32, 1, 2>
      <<<dim3(cdiv(NP, 128), cdiv(NP, 128), 4 * ZS), 256, SMEM_128x128_T1>>>(p);

  softmax_rows4_k<<<dim3(NP, 4 * ZS), 256>>>(sco4);

  // AV (z = 160)
  reset();
  p.A = sco4; p.lda = NP; p.as1 = (long long)NP * NP;
  p.Bm = qkv4 + 2LL * NP * HD_P; p.ldb = HD_P; p.bs1 = 3LL * NP * HD_P;
  p.C = y4; p.ldc = D; p.cDiv = E; p.cs1 = (long long)NP * D; p.cs2 = HD;
  p.N = HD;
  p.rout = r4; p.routN = NP;
  p.zSeg = ZS; p.segFlags = 1 | 4;
  tmma_k<128, 64, 32, 32, 0, 3>
      <<<dim3(1, cdiv(NP, 128), 4 * ZS), 256, SMEM_128x64_T0>>>(p);

  // out projection (z = 4)
  reset();
  p.A = y4; p.lda = D; p.as1 = (long long)MROWS * D;
  p.Bm = sc + OFF_OWR + (long long)layerBase * D * D; p.ldb = D;
  p.bias = w.ob + (long long)layerBase * D;
  p.C = a4; p.ldc = D; p.cs1 = (long long)MROWS * D;
  p.M = MROWS; p.N = D; p.K = D;
  p.zSeg = 1; p.bSeg = (long long)D * D; p.biasSeg = D;
  tmma_k<128, 128, 64, 32, 0, 0>
      <<<dim3(cdiv(D, 128), cdiv(MROWS, 128), 4), 256, SMEM_128x128_T0>>>(p);

  add_ln_k<true, B * NP><<<NR4, 256>>>(
      t4, a4, w.l1g + (long long)layerBase * D, w.l1b + (long long)layerBase * D,
      x14);

  // FF1 (z = 4)
  reset();
  p.A = x14; p.lda = D; p.as1 = (long long)MROWS * D;
  p.Bm = sc + OFF_W1R + (long long)layerBase * D * F; p.ldb = F;
  p.bias = w.b1 + (long long)layerBase * F;
  p.C = h4; p.ldc = F; p.cs1 = (long long)MROWS * F;
  p.M = MROWS; p.N = F; p.K = D;
  p.zSeg = 1; p.bSeg = (long long)D * F; p.biasSeg = F;
  tmma_k<128, 128, 64, 32, 0, 1>
      <<<dim3(cdiv(F, 128), cdiv(MROWS, 128), 4), 256, SMEM_128x128_T0>>>(p);

  // FF2 (z = 4) -> y4 (free after out projection)
  reset();
  p.A = h4; p.lda = F; p.as1 = (long long)MROWS * F;
  p.Bm = sc + OFF_W2R + (long long)layerBase * F * D; p.ldb = D;
  p.bias = w.b2 + (long long)layerBase * D;
  p.C = y4; p.ldc = D; p.cs1 = (long long)MROWS * D;
  p.M = MROWS; p.N = D; p.K = F;
  p.zSeg = 1; p.bSeg = (long long)F * D; p.biasSeg = D;
  tmma_k<128, 128, 64, 32, 0, 0>
      <<<dim3(cdiv(D, 128), cdiv(MROWS, 128), 4), 256, SMEM_128x128_T0>>>(p);

  add_ln_k<true, B * NP><<<NR4, 256>>>(
      x14, y4, w.l2g + (long long)layerBase * D,
      w.l2b + (long long)layerBase * D, o4);

  combine_k<<<cdiv((int)NX, 256), 256>>>(sc + OFF_X, o4);
}

extern "C" void kernel_launch(void* const* d_in, const int* in_sizes, int n_in,
                              void* d_out, int out_size) {
  (void)in_sizes; (void)n_in; (void)out_size;
  float* sc = nullptr;
  cudaGetSymbolAddress((void**)&sc, g_scratch);

  cudaFuncSetAttribute((const void*)tmma_k<128, 64, 32, 32, 0, 3>,
                       cudaFuncAttributeMaxDynamicSharedMemorySize,
                       SMEM_128x64_T0);
  cudaFuncSetAttribute((const void*)tmma_k<128, 128, 64, 32, 1, 2>,
                       cudaFuncAttributeMaxDynamicSharedMemorySize,
                       SMEM_128x128_T1);
  cudaFuncSetAttribute((const void*)tmma_k<128, 128, 64, 32, 0, 0>,
                       cudaFuncAttributeMaxDynamicSharedMemorySize,
                       SMEM_128x128_T0);
  cudaFuncSetAttribute((const void*)tmma_k<128, 128, 64, 32, 0, 1>,
                       cudaFuncAttributeMaxDynamicSharedMemorySize,
                       SMEM_128x128_T0);
  cudaFuncSetAttribute((const void*)tmma_k<128, 128, 64, 32, 0, 6>,
                       cudaFuncAttributeMaxDynamicSharedMemorySize,
                       SMEM_128x128_T0);

  const float* x_in = (const float*)d_in[0];
  Wts w;
  w.ew = (const float*)d_in[1];  w.eb = (const float*)d_in[2];
  w.rw = (const float*)d_in[3];  w.rb = (const float*)d_in[4];
  w.ow = (const float*)d_in[5];  w.ob = (const float*)d_in[6];
  w.l1g = (const float*)d_in[7]; w.l1b = (const float*)d_in[8];
  w.w1 = (const float*)d_in[9];  w.b1 = (const float*)d_in[10];
  w.w2 = (const float*)d_in[11]; w.b2 = (const float*)d_in[12];
  w.l2g = (const float*)d_in[13]; w.l2b = (const float*)d_in[14];

  {
    const long long tot = (long long)L * D * EN + (long long)L * D * D +
                          (long long)L * D * F + (long long)L * F * D;
    prep_k<<<(int)((tot + 255) / 256), 256>>>(sc, w.ew, w.ow, w.w1, w.w2);
  }

  copy_round_k<<<cdiv((int)NX, 256), 256>>>(sc + OFF_X, x_in, NX);

  run_block(sc, sc + OFF_X, sc + OFF_X, 0, S, w);

  for (int c = 0; c < CYCLES; c++) run_segs(sc, c, w);

  run_block(sc, sc + OFF_X, (float*)d_out, 13, S, w);
}